// round 1
// baseline (speedup 1.0000x reference)
#include <cuda_runtime.h>
#include <math.h>

#define NN 10000
#define NE 30000
#define NG 50
#define HH 8
#define MAXHC 4096

// ---------------- scratch (device globals; no allocation allowed) ----------------
__device__ float g_q[NN * MAXHC];
__device__ float g_k[NN * MAXHC];
__device__ float g_v[NN * MAXHC];
__device__ float g_agg[NN * MAXHC];
__device__ float g_skip[NN * 512];
__device__ float g_hA[NN * 512];
__device__ float g_hB[NN * 512];
__device__ float g_alpha[NE * HH];
__device__ float g_m[NN * HH];
__device__ float g_den[NN * HH];
__device__ float g_gate[NN];
__device__ float g_gm[NG];
__device__ float g_gd[NG];
__device__ float g_pool[NG * 64];

// ---------------- utility kernels ----------------
__global__ void fill_kernel(float* p, float v, size_t n) {
    size_t i = (size_t)blockIdx.x * blockDim.x + threadIdx.x;
    if (i < n) p[i] = v;
}

__device__ __forceinline__ void atomicMaxFloat(float* addr, float v) {
    int* ai = (int*)addr;
    int old = *ai;
    while (__int_as_float(old) < v) {
        int assumed = old;
        old = atomicCAS(ai, assumed, __float_as_int(v));
        if (old == assumed) break;
    }
}

// ---------------- GEMM: C[M,N] = A[M,K] @ B[K,N] + bias[N] ----------------
#define BM 64
#define BN 64
#define BK 16
#define TM 4
#define TN 4

__global__ void gemm_bias_kernel(const float* __restrict__ A, const float* __restrict__ B,
                                 const float* __restrict__ bias, float* __restrict__ C,
                                 int M, int K, int N) {
    __shared__ float As[BK][BM];
    __shared__ float Bs[BK][BN];
    int tid = threadIdx.x;              // 256 threads
    int m0 = blockIdx.y * BM;
    int n0 = blockIdx.x * BN;
    int trow = (tid / 16) * TM;
    int tcol = (tid % 16) * TN;
    float acc[TM][TN];
#pragma unroll
    for (int i = 0; i < TM; i++)
#pragma unroll
        for (int j = 0; j < TN; j++) acc[i][j] = 0.f;

    for (int k0 = 0; k0 < K; k0 += BK) {
#pragma unroll
        for (int l = 0; l < 4; l++) {
            int i = tid + l * 256;
            int am = i / BK, ak = i % BK;
            int gr = m0 + am;
            As[ak][am] = (gr < M) ? A[(size_t)gr * K + k0 + ak] : 0.f;
        }
#pragma unroll
        for (int l = 0; l < 4; l++) {
            int i = tid + l * 256;
            int bk = i / BN, bn = i % BN;
            Bs[bk][bn] = B[(size_t)(k0 + bk) * N + n0 + bn];
        }
        __syncthreads();
#pragma unroll
        for (int kk = 0; kk < BK; kk++) {
            float ra[TM], rb[TN];
#pragma unroll
            for (int i = 0; i < TM; i++) ra[i] = As[kk][trow + i];
#pragma unroll
            for (int j = 0; j < TN; j++) rb[j] = Bs[kk][tcol + j];
#pragma unroll
            for (int i = 0; i < TM; i++)
#pragma unroll
                for (int j = 0; j < TN; j++) acc[i][j] += ra[i] * rb[j];
        }
        __syncthreads();
    }
#pragma unroll
    for (int i = 0; i < TM; i++) {
        int row = m0 + trow + i;
        if (row >= M) continue;
#pragma unroll
        for (int j = 0; j < TN; j++) {
            int col = n0 + tcol + j;
            C[(size_t)row * N + col] = acc[i][j] + bias[col];
        }
    }
}

// ---------------- edge attention kernels ----------------
// warp per (edge, head): alpha = scale * dot(q[dst], k[src]); atomic max into m[dst,h]
__global__ void edge_alpha_kernel(const float* __restrict__ q, const float* __restrict__ k,
                                  const int* __restrict__ src, const int* __restrict__ dst,
                                  float* __restrict__ alpha, float* __restrict__ m,
                                  int C, float scale) {
    int w = (blockIdx.x * blockDim.x + threadIdx.x) >> 5;
    int lane = threadIdx.x & 31;
    if (w >= NE * HH) return;
    int e = w / HH, h = w % HH;
    int s = src[e], d = dst[e];
    const float* qp = q + (size_t)d * HH * C + (size_t)h * C;
    const float* kp = k + (size_t)s * HH * C + (size_t)h * C;
    float sum = 0.f;
    for (int c = lane; c < C; c += 32) sum += qp[c] * kp[c];
#pragma unroll
    for (int o = 16; o; o >>= 1) sum += __shfl_xor_sync(0xFFFFFFFFu, sum, o);
    if (lane == 0) {
        float a = sum * scale;
        alpha[(size_t)e * HH + h] = a;
        atomicMaxFloat(&m[(size_t)d * HH + h], a);
    }
}

// thread per (edge, head): ex = exp(alpha - m[dst]); alpha <- ex; den[dst] += ex
__global__ void edge_exp_kernel(const int* __restrict__ dst, float* __restrict__ alpha,
                                const float* __restrict__ m, float* __restrict__ den) {
    int i = blockIdx.x * blockDim.x + threadIdx.x;
    if (i >= NE * HH) return;
    int e = i / HH, h = i % HH;
    int d = dst[e];
    float ex = expf(alpha[i] - m[(size_t)d * HH + h]);
    alpha[i] = ex;
    atomicAdd(&den[(size_t)d * HH + h], ex);
}

// warp per (edge, head): agg[dst,h,:] += (ex/den) * v[src,h,:]
__global__ void edge_agg_kernel(const float* __restrict__ v, const int* __restrict__ src,
                                const int* __restrict__ dst, const float* __restrict__ alpha,
                                const float* __restrict__ den, float* __restrict__ agg, int C) {
    int w = (blockIdx.x * blockDim.x + threadIdx.x) >> 5;
    int lane = threadIdx.x & 31;
    if (w >= NE * HH) return;
    int e = w / HH, h = w % HH;
    int s = src[e], d = dst[e];
    float wt = alpha[(size_t)e * HH + h] / fmaxf(den[(size_t)d * HH + h], 1e-16f);
    const float* vp = v + (size_t)s * HH * C + (size_t)h * C;
    float* ap = agg + (size_t)d * HH * C + (size_t)h * C;
    for (int c = lane; c < C; c += 32) atomicAdd(&ap[c], wt * vp[c]);
}

// thread per (node, c): out = elu(mean_h(agg) + skip)
__global__ void combine_kernel(const float* __restrict__ agg, const float* __restrict__ skip,
                               float* __restrict__ out, int C) {
    int i = blockIdx.x * blockDim.x + threadIdx.x;
    if (i >= NN * C) return;
    int n = i / C, c = i % C;
    const float* ap = agg + (size_t)n * HH * C + c;
    float s = 0.f;
#pragma unroll
    for (int h = 0; h < HH; h++) s += ap[(size_t)h * C];
    float val = s * (1.f / HH) + skip[i];
    out[i] = val > 0.f ? val : expm1f(val);
}

// ---------------- pooling ----------------
__global__ void gate_kernel(const float* __restrict__ h, const float* __restrict__ gw,
                            const float* __restrict__ gb, const int* __restrict__ batch,
                            float* __restrict__ gate, float* __restrict__ gm) {
    int n = (blockIdx.x * blockDim.x + threadIdx.x) >> 5;
    int lane = threadIdx.x & 31;
    if (n >= NN) return;
    float s = 0.f;
    for (int c = lane; c < 64; c += 32) s += h[(size_t)n * 64 + c] * gw[c];
#pragma unroll
    for (int o = 16; o; o >>= 1) s += __shfl_xor_sync(0xFFFFFFFFu, s, o);
    if (lane == 0) {
        s += gb[0];
        gate[n] = s;
        atomicMaxFloat(&gm[batch[n]], s);
    }
}

__global__ void gate_exp_kernel(const int* __restrict__ batch, float* __restrict__ gate,
                                const float* __restrict__ gm, float* __restrict__ gd) {
    int n = blockIdx.x * blockDim.x + threadIdx.x;
    if (n >= NN) return;
    int b = batch[n];
    float e = expf(gate[n] - gm[b]);
    gate[n] = e;
    atomicAdd(&gd[b], e);
}

__global__ void pool_kernel(const float* __restrict__ h, const int* __restrict__ batch,
                            const float* __restrict__ gate, const float* __restrict__ gd,
                            float* __restrict__ pool) {
    int i = blockIdx.x * blockDim.x + threadIdx.x;
    if (i >= NN * 64) return;
    int n = i / 64, c = i % 64;
    int b = batch[n];
    float w = gate[n] / fmaxf(gd[b], 1e-16f);
    atomicAdd(&pool[b * 64 + c], w * h[i]);
}

__global__ void fc_kernel(const float* __restrict__ pool, const float* __restrict__ fw,
                          const float* __restrict__ fb, float* __restrict__ out) {
    int i = blockIdx.x * blockDim.x + threadIdx.x;
    if (i >= NG * 10) return;
    int g = i / 10, o = i % 10;
    float s = fb[o];
#pragma unroll
    for (int c = 0; c < 64; c++) s += pool[g * 64 + c] * fw[c * 10 + o];
    out[i] = s;
}

// ---------------- host-side helpers ----------------
static inline void launch_gemm(const float* A, const float* B, const float* bias, float* C,
                               int M, int K, int N) {
    dim3 grid(N / BN, (M + BM - 1) / BM);
    gemm_bias_kernel<<<grid, 256>>>(A, B, bias, C, M, K, N);
}

static inline void launch_fill(float* p, float v, size_t n) {
    fill_kernel<<<(unsigned)((n + 255) / 256), 256>>>(p, v, n);
}

static void tconv_layer(const float* x, int fin, int C,
                        const float* qw, const float* qb, const float* kw, const float* kb,
                        const float* vw, const float* vb, const float* sw, const float* sb,
                        const int* src, const int* dst, float* hout,
                        float* q, float* k, float* v, float* agg, float* skip,
                        float* alpha, float* m, float* den) {
    int hc = C * HH;
    launch_gemm(x, qw, qb, q, NN, fin, hc);
    launch_gemm(x, kw, kb, k, NN, fin, hc);
    launch_gemm(x, vw, vb, v, NN, fin, hc);
    launch_gemm(x, sw, sb, skip, NN, fin, C);
    launch_fill(m, -INFINITY, (size_t)NN * HH);
    launch_fill(den, 0.f, (size_t)NN * HH);
    launch_fill(agg, 0.f, (size_t)NN * hc);
    float scale = 1.f / sqrtf((float)C);
    int warps = NE * HH;
    edge_alpha_kernel<<<(warps * 32 + 255) / 256, 256>>>(q, k, src, dst, alpha, m, C, scale);
    edge_exp_kernel<<<(NE * HH + 255) / 256, 256>>>(dst, alpha, m, den);
    edge_agg_kernel<<<(warps * 32 + 255) / 256, 256>>>(v, src, dst, alpha, den, agg, C);
    combine_kernel<<<(NN * C + 255) / 256, 256>>>(agg, skip, hout, C);
}

extern "C" void kernel_launch(void* const* d_in, const int* in_sizes, int n_in,
                              void* d_out, int out_size) {
    const float* x     = (const float*)d_in[0];
    const int*   ei    = (const int*)d_in[1];
    const int*   batch = (const int*)d_in[2];
    const float* W[24];
    for (int i = 0; i < 24; i++) W[i] = (const float*)d_in[3 + i];
    const float* gate_w = (const float*)d_in[27];
    const float* gate_b = (const float*)d_in[28];
    const float* fc_w   = (const float*)d_in[29];
    const float* fc_b   = (const float*)d_in[30];
    float* out = (float*)d_out;

    const int* src = ei;
    const int* dst = ei + NE;

    float *q, *k, *v, *agg, *skip, *hA, *hB, *alpha, *m, *den, *gate, *gm, *gd, *pool;
    cudaGetSymbolAddress((void**)&q, g_q);
    cudaGetSymbolAddress((void**)&k, g_k);
    cudaGetSymbolAddress((void**)&v, g_v);
    cudaGetSymbolAddress((void**)&agg, g_agg);
    cudaGetSymbolAddress((void**)&skip, g_skip);
    cudaGetSymbolAddress((void**)&hA, g_hA);
    cudaGetSymbolAddress((void**)&hB, g_hB);
    cudaGetSymbolAddress((void**)&alpha, g_alpha);
    cudaGetSymbolAddress((void**)&m, g_m);
    cudaGetSymbolAddress((void**)&den, g_den);
    cudaGetSymbolAddress((void**)&gate, g_gate);
    cudaGetSymbolAddress((void**)&gm, g_gm);
    cudaGetSymbolAddress((void**)&gd, g_gd);
    cudaGetSymbolAddress((void**)&pool, g_pool);

    // Layer 1: fin=128, C=512 (hc=4096)
    tconv_layer(x, 128, 512,
                W[0], W[1], W[2], W[3], W[4], W[5], W[6], W[7],
                src, dst, hA, q, k, v, agg, skip, alpha, m, den);
    // Layer 2: fin=512, C=256 (hc=2048)
    tconv_layer(hA, 512, 256,
                W[8], W[9], W[10], W[11], W[12], W[13], W[14], W[15],
                src, dst, hB, q, k, v, agg, skip, alpha, m, den);
    // Layer 3: fin=256, C=64 (hc=512)
    tconv_layer(hB, 256, 64,
                W[16], W[17], W[18], W[19], W[20], W[21], W[22], W[23],
                src, dst, hA, q, k, v, agg, skip, alpha, m, den);

    // Global attention pooling on hA [NN, 64]
    launch_fill(gm, -INFINITY, NG);
    launch_fill(gd, 0.f, NG);
    launch_fill(pool, 0.f, (size_t)NG * 64);
    gate_kernel<<<(NN * 32 + 255) / 256, 256>>>(hA, gate_w, gate_b, batch, gate, gm);
    gate_exp_kernel<<<(NN + 255) / 256, 256>>>(batch, gate, gm, gd);
    pool_kernel<<<(NN * 64 + 255) / 256, 256>>>(hA, batch, gate, gd, pool);
    fc_kernel<<<(NG * 10 + 255) / 256, 256>>>(pool, fc_w, fc_b, out);
}

// round 3
// speedup vs baseline: 2.7396x; 2.7396x over previous
#include <cuda_runtime.h>
#include <cuda_bf16.h>
#include <math.h>
#include <stdint.h>

#define NN 10000
#define NE 30000
#define NG 50
#define HH 8
#define MAXHC 4096

// ---------------- scratch (device globals; no allocation allowed) ----------------
__device__ float g_q[NN * MAXHC];
__device__ float g_k[NN * MAXHC];
__device__ float g_v[NN * MAXHC];
__device__ float g_agg[NN * MAXHC];
__device__ float g_skip[NN * 512];
__device__ float g_hA[NN * 512];
__device__ float g_hB[NN * 512];
__device__ float g_gate[NN];
__device__ float g_gm[NG];
__device__ float g_gd[NG];
__device__ float g_pool[NG * 64];
// composite bf16 split operands: A' = [hi|hi|lo] (M x 3K), B' = [hi|lo|hi] (N x 3K)
__device__ __nv_bfloat16 g_Acomp[NN * 1536];
__device__ __nv_bfloat16 g_Bcomp[4096 * 1536];
// CSR
__device__ int g_deg[NN];
__device__ int g_rowptr[NN + 1];
__device__ int g_cursor[NN];
__device__ int g_perm[NE];

// ---------------- helpers ----------------
__device__ __forceinline__ uint32_t smem_u32(const void* p) {
    uint32_t a;
    asm("{ .reg .u64 t; cvta.to.shared.u64 t, %1; cvt.u32.u64 %0, t; }" : "=r"(a) : "l"(p));
    return a;
}
__device__ __forceinline__ void cp16(uint32_t saddr, const void* g, bool pred) {
    int sz = pred ? 16 : 0;
    asm volatile("cp.async.cg.shared.global [%0], [%1], 16, %2;" :: "r"(saddr), "l"(g), "r"(sz));
}
__device__ __forceinline__ void cp_commit() { asm volatile("cp.async.commit_group;"); }
__device__ __forceinline__ void cp_wait0() { asm volatile("cp.async.wait_group 0;"); }
__device__ __forceinline__ void cp_wait1() { asm volatile("cp.async.wait_group 1;"); }
__device__ __forceinline__ void ldmx4(uint32_t* r, uint32_t addr) {
    asm volatile("ldmatrix.sync.aligned.m8n8.x4.shared.b16 {%0,%1,%2,%3}, [%4];"
                 : "=r"(r[0]), "=r"(r[1]), "=r"(r[2]), "=r"(r[3]) : "r"(addr));
}
__device__ __forceinline__ void mma_bf16(float* c, const uint32_t* a, uint32_t b0, uint32_t b1) {
    asm volatile(
        "mma.sync.aligned.m16n8k16.row.col.f32.bf16.bf16.f32 "
        "{%0,%1,%2,%3}, {%4,%5,%6,%7}, {%8,%9}, {%0,%1,%2,%3};"
        : "+f"(c[0]), "+f"(c[1]), "+f"(c[2]), "+f"(c[3])
        : "r"(a[0]), "r"(a[1]), "r"(a[2]), "r"(a[3]), "r"(b0), "r"(b1));
}

// ---------------- utility kernels ----------------
__global__ void fill_kernel(float* p, float v, size_t n) {
    size_t i = (size_t)blockIdx.x * blockDim.x + threadIdx.x;
    if (i < n) p[i] = v;
}
__global__ void fill_int_kernel(int* p, int v, int n) {
    int i = blockIdx.x * blockDim.x + threadIdx.x;
    if (i < n) p[i] = v;
}
__device__ __forceinline__ void atomicMaxFloat(float* addr, float v) {
    int* ai = (int*)addr;
    int old = *ai;
    while (__int_as_float(old) < v) {
        int assumed = old;
        old = atomicCAS(ai, assumed, __float_as_int(v));
        if (old == assumed) break;
    }
}

// ---------------- fp32 -> composite bf16 split ----------------
// A' row layout (3K): [0,K)=hi, [K,2K)=hi, [2K,3K)=lo
__global__ void splitA_kernel(const float* __restrict__ A, __nv_bfloat16* __restrict__ out,
                              int K, size_t n) {
    size_t i = (size_t)blockIdx.x * blockDim.x + threadIdx.x;
    if (i >= n) return;
    float x = A[i];
    __nv_bfloat16 h = __float2bfloat16(x);
    __nv_bfloat16 l = __float2bfloat16(x - __bfloat162float(h));
    size_t row = i / K, col = i % K;
    size_t base = row * (size_t)(3 * K) + col;
    out[base] = h;
    out[base + K] = h;
    out[base + 2 * K] = l;
}

// W [K,N] fp32 -> B' [N,3K]: [0,K)=hi, [K,2K)=lo, [2K,3K)=hi
__global__ void splitBT_kernel(const float* __restrict__ W, __nv_bfloat16* __restrict__ out,
                               int K, int N) {
    __shared__ float t[32][33];
    int kb = blockIdx.x * 32, nb = blockIdx.y * 32;
    int tx = threadIdx.x, ty = threadIdx.y;  // 32 x 8
    for (int r = ty; r < 32; r += 8) {
        int kk = kb + r, nn2 = nb + tx;
        t[r][tx] = (kk < K && nn2 < N) ? W[(size_t)kk * N + nn2] : 0.f;
    }
    __syncthreads();
    for (int r = ty; r < 32; r += 8) {
        int nn2 = nb + r, kk = kb + tx;
        if (nn2 < N && kk < K) {
            float x = t[tx][r];
            __nv_bfloat16 h = __float2bfloat16(x);
            __nv_bfloat16 l = __float2bfloat16(x - __bfloat162float(h));
            size_t base = (size_t)nn2 * (3 * K) + kk;
            out[base] = h;
            out[base + K] = l;
            out[base + 2 * K] = h;
        }
    }
}

// ---------------- bf16 mma.sync GEMM: C[M,N] = A'[M,K3] @ B'[N,K3]^T + bias ----------------
#define BM 128
#define BN 128
#define BKK 32
#define LDT 40  // padded smem row stride (elements)

__global__ void __launch_bounds__(256)
gemm_mma_kernel(const __nv_bfloat16* __restrict__ A, const __nv_bfloat16* __restrict__ B,
                const float* __restrict__ bias, float* __restrict__ C,
                int M, int K3, int N) {
    __shared__ __nv_bfloat16 As[2][BM * LDT];
    __shared__ __nv_bfloat16 Bs[2][BN * LDT];
    int tid = threadIdx.x;
    int lane = tid & 31, wid = tid >> 5;
    int m0 = blockIdx.y * BM, n0 = blockIdx.x * BN;
    int warp_m = wid >> 2, warp_n = wid & 3;   // 2 x 4
    int m_base = warp_m * 64, n_base = warp_n * 32;

    uint32_t aBase = smem_u32(&As[0][0]);
    uint32_t bBase = smem_u32(&Bs[0][0]);
    const uint32_t stageA = BM * LDT * 2;
    const uint32_t stageB = BN * LDT * 2;

    float acc[4][4][4];
#pragma unroll
    for (int i = 0; i < 4; i++)
#pragma unroll
        for (int j = 0; j < 4; j++)
#pragma unroll
            for (int r = 0; r < 4; r++) acc[i][j][r] = 0.f;

    int nk = K3 >> 5;

    // --- load helper (macro-ish lambda) ---
    auto load_stage = [&](int st, int kt) {
        // A: 128 rows x 32 cols -> 512 chunks of 16B
#pragma unroll
        for (int l = 0; l < 2; l++) {
            int idx = tid + l * 256;
            int row = idx >> 2, ch = idx & 3;
            int gr = m0 + row;
            uint32_t sa = aBase + st * stageA + (row * LDT + ch * 8) * 2;
            const __nv_bfloat16* g = A + (size_t)(gr < M ? gr : 0) * K3 + kt * 32 + ch * 8;
            cp16(sa, g, gr < M);
        }
#pragma unroll
        for (int l = 0; l < 2; l++) {
            int idx = tid + l * 256;
            int row = idx >> 2, ch = idx & 3;
            int gn = n0 + row;
            uint32_t sb = bBase + st * stageB + (row * LDT + ch * 8) * 2;
            const __nv_bfloat16* g = B + (size_t)(gn < N ? gn : 0) * K3 + kt * 32 + ch * 8;
            cp16(sb, g, gn < N);
        }
        cp_commit();
    };

    load_stage(0, 0);

    int a_r = (lane & 15);
    int a_c = (lane >> 4) * 8;
    int b_r = (lane & 7) + ((lane >> 4) << 3);
    int b_c = ((lane >> 3) & 1) * 8;

    for (int kt = 0; kt < nk; kt++) {
        int st = kt & 1;
        if (kt + 1 < nk) {
            load_stage(st ^ 1, kt + 1);
            cp_wait1();
        } else {
            cp_wait0();
        }
        __syncthreads();
        uint32_t sa = aBase + st * stageA;
        uint32_t sb = bBase + st * stageB;
#pragma unroll
        for (int ks = 0; ks < 32; ks += 16) {
            uint32_t af[4][4];
#pragma unroll
            for (int im = 0; im < 4; im++)
                ldmx4(af[im], sa + ((m_base + im * 16 + a_r) * LDT + ks + a_c) * 2);
            uint32_t bf[2][4];
#pragma unroll
            for (int ib = 0; ib < 2; ib++)
                ldmx4(bf[ib], sb + ((n_base + ib * 16 + b_r) * LDT + ks + b_c) * 2);
#pragma unroll
            for (int im = 0; im < 4; im++)
#pragma unroll
                for (int jn = 0; jn < 4; jn++)
                    mma_bf16(acc[im][jn], af[im], bf[jn >> 1][(jn & 1) * 2], bf[jn >> 1][(jn & 1) * 2 + 1]);
        }
        __syncthreads();
    }

    // epilogue
#pragma unroll
    for (int im = 0; im < 4; im++) {
        int row0 = m0 + m_base + im * 16 + (lane >> 2);
#pragma unroll
        for (int jn = 0; jn < 4; jn++) {
            int col = n0 + n_base + jn * 8 + (lane & 3) * 2;
            if (col < N) {
                float bx = bias[col], by = bias[col + 1];
                if (row0 < M) {
                    float2 o = make_float2(acc[im][jn][0] + bx, acc[im][jn][1] + by);
                    *(float2*)&C[(size_t)row0 * N + col] = o;
                }
                if (row0 + 8 < M) {
                    float2 o = make_float2(acc[im][jn][2] + bx, acc[im][jn][3] + by);
                    *(float2*)&C[(size_t)(row0 + 8) * N + col] = o;
                }
            }
        }
    }
}

// ---------------- CSR build ----------------
__global__ void hist_kernel(const int* __restrict__ dst, int* __restrict__ deg) {
    int e = blockIdx.x * blockDim.x + threadIdx.x;
    if (e < NE) atomicAdd(&deg[dst[e]], 1);
}
__global__ void csr_scan_kernel(const int* __restrict__ deg, int* __restrict__ rowptr,
                                int* __restrict__ cursor) {
    __shared__ int part[1024];
    int t = threadIdx.x;
    int base = t * 10;
    int local[10];
    int s = 0;
#pragma unroll
    for (int i = 0; i < 10; i++) {
        int idx = base + i;
        local[i] = (idx < NN) ? deg[idx] : 0;
        s += local[i];
    }
    part[t] = s;
    __syncthreads();
    for (int off = 1; off < 1024; off <<= 1) {
        int v = (t >= off) ? part[t - off] : 0;
        __syncthreads();
        part[t] += v;
        __syncthreads();
    }
    int run = (t > 0) ? part[t - 1] : 0;
#pragma unroll
    for (int i = 0; i < 10; i++) {
        int idx = base + i;
        if (idx < NN) {
            rowptr[idx] = run;
            cursor[idx] = run;
            run += local[i];
        }
    }
    if (t == 1023) rowptr[NN] = run;
}
__global__ void scatter_kernel(const int* __restrict__ dst, int* __restrict__ cursor,
                               int* __restrict__ perm) {
    int e = blockIdx.x * blockDim.x + threadIdx.x;
    if (e < NE) {
        int pos = atomicAdd(&cursor[dst[e]], 1);
        perm[pos] = e;
    }
}

// ---------------- fused attention (online softmax), warp per (node, head) ----------------
template <int CC>
__global__ void attn_kernel(const float* __restrict__ q, const float* __restrict__ k,
                            const float* __restrict__ v, const int* __restrict__ rowptr,
                            const int* __restrict__ perm, const int* __restrict__ src,
                            float* __restrict__ agg, float scale) {
    int w = (blockIdx.x * blockDim.x + threadIdx.x) >> 5;
    int lane = threadIdx.x & 31;
    if (w >= NN * HH) return;
    int n = w / HH, h = w % HH;
    const int R = CC / 32;
    float qv[R], acc[R];
    const size_t basen = (size_t)n * (HH * CC) + (size_t)h * CC;
#pragma unroll
    for (int i = 0; i < R; i++) {
        qv[i] = q[basen + i * 32 + lane];
        acc[i] = 0.f;
    }
    float mmax = -INFINITY, den = 0.f;
    int j0 = rowptr[n], j1 = rowptr[n + 1];
    for (int j = j0; j < j1; j++) {
        int e = perm[j];
        int s = src[e];
        const float* kp = k + (size_t)s * (HH * CC) + (size_t)h * CC;
        const float* vp = v + (size_t)s * (HH * CC) + (size_t)h * CC;
        float dot = 0.f;
#pragma unroll
        for (int i = 0; i < R; i++) dot += qv[i] * kp[i * 32 + lane];
#pragma unroll
        for (int o = 16; o; o >>= 1) dot += __shfl_xor_sync(0xFFFFFFFFu, dot, o);
        float a = dot * scale;
        float mnew = fmaxf(mmax, a);
        float corr = __expf(mmax - mnew);
        float wt = __expf(a - mnew);
        den = den * corr + wt;
#pragma unroll
        for (int i = 0; i < R; i++) acc[i] = acc[i] * corr + wt * vp[i * 32 + lane];
        mmax = mnew;
    }
    float inv = 1.f / fmaxf(den, 1e-16f);
#pragma unroll
    for (int i = 0; i < R; i++) agg[basen + i * 32 + lane] = acc[i] * inv;
}

// ---------------- combine: out = elu(mean_h(agg) + skip) ----------------
__global__ void combine_kernel(const float* __restrict__ agg, const float* __restrict__ skip,
                               float* __restrict__ out, int C) {
    int i = blockIdx.x * blockDim.x + threadIdx.x;
    if (i >= NN * C) return;
    int n = i / C, c = i % C;
    const float* ap = agg + (size_t)n * HH * C + c;
    float s = 0.f;
#pragma unroll
    for (int h = 0; h < HH; h++) s += ap[(size_t)h * C];
    float val = s * (1.f / HH) + skip[i];
    out[i] = val > 0.f ? val : expm1f(val);
}

// ---------------- pooling ----------------
__global__ void gate_kernel(const float* __restrict__ h, const float* __restrict__ gw,
                            const float* __restrict__ gb, const int* __restrict__ batch,
                            float* __restrict__ gate, float* __restrict__ gm) {
    int n = (blockIdx.x * blockDim.x + threadIdx.x) >> 5;
    int lane = threadIdx.x & 31;
    if (n >= NN) return;
    float s = 0.f;
    for (int c = lane; c < 64; c += 32) s += h[(size_t)n * 64 + c] * gw[c];
#pragma unroll
    for (int o = 16; o; o >>= 1) s += __shfl_xor_sync(0xFFFFFFFFu, s, o);
    if (lane == 0) {
        s += gb[0];
        gate[n] = s;
        atomicMaxFloat(&gm[batch[n]], s);
    }
}
__global__ void gate_exp_kernel(const int* __restrict__ batch, float* __restrict__ gate,
                                const float* __restrict__ gm, float* __restrict__ gd) {
    int n = blockIdx.x * blockDim.x + threadIdx.x;
    if (n >= NN) return;
    int b = batch[n];
    float e = expf(gate[n] - gm[b]);
    gate[n] = e;
    atomicAdd(&gd[b], e);
}
__global__ void pool_kernel(const float* __restrict__ h, const int* __restrict__ batch,
                            const float* __restrict__ gate, const float* __restrict__ gd,
                            float* __restrict__ pool) {
    int i = blockIdx.x * blockDim.x + threadIdx.x;
    if (i >= NN * 64) return;
    int n = i / 64, c = i % 64;
    int b = batch[n];
    float w = gate[n] / fmaxf(gd[b], 1e-16f);
    atomicAdd(&pool[b * 64 + c], w * h[i]);
}
__global__ void fc_kernel(const float* __restrict__ pool, const float* __restrict__ fw,
                          const float* __restrict__ fb, float* __restrict__ out) {
    int i = blockIdx.x * blockDim.x + threadIdx.x;
    if (i >= NG * 10) return;
    int g = i / 10, o = i % 10;
    float s = fb[o];
#pragma unroll
    for (int c = 0; c < 64; c++) s += pool[g * 64 + c] * fw[c * 10 + o];
    out[i] = s;
}

// ---------------- host side ----------------
static inline void launch_fill(float* p, float v, size_t n) {
    fill_kernel<<<(unsigned)((n + 255) / 256), 256>>>(p, v, n);
}

struct Ptrs {
    float *q, *k, *v, *agg, *skip, *hA, *hB, *gate, *gm, *gd, *pool;
    __nv_bfloat16 *Ac, *Bc;
    int *deg, *rowptr, *cursor, *perm;
};

static void run_gemm(const __nv_bfloat16* Ac, const float* W, const float* bias, float* C,
                     __nv_bfloat16* Bc, int M, int K, int N) {
    dim3 tg((K + 31) / 32, (N + 31) / 32);
    splitBT_kernel<<<tg, dim3(32, 8)>>>(W, Bc, K, N);
    int K3 = 3 * K;
    dim3 grid((N + BN - 1) / BN, (M + BM - 1) / BM);
    gemm_mma_kernel<<<grid, 256>>>(Ac, Bc, bias, C, M, K3, N);
}

static void tconv_layer(const float* x, int fin, int C, const float* const* W,
                        const int* src, float* hout, const Ptrs& P) {
    int hc = C * HH;
    size_t na = (size_t)NN * fin;
    splitA_kernel<<<(unsigned)((na + 255) / 256), 256>>>(x, P.Ac, fin, na);
    run_gemm(P.Ac, W[0], W[1], P.q, P.Bc, NN, fin, hc);
    run_gemm(P.Ac, W[2], W[3], P.k, P.Bc, NN, fin, hc);
    run_gemm(P.Ac, W[4], W[5], P.v, P.Bc, NN, fin, hc);
    run_gemm(P.Ac, W[6], W[7], P.skip, P.Bc, NN, fin, C);
    float scale = 1.f / sqrtf((float)C);
    int nwarp = NN * HH;
    int blocks = (nwarp * 32 + 255) / 256;
    if (C == 512)
        attn_kernel<512><<<blocks, 256>>>(P.q, P.k, P.v, P.rowptr, P.perm, src, P.agg, scale);
    else if (C == 256)
        attn_kernel<256><<<blocks, 256>>>(P.q, P.k, P.v, P.rowptr, P.perm, src, P.agg, scale);
    else
        attn_kernel<64><<<blocks, 256>>>(P.q, P.k, P.v, P.rowptr, P.perm, src, P.agg, scale);
    combine_kernel<<<(NN * C + 255) / 256, 256>>>(P.agg, P.skip, hout, C);
}

extern "C" void kernel_launch(void* const* d_in, const int* in_sizes, int n_in,
                              void* d_out, int out_size) {
    const float* x     = (const float*)d_in[0];
    const int*   ei    = (const int*)d_in[1];
    const int*   batch = (const int*)d_in[2];
    const float* W[24];
    for (int i = 0; i < 24; i++) W[i] = (const float*)d_in[3 + i];
    const float* gate_w = (const float*)d_in[27];
    const float* gate_b = (const float*)d_in[28];
    const float* fc_w   = (const float*)d_in[29];
    const float* fc_b   = (const float*)d_in[30];
    float* out = (float*)d_out;

    const int* src = ei;
    const int* dst = ei + NE;

    Ptrs P;
    cudaGetSymbolAddress((void**)&P.q, g_q);
    cudaGetSymbolAddress((void**)&P.k, g_k);
    cudaGetSymbolAddress((void**)&P.v, g_v);
    cudaGetSymbolAddress((void**)&P.agg, g_agg);
    cudaGetSymbolAddress((void**)&P.skip, g_skip);
    cudaGetSymbolAddress((void**)&P.hA, g_hA);
    cudaGetSymbolAddress((void**)&P.hB, g_hB);
    cudaGetSymbolAddress((void**)&P.gate, g_gate);
    cudaGetSymbolAddress((void**)&P.gm, g_gm);
    cudaGetSymbolAddress((void**)&P.gd, g_gd);
    cudaGetSymbolAddress((void**)&P.pool, g_pool);
    cudaGetSymbolAddress((void**)&P.Ac, g_Acomp);
    cudaGetSymbolAddress((void**)&P.Bc, g_Bcomp);
    cudaGetSymbolAddress((void**)&P.deg, g_deg);
    cudaGetSymbolAddress((void**)&P.rowptr, g_rowptr);
    cudaGetSymbolAddress((void**)&P.cursor, g_cursor);
    cudaGetSymbolAddress((void**)&P.perm, g_perm);

    // CSR build
    fill_int_kernel<<<(NN + 255) / 256, 256>>>(P.deg, 0, NN);
    hist_kernel<<<(NE + 255) / 256, 256>>>(dst, P.deg);
    csr_scan_kernel<<<1, 1024>>>(P.deg, P.rowptr, P.cursor);
    scatter_kernel<<<(NE + 255) / 256, 256>>>(dst, P.cursor, P.perm);

    // Layers
    tconv_layer(x,    128, 512, &W[0],  src, P.hA, P);
    tconv_layer(P.hA, 512, 256, &W[8],  src, P.hB, P);
    tconv_layer(P.hB, 256, 64,  &W[16], src, P.hA, P);

    // Global attention pooling on hA [NN, 64]
    launch_fill(P.gm, -INFINITY, NG);
    launch_fill(P.gd, 0.f, NG);
    launch_fill(P.pool, 0.f, (size_t)NG * 64);
    gate_kernel<<<(NN * 32 + 255) / 256, 256>>>(P.hA, gate_w, gate_b, batch, P.gate, P.gm);
    gate_exp_kernel<<<(NN + 255) / 256, 256>>>(batch, P.gate, P.gm, P.gd);
    pool_kernel<<<(NN * 64 + 255) / 256, 256>>>(P.hA, batch, P.gate, P.gd, P.pool);
    fc_kernel<<<(NG * 10 + 255) / 256, 256>>>(P.pool, fc_w, fc_b, out);
}

// round 4
// speedup vs baseline: 2.8470x; 1.0392x over previous
#include <cuda_runtime.h>
#include <cuda_bf16.h>
#include <math.h>
#include <stdint.h>

#define NN 10000
#define NE 30000
#define NG 50
#define HH 8
#define MAXHC 4096
#define NTOT1 12800  // 3*4096+512

// ---------------- scratch (device globals) ----------------
__device__ float g_qkvs[NN * NTOT1];          // merged [q|k|v|skip] output
__device__ float g_agg[NN * MAXHC];
__device__ float g_hA[NN * 512];
__device__ float g_hB[NN * 512];
__device__ float g_gate[NN];
__device__ float g_gm[NG];
__device__ float g_gd[NG];
__device__ float g_pool[NG * 64];
__device__ float g_biasp[NTOT1];
// composite bf16 operands: A' = [hi|hi|lo] (M x 3K), B' = [hi|lo|hi] (Ntot x 3K)
__device__ __nv_bfloat16 g_Acomp[NN * 1536];
__device__ __nv_bfloat16 g_Bcomp[6400 * 1536];
// CSR
__device__ int g_deg[NN];
__device__ int g_rowptr[NN + 1];
__device__ int g_cursor[NN];
__device__ int g_perm[NE];

// ---------------- helpers ----------------
__device__ __forceinline__ uint32_t smem_u32(const void* p) {
    uint32_t a;
    asm("{ .reg .u64 t; cvta.to.shared.u64 t, %1; cvt.u32.u64 %0, t; }" : "=r"(a) : "l"(p));
    return a;
}
__device__ __forceinline__ void cp16(uint32_t saddr, const void* g, bool pred) {
    int sz = pred ? 16 : 0;
    asm volatile("cp.async.cg.shared.global [%0], [%1], 16, %2;" :: "r"(saddr), "l"(g), "r"(sz));
}
__device__ __forceinline__ void cp_commit() { asm volatile("cp.async.commit_group;"); }
__device__ __forceinline__ void cp_wait0() { asm volatile("cp.async.wait_group 0;"); }
__device__ __forceinline__ void cp_wait1() { asm volatile("cp.async.wait_group 1;"); }
__device__ __forceinline__ void ldmx4(uint32_t* r, uint32_t addr) {
    asm volatile("ldmatrix.sync.aligned.m8n8.x4.shared.b16 {%0,%1,%2,%3}, [%4];"
                 : "=r"(r[0]), "=r"(r[1]), "=r"(r[2]), "=r"(r[3]) : "r"(addr));
}
__device__ __forceinline__ void mma_bf16(float* c, const uint32_t* a, uint32_t b0, uint32_t b1) {
    asm volatile(
        "mma.sync.aligned.m16n8k16.row.col.f32.bf16.bf16.f32 "
        "{%0,%1,%2,%3}, {%4,%5,%6,%7}, {%8,%9}, {%0,%1,%2,%3};"
        : "+f"(c[0]), "+f"(c[1]), "+f"(c[2]), "+f"(c[3])
        : "r"(a[0]), "r"(a[1]), "r"(a[2]), "r"(a[3]), "r"(b0), "r"(b1));
}

// ---------------- utility kernels ----------------
__global__ void fill_kernel(float* p, float v, size_t n) {
    size_t i = (size_t)blockIdx.x * blockDim.x + threadIdx.x;
    if (i < n) p[i] = v;
}
__global__ void fill_int_kernel(int* p, int v, int n) {
    int i = blockIdx.x * blockDim.x + threadIdx.x;
    if (i < n) p[i] = v;
}
__device__ __forceinline__ void atomicMaxFloat(float* addr, float v) {
    int* ai = (int*)addr;
    int old = *ai;
    while (__int_as_float(old) < v) {
        int assumed = old;
        old = atomicCAS(ai, assumed, __float_as_int(v));
        if (old == assumed) break;
    }
}

// ---------------- fp32 -> composite bf16 split ----------------
__global__ void splitA_kernel(const float* __restrict__ A, __nv_bfloat16* __restrict__ out,
                              int K, size_t n) {
    size_t i = (size_t)blockIdx.x * blockDim.x + threadIdx.x;
    if (i >= n) return;
    float x = A[i];
    __nv_bfloat16 h = __float2bfloat16(x);
    __nv_bfloat16 l = __float2bfloat16(x - __bfloat162float(h));
    size_t row = i / K, col = i % K;
    size_t base = row * (size_t)(3 * K) + col;
    out[base] = h;
    out[base + K] = h;
    out[base + 2 * K] = l;
}

// W [K,N] fp32 -> B' rows [rowOff, rowOff+N) of [Ntot, 3K]: [hi | lo | hi]
__global__ void splitBT_kernel(const float* __restrict__ W, __nv_bfloat16* __restrict__ out,
                               int K, int N, int rowOff) {
    __shared__ float t[32][33];
    int kb = blockIdx.x * 32, nb = blockIdx.y * 32;
    int tx = threadIdx.x, ty = threadIdx.y;  // 32 x 8
    for (int r = ty; r < 32; r += 8) {
        int kk = kb + r, nn2 = nb + tx;
        t[r][tx] = (kk < K && nn2 < N) ? W[(size_t)kk * N + nn2] : 0.f;
    }
    __syncthreads();
    for (int r = ty; r < 32; r += 8) {
        int nn2 = nb + r, kk = kb + tx;
        if (nn2 < N && kk < K) {
            float x = t[tx][r];
            __nv_bfloat16 h = __float2bfloat16(x);
            __nv_bfloat16 l = __float2bfloat16(x - __bfloat162float(h));
            size_t base = (size_t)(rowOff + nn2) * (3 * K) + kk;
            out[base] = h;
            out[base + K] = l;
            out[base + 2 * K] = h;
        }
    }
}

__global__ void pack_bias_kernel(const float* __restrict__ qb, const float* __restrict__ kb,
                                 const float* __restrict__ vb, const float* __restrict__ sb,
                                 int hc, int C, float* __restrict__ out) {
    int i = blockIdx.x * blockDim.x + threadIdx.x;
    int Ntot = 3 * hc + C;
    if (i >= Ntot) return;
    float v;
    if (i < hc) v = qb[i];
    else if (i < 2 * hc) v = kb[i - hc];
    else if (i < 3 * hc) v = vb[i - 2 * hc];
    else v = sb[i - 3 * hc];
    out[i] = v;
}

// ---------------- bf16 mma.sync GEMM: C[M,N] = A'[M,K3] @ B'[N,K3]^T + bias ----------------
// tile 128x256, 512 threads (16 warps, 4x4, each 32x64), 3-stage cp.async
#define BM 128
#define BN 256
#define LDT 40
#define SA_BYTES (BM * LDT * 2)
#define SB_BYTES (BN * LDT * 2)
#define GEMM_SMEM (3 * (SA_BYTES + SB_BYTES))

__global__ void __launch_bounds__(512)
gemm_mma_kernel(const __nv_bfloat16* __restrict__ A, const __nv_bfloat16* __restrict__ B,
                const float* __restrict__ bias, float* __restrict__ C,
                int M, int K3, int N) {
    extern __shared__ char smraw[];
    uint32_t aBase = smem_u32(smraw);
    uint32_t bBase = aBase + 3 * SA_BYTES;
    int tid = threadIdx.x;
    int lane = tid & 31, wid = tid >> 5;
    int m0 = blockIdx.y * BM, n0 = blockIdx.x * BN;
    int warp_m = wid >> 2, warp_n = wid & 3;  // 4 x 4
    int m_base = warp_m * 32, n_base = warp_n * 64;

    float acc[2][8][4];
#pragma unroll
    for (int i = 0; i < 2; i++)
#pragma unroll
        for (int j = 0; j < 8; j++)
#pragma unroll
            for (int r = 0; r < 4; r++) acc[i][j][r] = 0.f;

    int nk = K3 >> 5;

    auto load_stage = [&](int st, int kt) {
        // A: 128 rows x 4 chunks -> 512 tasks (1/thread)
        {
            int row = tid >> 2, ch = tid & 3;
            int gr = m0 + row;
            uint32_t sa = aBase + st * SA_BYTES + (row * LDT + ch * 8) * 2;
            const __nv_bfloat16* g = A + (size_t)(gr < M ? gr : 0) * K3 + kt * 32 + ch * 8;
            cp16(sa, g, gr < M);
        }
        // B: 256 rows x 4 chunks -> 1024 tasks (2/thread)
#pragma unroll
        for (int l = 0; l < 2; l++) {
            int idx = tid + l * 512;
            int row = idx >> 2, ch = idx & 3;
            int gn = n0 + row;
            uint32_t sb = bBase + st * SB_BYTES + (row * LDT + ch * 8) * 2;
            const __nv_bfloat16* g = B + (size_t)(gn < N ? gn : 0) * K3 + kt * 32 + ch * 8;
            cp16(sb, g, gn < N);
        }
        cp_commit();
    };

    load_stage(0, 0);
    if (nk > 1) load_stage(1, 1);
    else cp_commit();  // keep group count consistent

    int a_r = lane & 15;
    int a_c = (lane >> 4) * 8;
    int b_r = (lane & 7) + ((lane >> 4) << 3);
    int b_c = ((lane >> 3) & 1) * 8;

    for (int kt = 0; kt < nk; kt++) {
        int st = kt % 3;
        if (kt + 1 < nk) cp_wait1();
        else cp_wait0();
        __syncthreads();
        if (kt + 2 < nk) load_stage((kt + 2) % 3, kt + 2);
        uint32_t sa = aBase + st * SA_BYTES;
        uint32_t sb = bBase + st * SB_BYTES;
#pragma unroll
        for (int ks = 0; ks < 32; ks += 16) {
            uint32_t af[2][4];
#pragma unroll
            for (int im = 0; im < 2; im++)
                ldmx4(af[im], sa + ((m_base + im * 16 + a_r) * LDT + ks + a_c) * 2);
            uint32_t bf[4][4];
#pragma unroll
            for (int ib = 0; ib < 4; ib++)
                ldmx4(bf[ib], sb + ((n_base + ib * 16 + b_r) * LDT + ks + b_c) * 2);
#pragma unroll
            for (int im = 0; im < 2; im++)
#pragma unroll
                for (int jn = 0; jn < 8; jn++)
                    mma_bf16(acc[im][jn], af[im], bf[jn >> 1][(jn & 1) * 2], bf[jn >> 1][(jn & 1) * 2 + 1]);
        }
        __syncthreads();
    }

    // epilogue
#pragma unroll
    for (int im = 0; im < 2; im++) {
        int row0 = m0 + m_base + im * 16 + (lane >> 2);
#pragma unroll
        for (int jn = 0; jn < 8; jn++) {
            int col = n0 + n_base + jn * 8 + (lane & 3) * 2;
            if (col < N) {
                float bx = bias[col], by = bias[col + 1];
                if (row0 < M) {
                    float2 o = make_float2(acc[im][jn][0] + bx, acc[im][jn][1] + by);
                    *(float2*)&C[(size_t)row0 * N + col] = o;
                }
                if (row0 + 8 < M) {
                    float2 o = make_float2(acc[im][jn][2] + bx, acc[im][jn][3] + by);
                    *(float2*)&C[(size_t)(row0 + 8) * N + col] = o;
                }
            }
        }
    }
}

// ---------------- CSR build ----------------
__global__ void hist_kernel(const int* __restrict__ dst, int* __restrict__ deg) {
    int e = blockIdx.x * blockDim.x + threadIdx.x;
    if (e < NE) atomicAdd(&deg[dst[e]], 1);
}
__global__ void csr_scan_kernel(const int* __restrict__ deg, int* __restrict__ rowptr,
                                int* __restrict__ cursor) {
    __shared__ int part[1024];
    int t = threadIdx.x;
    int base = t * 10;
    int local[10];
    int s = 0;
#pragma unroll
    for (int i = 0; i < 10; i++) {
        int idx = base + i;
        local[i] = (idx < NN) ? deg[idx] : 0;
        s += local[i];
    }
    part[t] = s;
    __syncthreads();
    for (int off = 1; off < 1024; off <<= 1) {
        int v = (t >= off) ? part[t - off] : 0;
        __syncthreads();
        part[t] += v;
        __syncthreads();
    }
    int run = (t > 0) ? part[t - 1] : 0;
#pragma unroll
    for (int i = 0; i < 10; i++) {
        int idx = base + i;
        if (idx < NN) {
            rowptr[idx] = run;
            cursor[idx] = run;
            run += local[i];
        }
    }
    if (t == 1023) rowptr[NN] = run;
}
__global__ void scatter_kernel(const int* __restrict__ dst, int* __restrict__ cursor,
                               int* __restrict__ perm) {
    int e = blockIdx.x * blockDim.x + threadIdx.x;
    if (e < NE) {
        int pos = atomicAdd(&cursor[dst[e]], 1);
        perm[pos] = e;
    }
}

// ---------------- fused attention (online softmax), warp per (node, head) ----------------
// q/k/v live inside merged buffer with row stride ld
template <int CC>
__global__ void attn_kernel(const float* __restrict__ q, const float* __restrict__ k,
                            const float* __restrict__ v, int ld,
                            const int* __restrict__ rowptr, const int* __restrict__ perm,
                            const int* __restrict__ src, float* __restrict__ agg, float scale) {
    int w = (blockIdx.x * blockDim.x + threadIdx.x) >> 5;
    int lane = threadIdx.x & 31;
    if (w >= NN * HH) return;
    int n = w / HH, h = w % HH;
    const size_t qbase = (size_t)n * ld + (size_t)h * CC;
    const size_t abase = (size_t)n * (HH * CC) + (size_t)h * CC;
    int j0 = rowptr[n], j1 = rowptr[n + 1];
    float mmax = -INFINITY, den = 0.f;

    if constexpr (CC >= 128) {
        const int R4 = CC / 128;
        float4 qv[R4], acc[R4];
#pragma unroll
        for (int i = 0; i < R4; i++) {
            qv[i] = *(const float4*)(q + qbase + i * 128 + lane * 4);
            acc[i] = make_float4(0.f, 0.f, 0.f, 0.f);
        }
        for (int j = j0; j < j1; j++) {
            int e = perm[j];
            int s = src[e];
            const size_t sb = (size_t)s * ld + (size_t)h * CC;
            float4 kv[R4], vv[R4];
#pragma unroll
            for (int i = 0; i < R4; i++) {
                kv[i] = *(const float4*)(k + sb + i * 128 + lane * 4);
                vv[i] = *(const float4*)(v + sb + i * 128 + lane * 4);
            }
            float dot = 0.f;
#pragma unroll
            for (int i = 0; i < R4; i++) {
                dot = fmaf(qv[i].x, kv[i].x, dot);
                dot = fmaf(qv[i].y, kv[i].y, dot);
                dot = fmaf(qv[i].z, kv[i].z, dot);
                dot = fmaf(qv[i].w, kv[i].w, dot);
            }
#pragma unroll
            for (int o = 16; o; o >>= 1) dot += __shfl_xor_sync(0xFFFFFFFFu, dot, o);
            float a = dot * scale;
            float mnew = fmaxf(mmax, a);
            float corr = __expf(mmax - mnew);
            float wt = __expf(a - mnew);
            den = den * corr + wt;
#pragma unroll
            for (int i = 0; i < R4; i++) {
                acc[i].x = fmaf(wt, vv[i].x, acc[i].x * corr);
                acc[i].y = fmaf(wt, vv[i].y, acc[i].y * corr);
                acc[i].z = fmaf(wt, vv[i].z, acc[i].z * corr);
                acc[i].w = fmaf(wt, vv[i].w, acc[i].w * corr);
            }
            mmax = mnew;
        }
        float inv = 1.f / fmaxf(den, 1e-16f);
#pragma unroll
        for (int i = 0; i < R4; i++) {
            float4 o = make_float4(acc[i].x * inv, acc[i].y * inv, acc[i].z * inv, acc[i].w * inv);
            *(float4*)(agg + abase + i * 128 + lane * 4) = o;
        }
    } else {
        // CC == 64: float2 per lane
        float2 qv = *(const float2*)(q + qbase + lane * 2);
        float2 acc = make_float2(0.f, 0.f);
        for (int j = j0; j < j1; j++) {
            int e = perm[j];
            int s = src[e];
            const size_t sb = (size_t)s * ld + (size_t)h * CC;
            float2 kv = *(const float2*)(k + sb + lane * 2);
            float2 vv = *(const float2*)(v + sb + lane * 2);
            float dot = fmaf(qv.x, kv.x, qv.y * kv.y);
#pragma unroll
            for (int o = 16; o; o >>= 1) dot += __shfl_xor_sync(0xFFFFFFFFu, dot, o);
            float a = dot * scale;
            float mnew = fmaxf(mmax, a);
            float corr = __expf(mmax - mnew);
            float wt = __expf(a - mnew);
            den = den * corr + wt;
            acc.x = fmaf(wt, vv.x, acc.x * corr);
            acc.y = fmaf(wt, vv.y, acc.y * corr);
            mmax = mnew;
        }
        float inv = 1.f / fmaxf(den, 1e-16f);
        *(float2*)(agg + abase + lane * 2) = make_float2(acc.x * inv, acc.y * inv);
    }
}

// ---------------- combine: out = elu(mean_h(agg) + skip) ----------------
__global__ void combine_kernel(const float* __restrict__ agg, const float* __restrict__ skipB,
                               int lds, float* __restrict__ out, int C) {
    int i = blockIdx.x * blockDim.x + threadIdx.x;
    if (i >= NN * C) return;
    int n = i / C, c = i % C;
    const float* ap = agg + (size_t)n * HH * C + c;
    float s = 0.f;
#pragma unroll
    for (int h = 0; h < HH; h++) s += ap[(size_t)h * C];
    float val = s * (1.f / HH) + skipB[(size_t)n * lds + c];
    out[i] = val > 0.f ? val : expm1f(val);
}

// ---------------- pooling ----------------
__global__ void gate_kernel(const float* __restrict__ h, const float* __restrict__ gw,
                            const float* __restrict__ gb, const int* __restrict__ batch,
                            float* __restrict__ gate, float* __restrict__ gm) {
    int n = (blockIdx.x * blockDim.x + threadIdx.x) >> 5;
    int lane = threadIdx.x & 31;
    if (n >= NN) return;
    float s = 0.f;
    for (int c = lane; c < 64; c += 32) s += h[(size_t)n * 64 + c] * gw[c];
#pragma unroll
    for (int o = 16; o; o >>= 1) s += __shfl_xor_sync(0xFFFFFFFFu, s, o);
    if (lane == 0) {
        s += gb[0];
        gate[n] = s;
        atomicMaxFloat(&gm[batch[n]], s);
    }
}
__global__ void gate_exp_kernel(const int* __restrict__ batch, float* __restrict__ gate,
                                const float* __restrict__ gm, float* __restrict__ gd) {
    int n = blockIdx.x * blockDim.x + threadIdx.x;
    if (n >= NN) return;
    int b = batch[n];
    float e = expf(gate[n] - gm[b]);
    gate[n] = e;
    atomicAdd(&gd[b], e);
}
__global__ void pool_kernel(const float* __restrict__ h, const int* __restrict__ batch,
                            const float* __restrict__ gate, const float* __restrict__ gd,
                            float* __restrict__ pool) {
    int i = blockIdx.x * blockDim.x + threadIdx.x;
    if (i >= NN * 64) return;
    int n = i / 64, c = i % 64;
    int b = batch[n];
    float w = gate[n] / fmaxf(gd[b], 1e-16f);
    atomicAdd(&pool[b * 64 + c], w * h[i]);
}
__global__ void fc_kernel(const float* __restrict__ pool, const float* __restrict__ fw,
                          const float* __restrict__ fb, float* __restrict__ out) {
    int i = blockIdx.x * blockDim.x + threadIdx.x;
    if (i >= NG * 10) return;
    int g = i / 10, o = i % 10;
    float s = fb[o];
#pragma unroll
    for (int c = 0; c < 64; c++) s += pool[g * 64 + c] * fw[c * 10 + o];
    out[i] = s;
}

// ---------------- host side ----------------
static inline void launch_fill(float* p, float v, size_t n) {
    fill_kernel<<<(unsigned)((n + 255) / 256), 256>>>(p, v, n);
}

struct Ptrs {
    float *qkvs, *agg, *hA, *hB, *gate, *gm, *gd, *pool, *biasp;
    __nv_bfloat16 *Ac, *Bc;
    int *deg, *rowptr, *cursor, *perm;
};

static void tconv_layer(const float* x, int fin, int C, const float* const* W,
                        const int* src, float* hout, const Ptrs& P) {
    int hc = C * HH;
    int Ntot = 3 * hc + C;
    int K3 = 3 * fin;
    size_t na = (size_t)NN * fin;
    splitA_kernel<<<(unsigned)((na + 255) / 256), 256>>>(x, P.Ac, fin, na);
    dim3 tg((fin + 31) / 32, (hc + 31) / 32);
    splitBT_kernel<<<tg, dim3(32, 8)>>>(W[0], P.Bc, fin, hc, 0);
    splitBT_kernel<<<tg, dim3(32, 8)>>>(W[2], P.Bc, fin, hc, hc);
    splitBT_kernel<<<tg, dim3(32, 8)>>>(W[4], P.Bc, fin, hc, 2 * hc);
    dim3 tg2((fin + 31) / 32, (C + 31) / 32);
    splitBT_kernel<<<tg2, dim3(32, 8)>>>(W[6], P.Bc, fin, C, 3 * hc);
    pack_bias_kernel<<<(Ntot + 255) / 256, 256>>>(W[1], W[3], W[5], W[7], hc, C, P.biasp);

    dim3 grid((Ntot + BN - 1) / BN, (NN + BM - 1) / BM);
    gemm_mma_kernel<<<grid, 512, GEMM_SMEM>>>(P.Ac, P.Bc, P.biasp, P.qkvs, NN, K3, Ntot);

    const float* q = P.qkvs;
    const float* k = P.qkvs + hc;
    const float* v = P.qkvs + 2 * hc;
    const float* skip = P.qkvs + 3 * hc;
    float scale = 1.f / sqrtf((float)C);
    int blocks = (NN * HH * 32 + 255) / 256;
    if (C == 512)
        attn_kernel<512><<<blocks, 256>>>(q, k, v, Ntot, P.rowptr, P.perm, src, P.agg, scale);
    else if (C == 256)
        attn_kernel<256><<<blocks, 256>>>(q, k, v, Ntot, P.rowptr, P.perm, src, P.agg, scale);
    else
        attn_kernel<64><<<blocks, 256>>>(q, k, v, Ntot, P.rowptr, P.perm, src, P.agg, scale);
    combine_kernel<<<(NN * C + 255) / 256, 256>>>(P.agg, skip, Ntot, hout, C);
}

extern "C" void kernel_launch(void* const* d_in, const int* in_sizes, int n_in,
                              void* d_out, int out_size) {
    const float* x     = (const float*)d_in[0];
    const int*   ei    = (const int*)d_in[1];
    const int*   batch = (const int*)d_in[2];
    const float* W[24];
    for (int i = 0; i < 24; i++) W[i] = (const float*)d_in[3 + i];
    const float* gate_w = (const float*)d_in[27];
    const float* gate_b = (const float*)d_in[28];
    const float* fc_w   = (const float*)d_in[29];
    const float* fc_b   = (const float*)d_in[30];
    float* out = (float*)d_out;

    const int* src = ei;
    const int* dst = ei + NE;

    cudaFuncSetAttribute(gemm_mma_kernel, cudaFuncAttributeMaxDynamicSharedMemorySize, GEMM_SMEM);

    Ptrs P;
    cudaGetSymbolAddress((void**)&P.qkvs, g_qkvs);
    cudaGetSymbolAddress((void**)&P.agg, g_agg);
    cudaGetSymbolAddress((void**)&P.hA, g_hA);
    cudaGetSymbolAddress((void**)&P.hB, g_hB);
    cudaGetSymbolAddress((void**)&P.gate, g_gate);
    cudaGetSymbolAddress((void**)&P.gm, g_gm);
    cudaGetSymbolAddress((void**)&P.gd, g_gd);
    cudaGetSymbolAddress((void**)&P.pool, g_pool);
    cudaGetSymbolAddress((void**)&P.biasp, g_biasp);
    cudaGetSymbolAddress((void**)&P.Ac, g_Acomp);
    cudaGetSymbolAddress((void**)&P.Bc, g_Bcomp);
    cudaGetSymbolAddress((void**)&P.deg, g_deg);
    cudaGetSymbolAddress((void**)&P.rowptr, g_rowptr);
    cudaGetSymbolAddress((void**)&P.cursor, g_cursor);
    cudaGetSymbolAddress((void**)&P.perm, g_perm);

    // CSR build
    fill_int_kernel<<<(NN + 255) / 256, 256>>>(P.deg, 0, NN);
    hist_kernel<<<(NE + 255) / 256, 256>>>(dst, P.deg);
    csr_scan_kernel<<<1, 1024>>>(P.deg, P.rowptr, P.cursor);
    scatter_kernel<<<(NE + 255) / 256, 256>>>(dst, P.cursor, P.perm);

    // Layers
    tconv_layer(x,    128, 512, &W[0],  src, P.hA, P);
    tconv_layer(P.hA, 512, 256, &W[8],  src, P.hB, P);
    tconv_layer(P.hB, 256, 64,  &W[16], src, P.hA, P);

    // Global attention pooling on hA [NN, 64]
    launch_fill(P.gm, -INFINITY, NG);
    launch_fill(P.gd, 0.f, NG);
    launch_fill(P.pool, 0.f, (size_t)NG * 64);
    gate_kernel<<<(NN * 32 + 255) / 256, 256>>>(P.hA, gate_w, gate_b, batch, P.gate, P.gm);
    gate_exp_kernel<<<(NN + 255) / 256, 256>>>(batch, P.gate, P.gm, P.gd);
    pool_kernel<<<(NN * 64 + 255) / 256, 256>>>(P.hA, batch, P.gate, P.gd, P.pool);
    fc_kernel<<<(NG * 10 + 255) / 256, 256>>>(P.pool, fc_w, fc_b, out);
}

// round 5
// speedup vs baseline: 3.6242x; 1.2730x over previous
#include <cuda_runtime.h>
#include <cuda_fp16.h>
#include <math.h>
#include <stdint.h>

#define NN 10000
#define NE 30000
#define NG 50
#define HH 8
#define MAXHC 4096
#define NTOT1 12800  // 3*4096+512

// ---------------- scratch (device globals) ----------------
__device__ float g_qkvs[NN * NTOT1];          // merged [q|k|v|skip] output
__device__ float g_agg[NN * MAXHC];
__device__ float g_hA[NN * 512];
__device__ float g_hB[NN * 512];
__device__ float g_gate[NN];
__device__ float g_gm[NG];
__device__ float g_gd[NG];
__device__ float g_pool[NG * 64];
__device__ float g_biasp[NTOT1];
// composite fp16 operands: A' = [hi|lo] (M x 2K), B' = [hi|hi] (Ntot x 2K)
__device__ __half g_Acomp[NN * 1024];
__device__ __half g_Bcomp[6400 * 1024];
// CSR
__device__ int g_deg[NN];
__device__ int g_rowptr[NN + 1];
__device__ int g_cursor[NN];
__device__ int g_perm[NE];

// ---------------- helpers ----------------
__device__ __forceinline__ uint32_t smem_u32(const void* p) {
    uint32_t a;
    asm("{ .reg .u64 t; cvta.to.shared.u64 t, %1; cvt.u32.u64 %0, t; }" : "=r"(a) : "l"(p));
    return a;
}
__device__ __forceinline__ void cp16(uint32_t saddr, const void* g, bool pred) {
    int sz = pred ? 16 : 0;
    asm volatile("cp.async.cg.shared.global [%0], [%1], 16, %2;" :: "r"(saddr), "l"(g), "r"(sz));
}
__device__ __forceinline__ void cp_commit() { asm volatile("cp.async.commit_group;"); }
__device__ __forceinline__ void cp_wait0() { asm volatile("cp.async.wait_group 0;"); }
__device__ __forceinline__ void cp_wait1() { asm volatile("cp.async.wait_group 1;"); }
__device__ __forceinline__ void ldmx4(uint32_t* r, uint32_t addr) {
    asm volatile("ldmatrix.sync.aligned.m8n8.x4.shared.b16 {%0,%1,%2,%3}, [%4];"
                 : "=r"(r[0]), "=r"(r[1]), "=r"(r[2]), "=r"(r[3]) : "r"(addr));
}
__device__ __forceinline__ void mma_fp16(float* c, const uint32_t* a, uint32_t b0, uint32_t b1) {
    asm volatile(
        "mma.sync.aligned.m16n8k16.row.col.f32.f16.f16.f32 "
        "{%0,%1,%2,%3}, {%4,%5,%6,%7}, {%8,%9}, {%0,%1,%2,%3};"
        : "+f"(c[0]), "+f"(c[1]), "+f"(c[2]), "+f"(c[3])
        : "r"(a[0]), "r"(a[1]), "r"(a[2]), "r"(a[3]), "r"(b0), "r"(b1));
}

// ---------------- utility kernels ----------------
__global__ void fill_kernel(float* p, float v, size_t n) {
    size_t i = (size_t)blockIdx.x * blockDim.x + threadIdx.x;
    if (i < n) p[i] = v;
}
__global__ void fill_int_kernel(int* p, int v, int n) {
    int i = blockIdx.x * blockDim.x + threadIdx.x;
    if (i < n) p[i] = v;
}
__device__ __forceinline__ void atomicMaxFloat(float* addr, float v) {
    int* ai = (int*)addr;
    int old = *ai;
    while (__int_as_float(old) < v) {
        int assumed = old;
        old = atomicCAS(ai, assumed, __float_as_int(v));
        if (old == assumed) break;
    }
}

// ---------------- fp32 -> composite fp16 split ----------------
// A' row layout (2K): [0,K)=hi, [K,2K)=lo
__global__ void splitA_kernel(const float* __restrict__ A, __half* __restrict__ out,
                              int K, size_t n) {
    size_t i = (size_t)blockIdx.x * blockDim.x + threadIdx.x;
    if (i >= n) return;
    float x = A[i];
    __half h = __float2half_rn(x);
    __half l = __float2half_rn(x - __half2float(h));
    size_t row = i / K, col = i % K;
    size_t base = row * (size_t)(2 * K) + col;
    out[base] = h;
    out[base + K] = l;
}

// W [K,N] fp32 -> B' rows [rowOff, rowOff+N) of [Ntot, 2K]: [hi | hi]
__global__ void splitBT_kernel(const float* __restrict__ W, __half* __restrict__ out,
                               int K, int N, int rowOff) {
    __shared__ float t[32][33];
    int kb = blockIdx.x * 32, nb = blockIdx.y * 32;
    int tx = threadIdx.x, ty = threadIdx.y;  // 32 x 8
    for (int r = ty; r < 32; r += 8) {
        int kk = kb + r, nn2 = nb + tx;
        t[r][tx] = (kk < K && nn2 < N) ? W[(size_t)kk * N + nn2] : 0.f;
    }
    __syncthreads();
    for (int r = ty; r < 32; r += 8) {
        int nn2 = nb + r, kk = kb + tx;
        if (nn2 < N && kk < K) {
            __half h = __float2half_rn(t[tx][r]);
            size_t base = (size_t)(rowOff + nn2) * (2 * K) + kk;
            out[base] = h;
            out[base + K] = h;
        }
    }
}

__global__ void pack_bias_kernel(const float* __restrict__ qb, const float* __restrict__ kb,
                                 const float* __restrict__ vb, const float* __restrict__ sb,
                                 int hc, int C, float* __restrict__ out) {
    int i = blockIdx.x * blockDim.x + threadIdx.x;
    int Ntot = 3 * hc + C;
    if (i >= Ntot) return;
    float v;
    if (i < hc) v = qb[i];
    else if (i < 2 * hc) v = kb[i - hc];
    else if (i < 3 * hc) v = vb[i - 2 * hc];
    else v = sb[i - 3 * hc];
    out[i] = v;
}

// ---------------- fp16 mma.sync GEMM: C[M,N] = A'[M,K2] @ B'[N,K2]^T + bias ----------------
// tile 128x256, 512 threads (16 warps, 4x4, each 32x64), 3-stage cp.async
#define BM 128
#define BN 256
#define LDT 40
#define SA_BYTES (BM * LDT * 2)
#define SB_BYTES (BN * LDT * 2)
#define GEMM_SMEM (3 * (SA_BYTES + SB_BYTES))

__global__ void __launch_bounds__(512)
gemm_mma_kernel(const __half* __restrict__ A, const __half* __restrict__ B,
                const float* __restrict__ bias, float* __restrict__ C,
                int M, int K2, int N) {
    extern __shared__ char smraw[];
    uint32_t aBase = smem_u32(smraw);
    uint32_t bBase = aBase + 3 * SA_BYTES;
    int tid = threadIdx.x;
    int lane = tid & 31, wid = tid >> 5;
    int m0 = blockIdx.y * BM, n0 = blockIdx.x * BN;
    int warp_m = wid >> 2, warp_n = wid & 3;  // 4 x 4
    int m_base = warp_m * 32, n_base = warp_n * 64;

    float acc[2][8][4];
#pragma unroll
    for (int i = 0; i < 2; i++)
#pragma unroll
        for (int j = 0; j < 8; j++)
#pragma unroll
            for (int r = 0; r < 4; r++) acc[i][j][r] = 0.f;

    int nk = K2 >> 5;

    auto load_stage = [&](int st, int kt) {
        {
            int row = tid >> 2, ch = tid & 3;
            int gr = m0 + row;
            uint32_t sa = aBase + st * SA_BYTES + (row * LDT + ch * 8) * 2;
            const __half* g = A + (size_t)(gr < M ? gr : 0) * K2 + kt * 32 + ch * 8;
            cp16(sa, g, gr < M);
        }
#pragma unroll
        for (int l = 0; l < 2; l++) {
            int idx = tid + l * 512;
            int row = idx >> 2, ch = idx & 3;
            int gn = n0 + row;
            uint32_t sb = bBase + st * SB_BYTES + (row * LDT + ch * 8) * 2;
            const __half* g = B + (size_t)(gn < N ? gn : 0) * K2 + kt * 32 + ch * 8;
            cp16(sb, g, gn < N);
        }
        cp_commit();
    };

    load_stage(0, 0);
    if (nk > 1) load_stage(1, 1);
    else cp_commit();

    int a_r = lane & 15;
    int a_c = (lane >> 4) * 8;
    int b_r = (lane & 7) + ((lane >> 4) << 3);
    int b_c = ((lane >> 3) & 1) * 8;

    for (int kt = 0; kt < nk; kt++) {
        int st = kt % 3;
        if (kt + 1 < nk) cp_wait1();
        else cp_wait0();
        __syncthreads();
        if (kt + 2 < nk) load_stage((kt + 2) % 3, kt + 2);
        uint32_t sa = aBase + st * SA_BYTES;
        uint32_t sb = bBase + st * SB_BYTES;
#pragma unroll
        for (int ks = 0; ks < 32; ks += 16) {
            uint32_t af[2][4];
#pragma unroll
            for (int im = 0; im < 2; im++)
                ldmx4(af[im], sa + ((m_base + im * 16 + a_r) * LDT + ks + a_c) * 2);
            uint32_t bf[4][4];
#pragma unroll
            for (int ib = 0; ib < 4; ib++)
                ldmx4(bf[ib], sb + ((n_base + ib * 16 + b_r) * LDT + ks + b_c) * 2);
#pragma unroll
            for (int im = 0; im < 2; im++)
#pragma unroll
                for (int jn = 0; jn < 8; jn++)
                    mma_fp16(acc[im][jn], af[im], bf[jn >> 1][(jn & 1) * 2], bf[jn >> 1][(jn & 1) * 2 + 1]);
        }
        __syncthreads();
    }

#pragma unroll
    for (int im = 0; im < 2; im++) {
        int row0 = m0 + m_base + im * 16 + (lane >> 2);
#pragma unroll
        for (int jn = 0; jn < 8; jn++) {
            int col = n0 + n_base + jn * 8 + (lane & 3) * 2;
            if (col < N) {
                float bx = bias[col], by = bias[col + 1];
                if (row0 < M) {
                    float2 o = make_float2(acc[im][jn][0] + bx, acc[im][jn][1] + by);
                    *(float2*)&C[(size_t)row0 * N + col] = o;
                }
                if (row0 + 8 < M) {
                    float2 o = make_float2(acc[im][jn][2] + bx, acc[im][jn][3] + by);
                    *(float2*)&C[(size_t)(row0 + 8) * N + col] = o;
                }
            }
        }
    }
}

// ---------------- CSR build ----------------
__global__ void hist_kernel(const int* __restrict__ dst, int* __restrict__ deg) {
    int e = blockIdx.x * blockDim.x + threadIdx.x;
    if (e < NE) atomicAdd(&deg[dst[e]], 1);
}
__global__ void csr_scan_kernel(const int* __restrict__ deg, int* __restrict__ rowptr,
                                int* __restrict__ cursor) {
    __shared__ int part[1024];
    int t = threadIdx.x;
    int base = t * 10;
    int local[10];
    int s = 0;
#pragma unroll
    for (int i = 0; i < 10; i++) {
        int idx = base + i;
        local[i] = (idx < NN) ? deg[idx] : 0;
        s += local[i];
    }
    part[t] = s;
    __syncthreads();
    for (int off = 1; off < 1024; off <<= 1) {
        int v = (t >= off) ? part[t - off] : 0;
        __syncthreads();
        part[t] += v;
        __syncthreads();
    }
    int run = (t > 0) ? part[t - 1] : 0;
#pragma unroll
    for (int i = 0; i < 10; i++) {
        int idx = base + i;
        if (idx < NN) {
            rowptr[idx] = run;
            cursor[idx] = run;
            run += local[i];
        }
    }
    if (t == 1023) rowptr[NN] = run;
}
__global__ void scatter_kernel(const int* __restrict__ dst, int* __restrict__ cursor,
                               int* __restrict__ perm) {
    int e = blockIdx.x * blockDim.x + threadIdx.x;
    if (e < NE) {
        int pos = atomicAdd(&cursor[dst[e]], 1);
        perm[pos] = e;
    }
}

// ---------------- fused attention (online softmax), warp per (node, head) ----------------
template <int CC>
__global__ void attn_kernel(const float* __restrict__ q, const float* __restrict__ k,
                            const float* __restrict__ v, int ld,
                            const int* __restrict__ rowptr, const int* __restrict__ perm,
                            const int* __restrict__ src, float* __restrict__ agg, float scale) {
    int w = (blockIdx.x * blockDim.x + threadIdx.x) >> 5;
    int lane = threadIdx.x & 31;
    if (w >= NN * HH) return;
    int n = w / HH, h = w % HH;
    const size_t qbase = (size_t)n * ld + (size_t)h * CC;
    const size_t abase = (size_t)n * (HH * CC) + (size_t)h * CC;
    int j0 = rowptr[n], j1 = rowptr[n + 1];
    float mmax = -INFINITY, den = 0.f;

    if constexpr (CC >= 128) {
        const int R4 = CC / 128;
        float4 qv[R4], acc[R4];
#pragma unroll
        for (int i = 0; i < R4; i++) {
            qv[i] = *(const float4*)(q + qbase + i * 128 + lane * 4);
            acc[i] = make_float4(0.f, 0.f, 0.f, 0.f);
        }
        for (int j = j0; j < j1; j++) {
            int e = perm[j];
            int s = src[e];
            const size_t sb = (size_t)s * ld + (size_t)h * CC;
            float4 kv[R4], vv[R4];
#pragma unroll
            for (int i = 0; i < R4; i++) {
                kv[i] = *(const float4*)(k + sb + i * 128 + lane * 4);
                vv[i] = *(const float4*)(v + sb + i * 128 + lane * 4);
            }
            float dot = 0.f;
#pragma unroll
            for (int i = 0; i < R4; i++) {
                dot = fmaf(qv[i].x, kv[i].x, dot);
                dot = fmaf(qv[i].y, kv[i].y, dot);
                dot = fmaf(qv[i].z, kv[i].z, dot);
                dot = fmaf(qv[i].w, kv[i].w, dot);
            }
#pragma unroll
            for (int o = 16; o; o >>= 1) dot += __shfl_xor_sync(0xFFFFFFFFu, dot, o);
            float a = dot * scale;
            float mnew = fmaxf(mmax, a);
            float corr = __expf(mmax - mnew);
            float wt = __expf(a - mnew);
            den = den * corr + wt;
#pragma unroll
            for (int i = 0; i < R4; i++) {
                acc[i].x = fmaf(wt, vv[i].x, acc[i].x * corr);
                acc[i].y = fmaf(wt, vv[i].y, acc[i].y * corr);
                acc[i].z = fmaf(wt, vv[i].z, acc[i].z * corr);
                acc[i].w = fmaf(wt, vv[i].w, acc[i].w * corr);
            }
            mmax = mnew;
        }
        float inv = 1.f / fmaxf(den, 1e-16f);
#pragma unroll
        for (int i = 0; i < R4; i++) {
            float4 o = make_float4(acc[i].x * inv, acc[i].y * inv, acc[i].z * inv, acc[i].w * inv);
            *(float4*)(agg + abase + i * 128 + lane * 4) = o;
        }
    } else {
        float2 qv = *(const float2*)(q + qbase + lane * 2);
        float2 acc = make_float2(0.f, 0.f);
        for (int j = j0; j < j1; j++) {
            int e = perm[j];
            int s = src[e];
            const size_t sb = (size_t)s * ld + (size_t)h * CC;
            float2 kv = *(const float2*)(k + sb + lane * 2);
            float2 vv = *(const float2*)(v + sb + lane * 2);
            float dot = fmaf(qv.x, kv.x, qv.y * kv.y);
#pragma unroll
            for (int o = 16; o; o >>= 1) dot += __shfl_xor_sync(0xFFFFFFFFu, dot, o);
            float a = dot * scale;
            float mnew = fmaxf(mmax, a);
            float corr = __expf(mmax - mnew);
            float wt = __expf(a - mnew);
            den = den * corr + wt;
            acc.x = fmaf(wt, vv.x, acc.x * corr);
            acc.y = fmaf(wt, vv.y, acc.y * corr);
            mmax = mnew;
        }
        float inv = 1.f / fmaxf(den, 1e-16f);
        *(float2*)(agg + abase + lane * 2) = make_float2(acc.x * inv, acc.y * inv);
    }
}

// ---------------- combine: out = elu(mean_h(agg) + skip); optional fused split for next layer ----------------
__global__ void combine_kernel(const float* __restrict__ agg, const float* __restrict__ skipB,
                               int lds, float* __restrict__ out, int C,
                               __half* __restrict__ Anext) {
    int i = blockIdx.x * blockDim.x + threadIdx.x;
    if (i >= NN * C) return;
    int n = i / C, c = i % C;
    const float* ap = agg + (size_t)n * HH * C + c;
    float s = 0.f;
#pragma unroll
    for (int h = 0; h < HH; h++) s += ap[(size_t)h * C];
    float val = s * (1.f / HH) + skipB[(size_t)n * lds + c];
    val = val > 0.f ? val : expm1f(val);
    out[i] = val;
    if (Anext) {
        __half hi = __float2half_rn(val);
        __half lo = __float2half_rn(val - __half2float(hi));
        size_t base = (size_t)n * (2 * C) + c;
        Anext[base] = hi;
        Anext[base + C] = lo;
    }
}

// ---------------- pooling ----------------
__global__ void gate_kernel(const float* __restrict__ h, const float* __restrict__ gw,
                            const float* __restrict__ gb, const int* __restrict__ batch,
                            float* __restrict__ gate, float* __restrict__ gm) {
    int n = (blockIdx.x * blockDim.x + threadIdx.x) >> 5;
    int lane = threadIdx.x & 31;
    if (n >= NN) return;
    float s = 0.f;
    for (int c = lane; c < 64; c += 32) s += h[(size_t)n * 64 + c] * gw[c];
#pragma unroll
    for (int o = 16; o; o >>= 1) s += __shfl_xor_sync(0xFFFFFFFFu, s, o);
    if (lane == 0) {
        s += gb[0];
        gate[n] = s;
        atomicMaxFloat(&gm[batch[n]], s);
    }
}
__global__ void gate_exp_kernel(const int* __restrict__ batch, float* __restrict__ gate,
                                const float* __restrict__ gm, float* __restrict__ gd) {
    int n = blockIdx.x * blockDim.x + threadIdx.x;
    if (n >= NN) return;
    int b = batch[n];
    float e = expf(gate[n] - gm[b]);
    gate[n] = e;
    atomicAdd(&gd[b], e);
}
__global__ void pool_kernel(const float* __restrict__ h, const int* __restrict__ batch,
                            const float* __restrict__ gate, const float* __restrict__ gd,
                            float* __restrict__ pool) {
    int i = blockIdx.x * blockDim.x + threadIdx.x;
    if (i >= NN * 64) return;
    int n = i / 64, c = i % 64;
    int b = batch[n];
    float w = gate[n] / fmaxf(gd[b], 1e-16f);
    atomicAdd(&pool[b * 64 + c], w * h[i]);
}
__global__ void fc_kernel(const float* __restrict__ pool, const float* __restrict__ fw,
                          const float* __restrict__ fb, float* __restrict__ out) {
    int i = blockIdx.x * blockDim.x + threadIdx.x;
    if (i >= NG * 10) return;
    int g = i / 10, o = i % 10;
    float s = fb[o];
#pragma unroll
    for (int c = 0; c < 64; c++) s += pool[g * 64 + c] * fw[c * 10 + o];
    out[i] = s;
}

// ---------------- host side ----------------
static inline void launch_fill(float* p, float v, size_t n) {
    fill_kernel<<<(unsigned)((n + 255) / 256), 256>>>(p, v, n);
}

struct Ptrs {
    float *qkvs, *agg, *hA, *hB, *gate, *gm, *gd, *pool, *biasp;
    __half *Ac, *Bc;
    int *deg, *rowptr, *cursor, *perm;
};

// A' (P.Ac) must already contain this layer's [hi|lo]
static void tconv_layer(int fin, int C, const float* const* W, const int* src,
                        float* hout, __half* Anext, const Ptrs& P) {
    int hc = C * HH;
    int Ntot = 3 * hc + C;
    int K2 = 2 * fin;
    dim3 tg((fin + 31) / 32, (hc + 31) / 32);
    splitBT_kernel<<<tg, dim3(32, 8)>>>(W[0], P.Bc, fin, hc, 0);
    splitBT_kernel<<<tg, dim3(32, 8)>>>(W[2], P.Bc, fin, hc, hc);
    splitBT_kernel<<<tg, dim3(32, 8)>>>(W[4], P.Bc, fin, hc, 2 * hc);
    dim3 tg2((fin + 31) / 32, (C + 31) / 32);
    splitBT_kernel<<<tg2, dim3(32, 8)>>>(W[6], P.Bc, fin, C, 3 * hc);
    pack_bias_kernel<<<(Ntot + 255) / 256, 256>>>(W[1], W[3], W[5], W[7], hc, C, P.biasp);

    dim3 grid((Ntot + BN - 1) / BN, (NN + BM - 1) / BM);
    gemm_mma_kernel<<<grid, 512, GEMM_SMEM>>>(P.Ac, P.Bc, P.biasp, P.qkvs, NN, K2, Ntot);

    const float* q = P.qkvs;
    const float* k = P.qkvs + hc;
    const float* v = P.qkvs + 2 * hc;
    const float* skip = P.qkvs + 3 * hc;
    float scale = 1.f / sqrtf((float)C);
    int blocks = (NN * HH * 32 + 255) / 256;
    if (C == 512)
        attn_kernel<512><<<blocks, 256>>>(q, k, v, Ntot, P.rowptr, P.perm, src, P.agg, scale);
    else if (C == 256)
        attn_kernel<256><<<blocks, 256>>>(q, k, v, Ntot, P.rowptr, P.perm, src, P.agg, scale);
    else
        attn_kernel<64><<<blocks, 256>>>(q, k, v, Ntot, P.rowptr, P.perm, src, P.agg, scale);
    combine_kernel<<<(NN * C + 255) / 256, 256>>>(P.agg, skip, Ntot, hout, C, Anext);
}

extern "C" void kernel_launch(void* const* d_in, const int* in_sizes, int n_in,
                              void* d_out, int out_size) {
    const float* x     = (const float*)d_in[0];
    const int*   ei    = (const int*)d_in[1];
    const int*   batch = (const int*)d_in[2];
    const float* W[24];
    for (int i = 0; i < 24; i++) W[i] = (const float*)d_in[3 + i];
    const float* gate_w = (const float*)d_in[27];
    const float* gate_b = (const float*)d_in[28];
    const float* fc_w   = (const float*)d_in[29];
    const float* fc_b   = (const float*)d_in[30];
    float* out = (float*)d_out;

    const int* src = ei;
    const int* dst = ei + NE;

    cudaFuncSetAttribute(gemm_mma_kernel, cudaFuncAttributeMaxDynamicSharedMemorySize, GEMM_SMEM);

    Ptrs P;
    cudaGetSymbolAddress((void**)&P.qkvs, g_qkvs);
    cudaGetSymbolAddress((void**)&P.agg, g_agg);
    cudaGetSymbolAddress((void**)&P.hA, g_hA);
    cudaGetSymbolAddress((void**)&P.hB, g_hB);
    cudaGetSymbolAddress((void**)&P.gate, g_gate);
    cudaGetSymbolAddress((void**)&P.gm, g_gm);
    cudaGetSymbolAddress((void**)&P.gd, g_gd);
    cudaGetSymbolAddress((void**)&P.pool, g_pool);
    cudaGetSymbolAddress((void**)&P.biasp, g_biasp);
    cudaGetSymbolAddress((void**)&P.Ac, g_Acomp);
    cudaGetSymbolAddress((void**)&P.Bc, g_Bcomp);
    cudaGetSymbolAddress((void**)&P.deg, g_deg);
    cudaGetSymbolAddress((void**)&P.rowptr, g_rowptr);
    cudaGetSymbolAddress((void**)&P.cursor, g_cursor);
    cudaGetSymbolAddress((void**)&P.perm, g_perm);

    // CSR build
    fill_int_kernel<<<(NN + 255) / 256, 256>>>(P.deg, 0, NN);
    hist_kernel<<<(NE + 255) / 256, 256>>>(dst, P.deg);
    csr_scan_kernel<<<1, 1024>>>(P.deg, P.rowptr, P.cursor);
    scatter_kernel<<<(NE + 255) / 256, 256>>>(dst, P.cursor, P.perm);

    // Layer 1 A' from x
    size_t na = (size_t)NN * 128;
    splitA_kernel<<<(unsigned)((na + 255) / 256), 256>>>(x, P.Ac, 128, na);
    tconv_layer(128, 512, &W[0],  src, P.hA, P.Ac, P);  // combine writes next A' (C=512)
    tconv_layer(512, 256, &W[8],  src, P.hB, P.Ac, P);  // combine writes next A' (C=256)
    tconv_layer(256, 64,  &W[16], src, P.hA, nullptr, P);

    // Global attention pooling on hA [NN, 64]
    launch_fill(P.gm, -INFINITY, NG);
    launch_fill(P.gd, 0.f, NG);
    launch_fill(P.pool, 0.f, (size_t)NG * 64);
    gate_kernel<<<(NN * 32 + 255) / 256, 256>>>(P.hA, gate_w, gate_b, batch, P.gate, P.gm);
    gate_exp_kernel<<<(NN + 255) / 256, 256>>>(batch, P.gate, P.gm, P.gd);
    pool_kernel<<<(NN * 64 + 255) / 256, 256>>>(P.hA, batch, P.gate, P.gd, P.pool);
    fc_kernel<<<(NG * 10 + 255) / 256, 256>>>(P.pool, fc_w, fc_b, out);
}

// round 6
// speedup vs baseline: 4.8595x; 1.3409x over previous
#include <cuda_runtime.h>
#include <cuda_fp16.h>
#include <math.h>
#include <stdint.h>

#define NN 10000
#define NE 30000
#define NG 50
#define HH 8
#define MAXHC 4096
#define NTOT1 12800  // 3*4096+512

// ---------------- scratch (device globals) ----------------
__device__ float g_qkvs[NN * NTOT1];          // merged [q|k|v|skip] output
__device__ float g_agg[NN * MAXHC];
__device__ float g_hA[NN * 512];
__device__ float g_hB[NN * 512];
__device__ float g_gate[NN];
__device__ float g_gm[NG];
__device__ float g_gd[NG];
__device__ float g_pool[NG * 64];
__device__ float g_biasp[NTOT1];
// fp16 operands: A' = hi(A) (M x K), B' = hi(W)^T (Ntot x K)
__device__ __half g_Acomp[NN * 512];
__device__ __half g_Bcomp[6400 * 512];
// CSR
__device__ int g_deg[NN];
__device__ int g_rowptr[NN + 1];
__device__ int g_cursor[NN];
__device__ int g_perm[NE];

// ---------------- helpers ----------------
__device__ __forceinline__ uint32_t smem_u32(const void* p) {
    uint32_t a;
    asm("{ .reg .u64 t; cvta.to.shared.u64 t, %1; cvt.u32.u64 %0, t; }" : "=r"(a) : "l"(p));
    return a;
}
__device__ __forceinline__ void cp16(uint32_t saddr, const void* g, bool pred) {
    int sz = pred ? 16 : 0;
    asm volatile("cp.async.cg.shared.global [%0], [%1], 16, %2;" :: "r"(saddr), "l"(g), "r"(sz));
}
__device__ __forceinline__ void cp_commit() { asm volatile("cp.async.commit_group;"); }
__device__ __forceinline__ void cp_wait0() { asm volatile("cp.async.wait_group 0;"); }
__device__ __forceinline__ void cp_wait1() { asm volatile("cp.async.wait_group 1;"); }
__device__ __forceinline__ void ldmx4(uint32_t* r, uint32_t addr) {
    asm volatile("ldmatrix.sync.aligned.m8n8.x4.shared.b16 {%0,%1,%2,%3}, [%4];"
                 : "=r"(r[0]), "=r"(r[1]), "=r"(r[2]), "=r"(r[3]) : "r"(addr));
}
__device__ __forceinline__ void mma_fp16(float* c, const uint32_t* a, uint32_t b0, uint32_t b1) {
    asm volatile(
        "mma.sync.aligned.m16n8k16.row.col.f32.f16.f16.f32 "
        "{%0,%1,%2,%3}, {%4,%5,%6,%7}, {%8,%9}, {%0,%1,%2,%3};"
        : "+f"(c[0]), "+f"(c[1]), "+f"(c[2]), "+f"(c[3])
        : "r"(a[0]), "r"(a[1]), "r"(a[2]), "r"(a[3]), "r"(b0), "r"(b1));
}

// ---------------- utility kernels ----------------
__global__ void fill_kernel(float* p, float v, size_t n) {
    size_t i = (size_t)blockIdx.x * blockDim.x + threadIdx.x;
    if (i < n) p[i] = v;
}
__global__ void fill_int_kernel(int* p, int v, int n) {
    int i = blockIdx.x * blockDim.x + threadIdx.x;
    if (i < n) p[i] = v;
}
__device__ __forceinline__ void atomicMaxFloat(float* addr, float v) {
    int* ai = (int*)addr;
    int old = *ai;
    while (__int_as_float(old) < v) {
        int assumed = old;
        old = atomicCAS(ai, assumed, __float_as_int(v));
        if (old == assumed) break;
    }
}

// ---------------- fp32 -> fp16 convert ----------------
__global__ void convA_kernel(const float* __restrict__ A, __half* __restrict__ out, size_t n) {
    size_t i = (size_t)blockIdx.x * blockDim.x + threadIdx.x;
    if (i >= n) return;
    out[i] = __float2half_rn(A[i]);
}

// W [K,N] fp32 -> B' rows [rowOff, rowOff+N) of [Ntot, K] fp16
__global__ void convBT_kernel(const float* __restrict__ W, __half* __restrict__ out,
                              int K, int N, int rowOff) {
    __shared__ float t[32][33];
    int kb = blockIdx.x * 32, nb = blockIdx.y * 32;
    int tx = threadIdx.x, ty = threadIdx.y;  // 32 x 8
    for (int r = ty; r < 32; r += 8) {
        int kk = kb + r, nn2 = nb + tx;
        t[r][tx] = (kk < K && nn2 < N) ? W[(size_t)kk * N + nn2] : 0.f;
    }
    __syncthreads();
    for (int r = ty; r < 32; r += 8) {
        int nn2 = nb + r, kk = kb + tx;
        if (nn2 < N && kk < K)
            out[(size_t)(rowOff + nn2) * K + kk] = __float2half_rn(t[tx][r]);
    }
}

__global__ void pack_bias_kernel(const float* __restrict__ qb, const float* __restrict__ kb,
                                 const float* __restrict__ vb, const float* __restrict__ sb,
                                 int hc, int C, float* __restrict__ out) {
    int i = blockIdx.x * blockDim.x + threadIdx.x;
    int Ntot = 3 * hc + C;
    if (i >= Ntot) return;
    float v;
    if (i < hc) v = qb[i];
    else if (i < 2 * hc) v = kb[i - hc];
    else if (i < 3 * hc) v = vb[i - 2 * hc];
    else v = sb[i - 3 * hc];
    out[i] = v;
}

// ---------------- fp16 mma.sync GEMM: C[M,N] = A[M,K] @ B[N,K]^T + bias ----------------
// tile 128x256, 512 threads (16 warps, 4x4, each 32x64), 3-stage cp.async
#define BM 128
#define BN 256
#define LDT 40
#define SA_BYTES (BM * LDT * 2)
#define SB_BYTES (BN * LDT * 2)
#define GEMM_SMEM (3 * (SA_BYTES + SB_BYTES))

__global__ void __launch_bounds__(512)
gemm_mma_kernel(const __half* __restrict__ A, const __half* __restrict__ B,
                const float* __restrict__ bias, float* __restrict__ C,
                int M, int K, int N) {
    extern __shared__ char smraw[];
    uint32_t aBase = smem_u32(smraw);
    uint32_t bBase = aBase + 3 * SA_BYTES;
    int tid = threadIdx.x;
    int lane = tid & 31, wid = tid >> 5;
    int m0 = blockIdx.y * BM, n0 = blockIdx.x * BN;
    int warp_m = wid >> 2, warp_n = wid & 3;  // 4 x 4
    int m_base = warp_m * 32, n_base = warp_n * 64;

    float acc[2][8][4];
#pragma unroll
    for (int i = 0; i < 2; i++)
#pragma unroll
        for (int j = 0; j < 8; j++)
#pragma unroll
            for (int r = 0; r < 4; r++) acc[i][j][r] = 0.f;

    int nk = K >> 5;

    auto load_stage = [&](int st, int kt) {
        {
            int row = tid >> 2, ch = tid & 3;
            int gr = m0 + row;
            uint32_t sa = aBase + st * SA_BYTES + (row * LDT + ch * 8) * 2;
            const __half* g = A + (size_t)(gr < M ? gr : 0) * K + kt * 32 + ch * 8;
            cp16(sa, g, gr < M);
        }
#pragma unroll
        for (int l = 0; l < 2; l++) {
            int idx = tid + l * 512;
            int row = idx >> 2, ch = idx & 3;
            int gn = n0 + row;
            uint32_t sb = bBase + st * SB_BYTES + (row * LDT + ch * 8) * 2;
            const __half* g = B + (size_t)(gn < N ? gn : 0) * K + kt * 32 + ch * 8;
            cp16(sb, g, gn < N);
        }
        cp_commit();
    };

    load_stage(0, 0);
    if (nk > 1) load_stage(1, 1);
    else cp_commit();

    int a_r = lane & 15;
    int a_c = (lane >> 4) * 8;
    int b_r = (lane & 7) + ((lane >> 4) << 3);
    int b_c = ((lane >> 3) & 1) * 8;

    for (int kt = 0; kt < nk; kt++) {
        int st = kt % 3;
        if (kt + 1 < nk) cp_wait1();
        else cp_wait0();
        __syncthreads();
        if (kt + 2 < nk) load_stage((kt + 2) % 3, kt + 2);
        uint32_t sa = aBase + st * SA_BYTES;
        uint32_t sb = bBase + st * SB_BYTES;
#pragma unroll
        for (int ks = 0; ks < 32; ks += 16) {
            uint32_t af[2][4];
#pragma unroll
            for (int im = 0; im < 2; im++)
                ldmx4(af[im], sa + ((m_base + im * 16 + a_r) * LDT + ks + a_c) * 2);
            uint32_t bf[4][4];
#pragma unroll
            for (int ib = 0; ib < 4; ib++)
                ldmx4(bf[ib], sb + ((n_base + ib * 16 + b_r) * LDT + ks + b_c) * 2);
#pragma unroll
            for (int im = 0; im < 2; im++)
#pragma unroll
                for (int jn = 0; jn < 8; jn++)
                    mma_fp16(acc[im][jn], af[im], bf[jn >> 1][(jn & 1) * 2], bf[jn >> 1][(jn & 1) * 2 + 1]);
        }
        __syncthreads();
    }

#pragma unroll
    for (int im = 0; im < 2; im++) {
        int row0 = m0 + m_base + im * 16 + (lane >> 2);
#pragma unroll
        for (int jn = 0; jn < 8; jn++) {
            int col = n0 + n_base + jn * 8 + (lane & 3) * 2;
            if (col < N) {
                float bx = bias[col], by = bias[col + 1];
                if (row0 < M) {
                    float2 o = make_float2(acc[im][jn][0] + bx, acc[im][jn][1] + by);
                    *(float2*)&C[(size_t)row0 * N + col] = o;
                }
                if (row0 + 8 < M) {
                    float2 o = make_float2(acc[im][jn][2] + bx, acc[im][jn][3] + by);
                    *(float2*)&C[(size_t)(row0 + 8) * N + col] = o;
                }
            }
        }
    }
}

// ---------------- CSR build ----------------
__global__ void hist_kernel(const int* __restrict__ dst, int* __restrict__ deg) {
    int e = blockIdx.x * blockDim.x + threadIdx.x;
    if (e < NE) atomicAdd(&deg[dst[e]], 1);
}
__global__ void csr_scan_kernel(const int* __restrict__ deg, int* __restrict__ rowptr,
                                int* __restrict__ cursor) {
    __shared__ int part[1024];
    int t = threadIdx.x;
    int base = t * 10;
    int local[10];
    int s = 0;
#pragma unroll
    for (int i = 0; i < 10; i++) {
        int idx = base + i;
        local[i] = (idx < NN) ? deg[idx] : 0;
        s += local[i];
    }
    part[t] = s;
    __syncthreads();
    for (int off = 1; off < 1024; off <<= 1) {
        int v = (t >= off) ? part[t - off] : 0;
        __syncthreads();
        part[t] += v;
        __syncthreads();
    }
    int run = (t > 0) ? part[t - 1] : 0;
#pragma unroll
    for (int i = 0; i < 10; i++) {
        int idx = base + i;
        if (idx < NN) {
            rowptr[idx] = run;
            cursor[idx] = run;
            run += local[i];
        }
    }
    if (t == 1023) rowptr[NN] = run;
}
__global__ void scatter_kernel(const int* __restrict__ dst, int* __restrict__ cursor,
                               int* __restrict__ perm) {
    int e = blockIdx.x * blockDim.x + threadIdx.x;
    if (e < NE) {
        int pos = atomicAdd(&cursor[dst[e]], 1);
        perm[pos] = e;
    }
}

// ---------------- fused attention (online softmax), warp per (node, head) ----------------
template <int CC>
__global__ void attn_kernel(const float* __restrict__ q, const float* __restrict__ k,
                            const float* __restrict__ v, int ld,
                            const int* __restrict__ rowptr, const int* __restrict__ perm,
                            const int* __restrict__ src, float* __restrict__ agg, float scale) {
    int w = (blockIdx.x * blockDim.x + threadIdx.x) >> 5;
    int lane = threadIdx.x & 31;
    if (w >= NN * HH) return;
    int n = w / HH, h = w % HH;
    const size_t qbase = (size_t)n * ld + (size_t)h * CC;
    const size_t abase = (size_t)n * (HH * CC) + (size_t)h * CC;
    int j0 = rowptr[n], j1 = rowptr[n + 1];
    float mmax = -INFINITY, den = 0.f;

    if constexpr (CC >= 128) {
        const int R4 = CC / 128;
        float4 qv[R4], acc[R4];
#pragma unroll
        for (int i = 0; i < R4; i++) {
            qv[i] = *(const float4*)(q + qbase + i * 128 + lane * 4);
            acc[i] = make_float4(0.f, 0.f, 0.f, 0.f);
        }
        for (int j = j0; j < j1; j++) {
            int e = perm[j];
            int s = src[e];
            const size_t sb = (size_t)s * ld + (size_t)h * CC;
            float4 kv[R4], vv[R4];
#pragma unroll
            for (int i = 0; i < R4; i++) {
                kv[i] = *(const float4*)(k + sb + i * 128 + lane * 4);
                vv[i] = *(const float4*)(v + sb + i * 128 + lane * 4);
            }
            float dot = 0.f;
#pragma unroll
            for (int i = 0; i < R4; i++) {
                dot = fmaf(qv[i].x, kv[i].x, dot);
                dot = fmaf(qv[i].y, kv[i].y, dot);
                dot = fmaf(qv[i].z, kv[i].z, dot);
                dot = fmaf(qv[i].w, kv[i].w, dot);
            }
#pragma unroll
            for (int o = 16; o; o >>= 1) dot += __shfl_xor_sync(0xFFFFFFFFu, dot, o);
            float a = dot * scale;
            float mnew = fmaxf(mmax, a);
            float corr = __expf(mmax - mnew);
            float wt = __expf(a - mnew);
            den = den * corr + wt;
#pragma unroll
            for (int i = 0; i < R4; i++) {
                acc[i].x = fmaf(wt, vv[i].x, acc[i].x * corr);
                acc[i].y = fmaf(wt, vv[i].y, acc[i].y * corr);
                acc[i].z = fmaf(wt, vv[i].z, acc[i].z * corr);
                acc[i].w = fmaf(wt, vv[i].w, acc[i].w * corr);
            }
            mmax = mnew;
        }
        float inv = 1.f / fmaxf(den, 1e-16f);
#pragma unroll
        for (int i = 0; i < R4; i++) {
            float4 o = make_float4(acc[i].x * inv, acc[i].y * inv, acc[i].z * inv, acc[i].w * inv);
            *(float4*)(agg + abase + i * 128 + lane * 4) = o;
        }
    } else {
        float2 qv = *(const float2*)(q + qbase + lane * 2);
        float2 acc = make_float2(0.f, 0.f);
        for (int j = j0; j < j1; j++) {
            int e = perm[j];
            int s = src[e];
            const size_t sb = (size_t)s * ld + (size_t)h * CC;
            float2 kv = *(const float2*)(k + sb + lane * 2);
            float2 vv = *(const float2*)(v + sb + lane * 2);
            float dot = fmaf(qv.x, kv.x, qv.y * kv.y);
#pragma unroll
            for (int o = 16; o; o >>= 1) dot += __shfl_xor_sync(0xFFFFFFFFu, dot, o);
            float a = dot * scale;
            float mnew = fmaxf(mmax, a);
            float corr = __expf(mmax - mnew);
            float wt = __expf(a - mnew);
            den = den * corr + wt;
            acc.x = fmaf(wt, vv.x, acc.x * corr);
            acc.y = fmaf(wt, vv.y, acc.y * corr);
            mmax = mnew;
        }
        float inv = 1.f / fmaxf(den, 1e-16f);
        *(float2*)(agg + abase + lane * 2) = make_float2(acc.x * inv, acc.y * inv);
    }
}

// ---------------- combine: out = elu(mean_h(agg) + skip); optional fused fp16 convert ----------------
__global__ void combine_kernel(const float* __restrict__ agg, const float* __restrict__ skipB,
                               int lds, float* __restrict__ out, int C,
                               __half* __restrict__ Anext) {
    int i = blockIdx.x * blockDim.x + threadIdx.x;
    if (i >= NN * C) return;
    int n = i / C, c = i % C;
    const float* ap = agg + (size_t)n * HH * C + c;
    float s = 0.f;
#pragma unroll
    for (int h = 0; h < HH; h++) s += ap[(size_t)h * C];
    float val = s * (1.f / HH) + skipB[(size_t)n * lds + c];
    val = val > 0.f ? val : expm1f(val);
    out[i] = val;
    if (Anext) Anext[i] = __float2half_rn(val);
}

// ---------------- pooling ----------------
__global__ void gate_kernel(const float* __restrict__ h, const float* __restrict__ gw,
                            const float* __restrict__ gb, const int* __restrict__ batch,
                            float* __restrict__ gate, float* __restrict__ gm) {
    int n = (blockIdx.x * blockDim.x + threadIdx.x) >> 5;
    int lane = threadIdx.x & 31;
    if (n >= NN) return;
    float s = 0.f;
    for (int c = lane; c < 64; c += 32) s += h[(size_t)n * 64 + c] * gw[c];
#pragma unroll
    for (int o = 16; o; o >>= 1) s += __shfl_xor_sync(0xFFFFFFFFu, s, o);
    if (lane == 0) {
        s += gb[0];
        gate[n] = s;
        atomicMaxFloat(&gm[batch[n]], s);
    }
}
__global__ void gate_exp_kernel(const int* __restrict__ batch, float* __restrict__ gate,
                                const float* __restrict__ gm, float* __restrict__ gd) {
    int n = blockIdx.x * blockDim.x + threadIdx.x;
    if (n >= NN) return;
    int b = batch[n];
    float e = expf(gate[n] - gm[b]);
    gate[n] = e;
    atomicAdd(&gd[b], e);
}
__global__ void pool_kernel(const float* __restrict__ h, const int* __restrict__ batch,
                            const float* __restrict__ gate, const float* __restrict__ gd,
                            float* __restrict__ pool) {
    int i = blockIdx.x * blockDim.x + threadIdx.x;
    if (i >= NN * 64) return;
    int n = i / 64, c = i % 64;
    int b = batch[n];
    float w = gate[n] / fmaxf(gd[b], 1e-16f);
    atomicAdd(&pool[b * 64 + c], w * h[i]);
}
__global__ void fc_kernel(const float* __restrict__ pool, const float* __restrict__ fw,
                          const float* __restrict__ fb, float* __restrict__ out) {
    int i = blockIdx.x * blockDim.x + threadIdx.x;
    if (i >= NG * 10) return;
    int g = i / 10, o = i % 10;
    float s = fb[o];
#pragma unroll
    for (int c = 0; c < 64; c++) s += pool[g * 64 + c] * fw[c * 10 + o];
    out[i] = s;
}

// ---------------- host side ----------------
static inline void launch_fill(float* p, float v, size_t n) {
    fill_kernel<<<(unsigned)((n + 255) / 256), 256>>>(p, v, n);
}

struct Ptrs {
    float *qkvs, *agg, *hA, *hB, *gate, *gm, *gd, *pool, *biasp;
    __half *Ac, *Bc;
    int *deg, *rowptr, *cursor, *perm;
};

// A' (P.Ac) must already contain this layer's fp16 input
static void tconv_layer(int fin, int C, const float* const* W, const int* src,
                        float* hout, __half* Anext, const Ptrs& P) {
    int hc = C * HH;
    int Ntot = 3 * hc + C;
    dim3 tg((fin + 31) / 32, (hc + 31) / 32);
    convBT_kernel<<<tg, dim3(32, 8)>>>(W[0], P.Bc, fin, hc, 0);
    convBT_kernel<<<tg, dim3(32, 8)>>>(W[2], P.Bc, fin, hc, hc);
    convBT_kernel<<<tg, dim3(32, 8)>>>(W[4], P.Bc, fin, hc, 2 * hc);
    dim3 tg2((fin + 31) / 32, (C + 31) / 32);
    convBT_kernel<<<tg2, dim3(32, 8)>>>(W[6], P.Bc, fin, C, 3 * hc);
    pack_bias_kernel<<<(Ntot + 255) / 256, 256>>>(W[1], W[3], W[5], W[7], hc, C, P.biasp);

    dim3 grid((Ntot + BN - 1) / BN, (NN + BM - 1) / BM);
    gemm_mma_kernel<<<grid, 512, GEMM_SMEM>>>(P.Ac, P.Bc, P.biasp, P.qkvs, NN, fin, Ntot);

    const float* q = P.qkvs;
    const float* k = P.qkvs + hc;
    const float* v = P.qkvs + 2 * hc;
    const float* skip = P.qkvs + 3 * hc;
    float scale = 1.f / sqrtf((float)C);
    int blocks = (NN * HH * 32 + 255) / 256;
    if (C == 512)
        attn_kernel<512><<<blocks, 256>>>(q, k, v, Ntot, P.rowptr, P.perm, src, P.agg, scale);
    else if (C == 256)
        attn_kernel<256><<<blocks, 256>>>(q, k, v, Ntot, P.rowptr, P.perm, src, P.agg, scale);
    else
        attn_kernel<64><<<blocks, 256>>>(q, k, v, Ntot, P.rowptr, P.perm, src, P.agg, scale);
    combine_kernel<<<(NN * C + 255) / 256, 256>>>(P.agg, skip, Ntot, hout, C, Anext);
}

extern "C" void kernel_launch(void* const* d_in, const int* in_sizes, int n_in,
                              void* d_out, int out_size) {
    const float* x     = (const float*)d_in[0];
    const int*   ei    = (const int*)d_in[1];
    const int*   batch = (const int*)d_in[2];
    const float* W[24];
    for (int i = 0; i < 24; i++) W[i] = (const float*)d_in[3 + i];
    const float* gate_w = (const float*)d_in[27];
    const float* gate_b = (const float*)d_in[28];
    const float* fc_w   = (const float*)d_in[29];
    const float* fc_b   = (const float*)d_in[30];
    float* out = (float*)d_out;

    const int* src = ei;
    const int* dst = ei + NE;

    cudaFuncSetAttribute(gemm_mma_kernel, cudaFuncAttributeMaxDynamicSharedMemorySize, GEMM_SMEM);

    Ptrs P;
    cudaGetSymbolAddress((void**)&P.qkvs, g_qkvs);
    cudaGetSymbolAddress((void**)&P.agg, g_agg);
    cudaGetSymbolAddress((void**)&P.hA, g_hA);
    cudaGetSymbolAddress((void**)&P.hB, g_hB);
    cudaGetSymbolAddress((void**)&P.gate, g_gate);
    cudaGetSymbolAddress((void**)&P.gm, g_gm);
    cudaGetSymbolAddress((void**)&P.gd, g_gd);
    cudaGetSymbolAddress((void**)&P.pool, g_pool);
    cudaGetSymbolAddress((void**)&P.biasp, g_biasp);
    cudaGetSymbolAddress((void**)&P.Ac, g_Acomp);
    cudaGetSymbolAddress((void**)&P.Bc, g_Bcomp);
    cudaGetSymbolAddress((void**)&P.deg, g_deg);
    cudaGetSymbolAddress((void**)&P.rowptr, g_rowptr);
    cudaGetSymbolAddress((void**)&P.cursor, g_cursor);
    cudaGetSymbolAddress((void**)&P.perm, g_perm);

    // CSR build
    fill_int_kernel<<<(NN + 255) / 256, 256>>>(P.deg, 0, NN);
    hist_kernel<<<(NE + 255) / 256, 256>>>(dst, P.deg);
    csr_scan_kernel<<<1, 1024>>>(P.deg, P.rowptr, P.cursor);
    scatter_kernel<<<(NE + 255) / 256, 256>>>(dst, P.cursor, P.perm);

    // Layer 1 A' from x
    size_t na = (size_t)NN * 128;
    convA_kernel<<<(unsigned)((na + 255) / 256), 256>>>(x, P.Ac, na);
    tconv_layer(128, 512, &W[0],  src, P.hA, P.Ac, P);  // combine writes next A' (C=512)
    tconv_layer(512, 256, &W[8],  src, P.hB, P.Ac, P);  // combine writes next A' (C=256)
    tconv_layer(256, 64,  &W[16], src, P.hA, nullptr, P);

    // Global attention pooling on hA [NN, 64]
    launch_fill(P.gm, -INFINITY, NG);
    launch_fill(P.gd, 0.f, NG);
    launch_fill(P.pool, 0.f, (size_t)NG * 64);
    gate_kernel<<<(NN * 32 + 255) / 256, 256>>>(P.hA, gate_w, gate_b, batch, P.gate, P.gm);
    gate_exp_kernel<<<(NN + 255) / 256, 256>>>(batch, P.gate, P.gm, P.gd);
    pool_kernel<<<(NN * 64 + 255) / 256, 256>>>(P.hA, batch, P.gate, P.gd, P.pool);
    fc_kernel<<<(NG * 10 + 255) / 256, 256>>>(P.pool, fc_w, fc_b, out);
}

// round 7
// speedup vs baseline: 5.2710x; 1.0847x over previous
#include <cuda_runtime.h>
#include <cuda_fp16.h>
#include <math.h>
#include <stdint.h>

#define NN 10000
#define NE 30000
#define NG 50
#define HH 8
#define MAXHC 4096
#define NTOT1 12800  // 3*4096+512

// ---------------- scratch (device globals) ----------------
__device__ __half g_qkvs[NN * NTOT1];         // merged [q|k|v|skip] output (fp16)
__device__ float g_agg[NN * MAXHC];
__device__ float g_hA[NN * 512];
__device__ float g_hB[NN * 512];
__device__ float g_gate[NN];
__device__ float g_gm[NG];
__device__ float g_gd[NG];
__device__ float g_pool[NG * 64];
__device__ float g_biasp[NTOT1];
// fp16 operands: A' (M x K), B' = W^T (Ntot x K)
__device__ __half g_Acomp[NN * 512];
__device__ __half g_Bcomp[6400 * 512];
// CSR
__device__ int g_deg[NN];
__device__ int g_rowptr[NN + 1];
__device__ int g_cursor[NN];
__device__ int g_perm[NE];

// ---------------- helpers ----------------
__device__ __forceinline__ uint32_t smem_u32(const void* p) {
    uint32_t a;
    asm("{ .reg .u64 t; cvta.to.shared.u64 t, %1; cvt.u32.u64 %0, t; }" : "=r"(a) : "l"(p));
    return a;
}
__device__ __forceinline__ void cp16(uint32_t saddr, const void* g, bool pred) {
    int sz = pred ? 16 : 0;
    asm volatile("cp.async.cg.shared.global [%0], [%1], 16, %2;" :: "r"(saddr), "l"(g), "r"(sz));
}
__device__ __forceinline__ void cp_commit() { asm volatile("cp.async.commit_group;"); }
__device__ __forceinline__ void cp_wait0() { asm volatile("cp.async.wait_group 0;"); }
__device__ __forceinline__ void cp_wait1() { asm volatile("cp.async.wait_group 1;"); }
__device__ __forceinline__ void ldmx4(uint32_t* r, uint32_t addr) {
    asm volatile("ldmatrix.sync.aligned.m8n8.x4.shared.b16 {%0,%1,%2,%3}, [%4];"
                 : "=r"(r[0]), "=r"(r[1]), "=r"(r[2]), "=r"(r[3]) : "r"(addr));
}
__device__ __forceinline__ void mma_fp16(float* c, const uint32_t* a, uint32_t b0, uint32_t b1) {
    asm volatile(
        "mma.sync.aligned.m16n8k16.row.col.f32.f16.f16.f32 "
        "{%0,%1,%2,%3}, {%4,%5,%6,%7}, {%8,%9}, {%0,%1,%2,%3};"
        : "+f"(c[0]), "+f"(c[1]), "+f"(c[2]), "+f"(c[3])
        : "r"(a[0]), "r"(a[1]), "r"(a[2]), "r"(a[3]), "r"(b0), "r"(b1));
}
__device__ __forceinline__ void h8_to_f8(uint4 t, float* f) {
    const __half2* hp = (const __half2*)&t;
#pragma unroll
    for (int j = 0; j < 4; j++) {
        float2 xy = __half22float2(hp[j]);
        f[2 * j] = xy.x;
        f[2 * j + 1] = xy.y;
    }
}

// ---------------- utility kernels ----------------
__global__ void fill_kernel(float* p, float v, size_t n) {
    size_t i = (size_t)blockIdx.x * blockDim.x + threadIdx.x;
    if (i < n) p[i] = v;
}
__global__ void fill_int_kernel(int* p, int v, int n) {
    int i = blockIdx.x * blockDim.x + threadIdx.x;
    if (i < n) p[i] = v;
}
__device__ __forceinline__ void atomicMaxFloat(float* addr, float v) {
    int* ai = (int*)addr;
    int old = *ai;
    while (__int_as_float(old) < v) {
        int assumed = old;
        old = atomicCAS(ai, assumed, __float_as_int(v));
        if (old == assumed) break;
    }
}

// ---------------- fp32 -> fp16 convert ----------------
__global__ void convA_kernel(const float* __restrict__ A, __half* __restrict__ out, size_t n) {
    size_t i = (size_t)blockIdx.x * blockDim.x + threadIdx.x;
    if (i >= n) return;
    out[i] = __float2half_rn(A[i]);
}

// W [K,N] fp32 -> B' rows [rowOff, rowOff+N) of [Ntot, K] fp16
__global__ void convBT_kernel(const float* __restrict__ W, __half* __restrict__ out,
                              int K, int N, int rowOff) {
    __shared__ float t[32][33];
    int kb = blockIdx.x * 32, nb = blockIdx.y * 32;
    int tx = threadIdx.x, ty = threadIdx.y;  // 32 x 8
    for (int r = ty; r < 32; r += 8) {
        int kk = kb + r, nn2 = nb + tx;
        t[r][tx] = (kk < K && nn2 < N) ? W[(size_t)kk * N + nn2] : 0.f;
    }
    __syncthreads();
    for (int r = ty; r < 32; r += 8) {
        int nn2 = nb + r, kk = kb + tx;
        if (nn2 < N && kk < K)
            out[(size_t)(rowOff + nn2) * K + kk] = __float2half_rn(t[tx][r]);
    }
}

__global__ void pack_bias_kernel(const float* __restrict__ qb, const float* __restrict__ kb,
                                 const float* __restrict__ vb, const float* __restrict__ sb,
                                 int hc, int C, float* __restrict__ out) {
    int i = blockIdx.x * blockDim.x + threadIdx.x;
    int Ntot = 3 * hc + C;
    if (i >= Ntot) return;
    float v;
    if (i < hc) v = qb[i];
    else if (i < 2 * hc) v = kb[i - hc];
    else if (i < 3 * hc) v = vb[i - 2 * hc];
    else v = sb[i - 3 * hc];
    out[i] = v;
}

// ---------------- fp16 mma.sync GEMM: C[M,N] (fp16) = A[M,K] @ B[N,K]^T + bias ----------------
#define BM 128
#define BN 256
#define LDT 40
#define SA_BYTES (BM * LDT * 2)
#define SB_BYTES (BN * LDT * 2)
#define GEMM_SMEM (3 * (SA_BYTES + SB_BYTES))

__global__ void __launch_bounds__(512)
gemm_mma_kernel(const __half* __restrict__ A, const __half* __restrict__ B,
                const float* __restrict__ bias, __half* __restrict__ C,
                int M, int K, int N) {
    extern __shared__ char smraw[];
    uint32_t aBase = smem_u32(smraw);
    uint32_t bBase = aBase + 3 * SA_BYTES;
    int tid = threadIdx.x;
    int lane = tid & 31, wid = tid >> 5;
    int m0 = blockIdx.y * BM, n0 = blockIdx.x * BN;
    int warp_m = wid >> 2, warp_n = wid & 3;  // 4 x 4
    int m_base = warp_m * 32, n_base = warp_n * 64;

    float acc[2][8][4];
#pragma unroll
    for (int i = 0; i < 2; i++)
#pragma unroll
        for (int j = 0; j < 8; j++)
#pragma unroll
            for (int r = 0; r < 4; r++) acc[i][j][r] = 0.f;

    int nk = K >> 5;

    auto load_stage = [&](int st, int kt) {
        {
            int row = tid >> 2, ch = tid & 3;
            int gr = m0 + row;
            uint32_t sa = aBase + st * SA_BYTES + (row * LDT + ch * 8) * 2;
            const __half* g = A + (size_t)(gr < M ? gr : 0) * K + kt * 32 + ch * 8;
            cp16(sa, g, gr < M);
        }
#pragma unroll
        for (int l = 0; l < 2; l++) {
            int idx = tid + l * 512;
            int row = idx >> 2, ch = idx & 3;
            int gn = n0 + row;
            uint32_t sb = bBase + st * SB_BYTES + (row * LDT + ch * 8) * 2;
            const __half* g = B + (size_t)(gn < N ? gn : 0) * K + kt * 32 + ch * 8;
            cp16(sb, g, gn < N);
        }
        cp_commit();
    };

    load_stage(0, 0);
    if (nk > 1) load_stage(1, 1);
    else cp_commit();

    int a_r = lane & 15;
    int a_c = (lane >> 4) * 8;
    int b_r = (lane & 7) + ((lane >> 4) << 3);
    int b_c = ((lane >> 3) & 1) * 8;

    for (int kt = 0; kt < nk; kt++) {
        int st = kt % 3;
        if (kt + 1 < nk) cp_wait1();
        else cp_wait0();
        __syncthreads();
        if (kt + 2 < nk) load_stage((kt + 2) % 3, kt + 2);
        uint32_t sa = aBase + st * SA_BYTES;
        uint32_t sb = bBase + st * SB_BYTES;
#pragma unroll
        for (int ks = 0; ks < 32; ks += 16) {
            uint32_t af[2][4];
#pragma unroll
            for (int im = 0; im < 2; im++)
                ldmx4(af[im], sa + ((m_base + im * 16 + a_r) * LDT + ks + a_c) * 2);
            uint32_t bf[4][4];
#pragma unroll
            for (int ib = 0; ib < 4; ib++)
                ldmx4(bf[ib], sb + ((n_base + ib * 16 + b_r) * LDT + ks + b_c) * 2);
#pragma unroll
            for (int im = 0; im < 2; im++)
#pragma unroll
                for (int jn = 0; jn < 8; jn++)
                    mma_fp16(acc[im][jn], af[im], bf[jn >> 1][(jn & 1) * 2], bf[jn >> 1][(jn & 1) * 2 + 1]);
        }
        __syncthreads();
    }

#pragma unroll
    for (int im = 0; im < 2; im++) {
        int row0 = m0 + m_base + im * 16 + (lane >> 2);
#pragma unroll
        for (int jn = 0; jn < 8; jn++) {
            int col = n0 + n_base + jn * 8 + (lane & 3) * 2;
            if (col < N) {
                float bx = bias[col], by = bias[col + 1];
                if (row0 < M) {
                    __half2 o = __floats2half2_rn(acc[im][jn][0] + bx, acc[im][jn][1] + by);
                    *(__half2*)&C[(size_t)row0 * N + col] = o;
                }
                if (row0 + 8 < M) {
                    __half2 o = __floats2half2_rn(acc[im][jn][2] + bx, acc[im][jn][3] + by);
                    *(__half2*)&C[(size_t)(row0 + 8) * N + col] = o;
                }
            }
        }
    }
}

// ---------------- CSR build ----------------
__global__ void hist_kernel(const int* __restrict__ dst, int* __restrict__ deg) {
    int e = blockIdx.x * blockDim.x + threadIdx.x;
    if (e < NE) atomicAdd(&deg[dst[e]], 1);
}
__global__ void csr_scan_kernel(const int* __restrict__ deg, int* __restrict__ rowptr,
                                int* __restrict__ cursor) {
    __shared__ int part[1024];
    int t = threadIdx.x;
    int base = t * 10;
    int local[10];
    int s = 0;
#pragma unroll
    for (int i = 0; i < 10; i++) {
        int idx = base + i;
        local[i] = (idx < NN) ? deg[idx] : 0;
        s += local[i];
    }
    part[t] = s;
    __syncthreads();
    for (int off = 1; off < 1024; off <<= 1) {
        int v = (t >= off) ? part[t - off] : 0;
        __syncthreads();
        part[t] += v;
        __syncthreads();
    }
    int run = (t > 0) ? part[t - 1] : 0;
#pragma unroll
    for (int i = 0; i < 10; i++) {
        int idx = base + i;
        if (idx < NN) {
            rowptr[idx] = run;
            cursor[idx] = run;
            run += local[i];
        }
    }
    if (t == 1023) rowptr[NN] = run;
}
__global__ void scatter_kernel(const int* __restrict__ dst, int* __restrict__ cursor,
                               int* __restrict__ perm) {
    int e = blockIdx.x * blockDim.x + threadIdx.x;
    if (e < NE) {
        int pos = atomicAdd(&cursor[dst[e]], 1);
        perm[pos] = e;
    }
}

// ---------------- fused attention (online softmax), warp per (node, head), fp16 inputs ----------------
template <int CC>
__global__ void attn_kernel(const __half* __restrict__ q, const __half* __restrict__ k,
                            const __half* __restrict__ v, int ld,
                            const int* __restrict__ rowptr, const int* __restrict__ perm,
                            const int* __restrict__ src, float* __restrict__ agg, float scale) {
    int w = (blockIdx.x * blockDim.x + threadIdx.x) >> 5;
    int lane = threadIdx.x & 31;
    if (w >= NN * HH) return;
    int n = w / HH, h = w % HH;
    const size_t qbase = (size_t)n * ld + (size_t)h * CC;
    const size_t abase = (size_t)n * (HH * CC) + (size_t)h * CC;
    int j0 = rowptr[n], j1 = rowptr[n + 1];
    float mmax = -INFINITY, den = 0.f;

    if constexpr (CC >= 256) {
        const int R = CC / 256;  // uint4 (8-half) iters per lane
        float qv[R][8], acc[R][8];
#pragma unroll
        for (int i = 0; i < R; i++) {
            uint4 t = *(const uint4*)(q + qbase + i * 256 + lane * 8);
            h8_to_f8(t, qv[i]);
#pragma unroll
            for (int j = 0; j < 8; j++) acc[i][j] = 0.f;
        }
        for (int j = j0; j < j1; j++) {
            int e = perm[j];
            int s = src[e];
            const size_t sb = (size_t)s * ld + (size_t)h * CC;
            float kf[R][8], vf[R][8];
#pragma unroll
            for (int i = 0; i < R; i++) {
                uint4 tk = *(const uint4*)(k + sb + i * 256 + lane * 8);
                uint4 tv = *(const uint4*)(v + sb + i * 256 + lane * 8);
                h8_to_f8(tk, kf[i]);
                h8_to_f8(tv, vf[i]);
            }
            float dot = 0.f;
#pragma unroll
            for (int i = 0; i < R; i++)
#pragma unroll
                for (int c = 0; c < 8; c++) dot = fmaf(qv[i][c], kf[i][c], dot);
#pragma unroll
            for (int o = 16; o; o >>= 1) dot += __shfl_xor_sync(0xFFFFFFFFu, dot, o);
            float a = dot * scale;
            float mnew = fmaxf(mmax, a);
            float corr = __expf(mmax - mnew);
            float wt = __expf(a - mnew);
            den = den * corr + wt;
#pragma unroll
            for (int i = 0; i < R; i++)
#pragma unroll
                for (int c = 0; c < 8; c++) acc[i][c] = fmaf(wt, vf[i][c], acc[i][c] * corr);
            mmax = mnew;
        }
        float inv = 1.f / fmaxf(den, 1e-16f);
#pragma unroll
        for (int i = 0; i < R; i++) {
            float4 o0 = make_float4(acc[i][0] * inv, acc[i][1] * inv, acc[i][2] * inv, acc[i][3] * inv);
            float4 o1 = make_float4(acc[i][4] * inv, acc[i][5] * inv, acc[i][6] * inv, acc[i][7] * inv);
            *(float4*)(agg + abase + i * 256 + lane * 8) = o0;
            *(float4*)(agg + abase + i * 256 + lane * 8 + 4) = o1;
        }
    } else {
        // CC == 64: half2 per lane
        float2 qv = __half22float2(*(const __half2*)(q + qbase + lane * 2));
        float2 acc = make_float2(0.f, 0.f);
        for (int j = j0; j < j1; j++) {
            int e = perm[j];
            int s = src[e];
            const size_t sb = (size_t)s * ld + (size_t)h * CC;
            float2 kv = __half22float2(*(const __half2*)(k + sb + lane * 2));
            float2 vv = __half22float2(*(const __half2*)(v + sb + lane * 2));
            float dot = fmaf(qv.x, kv.x, qv.y * kv.y);
#pragma unroll
            for (int o = 16; o; o >>= 1) dot += __shfl_xor_sync(0xFFFFFFFFu, dot, o);
            float a = dot * scale;
            float mnew = fmaxf(mmax, a);
            float corr = __expf(mmax - mnew);
            float wt = __expf(a - mnew);
            den = den * corr + wt;
            acc.x = fmaf(wt, vv.x, acc.x * corr);
            acc.y = fmaf(wt, vv.y, acc.y * corr);
            mmax = mnew;
        }
        float inv = 1.f / fmaxf(den, 1e-16f);
        *(float2*)(agg + abase + lane * 2) = make_float2(acc.x * inv, acc.y * inv);
    }
}

// ---------------- combine: out = elu(mean_h(agg) + skip); optional fused fp16 convert ----------------
__global__ void combine_kernel(const float* __restrict__ agg, const __half* __restrict__ skipB,
                               int lds, float* __restrict__ out, int C,
                               __half* __restrict__ Anext) {
    int i = blockIdx.x * blockDim.x + threadIdx.x;
    if (i >= NN * C) return;
    int n = i / C, c = i % C;
    const float* ap = agg + (size_t)n * HH * C + c;
    float s = 0.f;
#pragma unroll
    for (int h = 0; h < HH; h++) s += ap[(size_t)h * C];
    float val = s * (1.f / HH) + __half2float(skipB[(size_t)n * lds + c]);
    val = val > 0.f ? val : expm1f(val);
    out[i] = val;
    if (Anext) Anext[i] = __float2half_rn(val);
}

// ---------------- pooling ----------------
__global__ void gate_kernel(const float* __restrict__ h, const float* __restrict__ gw,
                            const float* __restrict__ gb, const int* __restrict__ batch,
                            float* __restrict__ gate, float* __restrict__ gm) {
    int n = (blockIdx.x * blockDim.x + threadIdx.x) >> 5;
    int lane = threadIdx.x & 31;
    if (n >= NN) return;
    float s = 0.f;
    for (int c = lane; c < 64; c += 32) s += h[(size_t)n * 64 + c] * gw[c];
#pragma unroll
    for (int o = 16; o; o >>= 1) s += __shfl_xor_sync(0xFFFFFFFFu, s, o);
    if (lane == 0) {
        s += gb[0];
        gate[n] = s;
        atomicMaxFloat(&gm[batch[n]], s);
    }
}
__global__ void gate_exp_kernel(const int* __restrict__ batch, float* __restrict__ gate,
                                const float* __restrict__ gm, float* __restrict__ gd) {
    int n = blockIdx.x * blockDim.x + threadIdx.x;
    if (n >= NN) return;
    int b = batch[n];
    float e = expf(gate[n] - gm[b]);
    gate[n] = e;
    atomicAdd(&gd[b], e);
}
__global__ void pool_kernel(const float* __restrict__ h, const int* __restrict__ batch,
                            const float* __restrict__ gate, const float* __restrict__ gd,
                            float* __restrict__ pool) {
    int i = blockIdx.x * blockDim.x + threadIdx.x;
    if (i >= NN * 64) return;
    int n = i / 64, c = i % 64;
    int b = batch[n];
    float w = gate[n] / fmaxf(gd[b], 1e-16f);
    atomicAdd(&pool[b * 64 + c], w * h[i]);
}
__global__ void fc_kernel(const float* __restrict__ pool, const float* __restrict__ fw,
                          const float* __restrict__ fb, float* __restrict__ out) {
    int i = blockIdx.x * blockDim.x + threadIdx.x;
    if (i >= NG * 10) return;
    int g = i / 10, o = i % 10;
    float s = fb[o];
#pragma unroll
    for (int c = 0; c < 64; c++) s += pool[g * 64 + c] * fw[c * 10 + o];
    out[i] = s;
}

// ---------------- host side ----------------
static inline void launch_fill(float* p, float v, size_t n) {
    fill_kernel<<<(unsigned)((n + 255) / 256), 256>>>(p, v, n);
}

struct Ptrs {
    __half* qkvs;
    float *agg, *hA, *hB, *gate, *gm, *gd, *pool, *biasp;
    __half *Ac, *Bc;
    int *deg, *rowptr, *cursor, *perm;
};

static void tconv_layer(int fin, int C, const float* const* W, const int* src,
                        float* hout, __half* Anext, const Ptrs& P) {
    int hc = C * HH;
    int Ntot = 3 * hc + C;
    dim3 tg((fin + 31) / 32, (hc + 31) / 32);
    convBT_kernel<<<tg, dim3(32, 8)>>>(W[0], P.Bc, fin, hc, 0);
    convBT_kernel<<<tg, dim3(32, 8)>>>(W[2], P.Bc, fin, hc, hc);
    convBT_kernel<<<tg, dim3(32, 8)>>>(W[4], P.Bc, fin, hc, 2 * hc);
    dim3 tg2((fin + 31) / 32, (C + 31) / 32);
    convBT_kernel<<<tg2, dim3(32, 8)>>>(W[6], P.Bc, fin, C, 3 * hc);
    pack_bias_kernel<<<(Ntot + 255) / 256, 256>>>(W[1], W[3], W[5], W[7], hc, C, P.biasp);

    dim3 grid((Ntot + BN - 1) / BN, (NN + BM - 1) / BM);
    gemm_mma_kernel<<<grid, 512, GEMM_SMEM>>>(P.Ac, P.Bc, P.biasp, P.qkvs, NN, fin, Ntot);

    const __half* q = P.qkvs;
    const __half* k = P.qkvs + hc;
    const __half* v = P.qkvs + 2 * hc;
    const __half* skip = P.qkvs + 3 * hc;
    float scale = 1.f / sqrtf((float)C);
    int blocks = (NN * HH * 32 + 255) / 256;
    if (C == 512)
        attn_kernel<512><<<blocks, 256>>>(q, k, v, Ntot, P.rowptr, P.perm, src, P.agg, scale);
    else if (C == 256)
        attn_kernel<256><<<blocks, 256>>>(q, k, v, Ntot, P.rowptr, P.perm, src, P.agg, scale);
    else
        attn_kernel<64><<<blocks, 256>>>(q, k, v, Ntot, P.rowptr, P.perm, src, P.agg, scale);
    combine_kernel<<<(NN * C + 255) / 256, 256>>>(P.agg, skip, Ntot, hout, C, Anext);
}

extern "C" void kernel_launch(void* const* d_in, const int* in_sizes, int n_in,
                              void* d_out, int out_size) {
    const float* x     = (const float*)d_in[0];
    const int*   ei    = (const int*)d_in[1];
    const int*   batch = (const int*)d_in[2];
    const float* W[24];
    for (int i = 0; i < 24; i++) W[i] = (const float*)d_in[3 + i];
    const float* gate_w = (const float*)d_in[27];
    const float* gate_b = (const float*)d_in[28];
    const float* fc_w   = (const float*)d_in[29];
    const float* fc_b   = (const float*)d_in[30];
    float* out = (float*)d_out;

    const int* src = ei;
    const int* dst = ei + NE;

    cudaFuncSetAttribute(gemm_mma_kernel, cudaFuncAttributeMaxDynamicSharedMemorySize, GEMM_SMEM);

    Ptrs P;
    cudaGetSymbolAddress((void**)&P.qkvs, g_qkvs);
    cudaGetSymbolAddress((void**)&P.agg, g_agg);
    cudaGetSymbolAddress((void**)&P.hA, g_hA);
    cudaGetSymbolAddress((void**)&P.hB, g_hB);
    cudaGetSymbolAddress((void**)&P.gate, g_gate);
    cudaGetSymbolAddress((void**)&P.gm, g_gm);
    cudaGetSymbolAddress((void**)&P.gd, g_gd);
    cudaGetSymbolAddress((void**)&P.pool, g_pool);
    cudaGetSymbolAddress((void**)&P.biasp, g_biasp);
    cudaGetSymbolAddress((void**)&P.Ac, g_Acomp);
    cudaGetSymbolAddress((void**)&P.Bc, g_Bcomp);
    cudaGetSymbolAddress((void**)&P.deg, g_deg);
    cudaGetSymbolAddress((void**)&P.rowptr, g_rowptr);
    cudaGetSymbolAddress((void**)&P.cursor, g_cursor);
    cudaGetSymbolAddress((void**)&P.perm, g_perm);

    // CSR build
    fill_int_kernel<<<(NN + 255) / 256, 256>>>(P.deg, 0, NN);
    hist_kernel<<<(NE + 255) / 256, 256>>>(dst, P.deg);
    csr_scan_kernel<<<1, 1024>>>(P.deg, P.rowptr, P.cursor);
    scatter_kernel<<<(NE + 255) / 256, 256>>>(dst, P.cursor, P.perm);

    // Layer 1 A' from x
    size_t na = (size_t)NN * 128;
    convA_kernel<<<(unsigned)((na + 255) / 256), 256>>>(x, P.Ac, na);
    tconv_layer(128, 512, &W[0],  src, P.hA, P.Ac, P);
    tconv_layer(512, 256, &W[8],  src, P.hB, P.Ac, P);
    tconv_layer(256, 64,  &W[16], src, P.hA, nullptr, P);

    // Global attention pooling on hA [NN, 64]
    launch_fill(P.gm, -INFINITY, NG);
    launch_fill(P.gd, 0.f, NG);
    launch_fill(P.pool, 0.f, (size_t)NG * 64);
    gate_kernel<<<(NN * 32 + 255) / 256, 256>>>(P.hA, gate_w, gate_b, batch, P.gate, P.gm);
    gate_exp_kernel<<<(NN + 255) / 256, 256>>>(batch, P.gate, P.gm, P.gd);
    pool_kernel<<<(NN * 64 + 255) / 256, 256>>>(P.hA, batch, P.gate, P.gd, P.pool);
    fc_kernel<<<(NG * 10 + 255) / 256, 256>>>(P.pool, fc_w, fc_b, out);
}

// round 8
// speedup vs baseline: 5.6907x; 1.0796x over previous
#include <cuda_runtime.h>
#include <cuda_fp16.h>
#include <math.h>
#include <stdint.h>

#define NN 10000
#define NE 30000
#define NG 50
#define HH 8
#define NTOT1 12800  // 3*4096+512

// ---------------- scratch (device globals) ----------------
__device__ __half g_qkvs[NN * NTOT1];         // merged [q|k|v|skip] output (fp16)
__device__ float g_hA[NN * 512];
__device__ float g_gate[NN];
__device__ float g_gm[NG];
__device__ float g_gd[NG];
__device__ float g_pool[NG * 64];
__device__ float g_biasp[NTOT1];
__device__ __half g_Acomp[NN * 512];
__device__ __half g_Bcomp[6400 * 512];
// CSR
__device__ int g_deg[NN];
__device__ int g_rowptr[NN + 1];
__device__ int g_cursor[NN];
__device__ int g_perm[NE];

// ---------------- helpers ----------------
__device__ __forceinline__ uint32_t smem_u32(const void* p) {
    uint32_t a;
    asm("{ .reg .u64 t; cvta.to.shared.u64 t, %1; cvt.u32.u64 %0, t; }" : "=r"(a) : "l"(p));
    return a;
}
__device__ __forceinline__ void cp16(uint32_t saddr, const void* g, bool pred) {
    int sz = pred ? 16 : 0;
    asm volatile("cp.async.cg.shared.global [%0], [%1], 16, %2;" :: "r"(saddr), "l"(g), "r"(sz));
}
__device__ __forceinline__ void cp_commit() { asm volatile("cp.async.commit_group;"); }
__device__ __forceinline__ void cp_wait0() { asm volatile("cp.async.wait_group 0;"); }
__device__ __forceinline__ void cp_wait1() { asm volatile("cp.async.wait_group 1;"); }
__device__ __forceinline__ void ldmx4(uint32_t* r, uint32_t addr) {
    asm volatile("ldmatrix.sync.aligned.m8n8.x4.shared.b16 {%0,%1,%2,%3}, [%4];"
                 : "=r"(r[0]), "=r"(r[1]), "=r"(r[2]), "=r"(r[3]) : "r"(addr));
}
__device__ __forceinline__ void mma_fp16(float* c, const uint32_t* a, uint32_t b0, uint32_t b1) {
    asm volatile(
        "mma.sync.aligned.m16n8k16.row.col.f32.f16.f16.f32 "
        "{%0,%1,%2,%3}, {%4,%5,%6,%7}, {%8,%9}, {%0,%1,%2,%3};"
        : "+f"(c[0]), "+f"(c[1]), "+f"(c[2]), "+f"(c[3])
        : "r"(a[0]), "r"(a[1]), "r"(a[2]), "r"(a[3]), "r"(b0), "r"(b1));
}
__device__ __forceinline__ void h8_to_f8(uint4 t, float* f) {
    const __half2* hp = (const __half2*)&t;
#pragma unroll
    for (int j = 0; j < 4; j++) {
        float2 xy = __half22float2(hp[j]);
        f[2 * j] = xy.x;
        f[2 * j + 1] = xy.y;
    }
}

// ---------------- utility kernels ----------------
__global__ void fill_kernel(float* p, float v, size_t n) {
    size_t i = (size_t)blockIdx.x * blockDim.x + threadIdx.x;
    if (i < n) p[i] = v;
}
__global__ void fill_int_kernel(int* p, int v, int n) {
    int i = blockIdx.x * blockDim.x + threadIdx.x;
    if (i < n) p[i] = v;
}
__device__ __forceinline__ void atomicMaxFloat(float* addr, float v) {
    int* ai = (int*)addr;
    int old = *ai;
    while (__int_as_float(old) < v) {
        int assumed = old;
        old = atomicCAS(ai, assumed, __float_as_int(v));
        if (old == assumed) break;
    }
}

// ---------------- fp32 -> fp16 convert ----------------
__global__ void convA_kernel(const float* __restrict__ A, __half* __restrict__ out, size_t n) {
    size_t i = (size_t)blockIdx.x * blockDim.x + threadIdx.x;
    if (i >= n) return;
    out[i] = __float2half_rn(A[i]);
}

__global__ void convBT_kernel(const float* __restrict__ W, __half* __restrict__ out,
                              int K, int N, int rowOff) {
    __shared__ float t[32][33];
    int kb = blockIdx.x * 32, nb = blockIdx.y * 32;
    int tx = threadIdx.x, ty = threadIdx.y;  // 32 x 8
    for (int r = ty; r < 32; r += 8) {
        int kk = kb + r, nn2 = nb + tx;
        t[r][tx] = (kk < K && nn2 < N) ? W[(size_t)kk * N + nn2] : 0.f;
    }
    __syncthreads();
    for (int r = ty; r < 32; r += 8) {
        int nn2 = nb + r, kk = kb + tx;
        if (nn2 < N && kk < K)
            out[(size_t)(rowOff + nn2) * K + kk] = __float2half_rn(t[tx][r]);
    }
}

__global__ void pack_bias_kernel(const float* __restrict__ qb, const float* __restrict__ kb,
                                 const float* __restrict__ vb, const float* __restrict__ sb,
                                 int hc, int C, float* __restrict__ out) {
    int i = blockIdx.x * blockDim.x + threadIdx.x;
    int Ntot = 3 * hc + C;
    if (i >= Ntot) return;
    float v;
    if (i < hc) v = qb[i];
    else if (i < 2 * hc) v = kb[i - hc];
    else if (i < 3 * hc) v = vb[i - 2 * hc];
    else v = sb[i - 3 * hc];
    out[i] = v;
}

// ---------------- fp16 mma.sync GEMM ----------------
#define BM 128
#define BN 256
#define LDT 40
#define SA_BYTES (BM * LDT * 2)
#define SB_BYTES (BN * LDT * 2)
#define GEMM_SMEM (3 * (SA_BYTES + SB_BYTES))

__global__ void __launch_bounds__(512)
gemm_mma_kernel(const __half* __restrict__ A, const __half* __restrict__ B,
                const float* __restrict__ bias, __half* __restrict__ C,
                int M, int K, int N) {
    extern __shared__ char smraw[];
    uint32_t aBase = smem_u32(smraw);
    uint32_t bBase = aBase + 3 * SA_BYTES;
    int tid = threadIdx.x;
    int lane = tid & 31, wid = tid >> 5;
    int m0 = blockIdx.y * BM, n0 = blockIdx.x * BN;
    int warp_m = wid >> 2, warp_n = wid & 3;
    int m_base = warp_m * 32, n_base = warp_n * 64;

    float acc[2][8][4];
#pragma unroll
    for (int i = 0; i < 2; i++)
#pragma unroll
        for (int j = 0; j < 8; j++)
#pragma unroll
            for (int r = 0; r < 4; r++) acc[i][j][r] = 0.f;

    int nk = K >> 5;

    auto load_stage = [&](int st, int kt) {
        {
            int row = tid >> 2, ch = tid & 3;
            int gr = m0 + row;
            uint32_t sa = aBase + st * SA_BYTES + (row * LDT + ch * 8) * 2;
            const __half* g = A + (size_t)(gr < M ? gr : 0) * K + kt * 32 + ch * 8;
            cp16(sa, g, gr < M);
        }
#pragma unroll
        for (int l = 0; l < 2; l++) {
            int idx = tid + l * 512;
            int row = idx >> 2, ch = idx & 3;
            int gn = n0 + row;
            uint32_t sb = bBase + st * SB_BYTES + (row * LDT + ch * 8) * 2;
            const __half* g = B + (size_t)(gn < N ? gn : 0) * K + kt * 32 + ch * 8;
            cp16(sb, g, gn < N);
        }
        cp_commit();
    };

    load_stage(0, 0);
    if (nk > 1) load_stage(1, 1);
    else cp_commit();

    int a_r = lane & 15;
    int a_c = (lane >> 4) * 8;
    int b_r = (lane & 7) + ((lane >> 4) << 3);
    int b_c = ((lane >> 3) & 1) * 8;

    for (int kt = 0; kt < nk; kt++) {
        int st = kt % 3;
        if (kt + 1 < nk) cp_wait1();
        else cp_wait0();
        __syncthreads();
        if (kt + 2 < nk) load_stage((kt + 2) % 3, kt + 2);
        uint32_t sa = aBase + st * SA_BYTES;
        uint32_t sb = bBase + st * SB_BYTES;
#pragma unroll
        for (int ks = 0; ks < 32; ks += 16) {
            uint32_t af[2][4];
#pragma unroll
            for (int im = 0; im < 2; im++)
                ldmx4(af[im], sa + ((m_base + im * 16 + a_r) * LDT + ks + a_c) * 2);
            uint32_t bf[4][4];
#pragma unroll
            for (int ib = 0; ib < 4; ib++)
                ldmx4(bf[ib], sb + ((n_base + ib * 16 + b_r) * LDT + ks + b_c) * 2);
#pragma unroll
            for (int im = 0; im < 2; im++)
#pragma unroll
                for (int jn = 0; jn < 8; jn++)
                    mma_fp16(acc[im][jn], af[im], bf[jn >> 1][(jn & 1) * 2], bf[jn >> 1][(jn & 1) * 2 + 1]);
        }
        __syncthreads();
    }

#pragma unroll
    for (int im = 0; im < 2; im++) {
        int row0 = m0 + m_base + im * 16 + (lane >> 2);
#pragma unroll
        for (int jn = 0; jn < 8; jn++) {
            int col = n0 + n_base + jn * 8 + (lane & 3) * 2;
            if (col < N) {
                float bx = bias[col], by = bias[col + 1];
                if (row0 < M) {
                    __half2 o = __floats2half2_rn(acc[im][jn][0] + bx, acc[im][jn][1] + by);
                    *(__half2*)&C[(size_t)row0 * N + col] = o;
                }
                if (row0 + 8 < M) {
                    __half2 o = __floats2half2_rn(acc[im][jn][2] + bx, acc[im][jn][3] + by);
                    *(__half2*)&C[(size_t)(row0 + 8) * N + col] = o;
                }
            }
        }
    }
}

// ---------------- CSR build ----------------
__global__ void hist_kernel(const int* __restrict__ dst, int* __restrict__ deg) {
    int e = blockIdx.x * blockDim.x + threadIdx.x;
    if (e < NE) atomicAdd(&deg[dst[e]], 1);
}
__global__ void csr_scan_kernel(const int* __restrict__ deg, int* __restrict__ rowptr,
                                int* __restrict__ cursor) {
    __shared__ int part[1024];
    int t = threadIdx.x;
    int base = t * 10;
    int local[10];
    int s = 0;
#pragma unroll
    for (int i = 0; i < 10; i++) {
        int idx = base + i;
        local[i] = (idx < NN) ? deg[idx] : 0;
        s += local[i];
    }
    part[t] = s;
    __syncthreads();
    for (int off = 1; off < 1024; off <<= 1) {
        int v = (t >= off) ? part[t - off] : 0;
        __syncthreads();
        part[t] += v;
        __syncthreads();
    }
    int run = (t > 0) ? part[t - 1] : 0;
#pragma unroll
    for (int i = 0; i < 10; i++) {
        int idx = base + i;
        if (idx < NN) {
            rowptr[idx] = run;
            cursor[idx] = run;
            run += local[i];
        }
    }
    if (t == 1023) rowptr[NN] = run;
}
__global__ void scatter_kernel(const int* __restrict__ dst, int* __restrict__ cursor,
                               int* __restrict__ perm) {
    int e = blockIdx.x * blockDim.x + threadIdx.x;
    if (e < NE) {
        int pos = atomicAdd(&cursor[dst[e]], 1);
        perm[pos] = e;
    }
}

// ---------------- fused attention + head-mean + skip + ELU ----------------
// block per node (8 warps = 8 heads); smem = HH*CC floats
template <int CC>
__global__ void __launch_bounds__(256)
attn_combine_kernel(const __half* __restrict__ qkvs, int ld, int hc,
                    const int* __restrict__ rowptr, const int* __restrict__ perm,
                    const int* __restrict__ src,
                    float* __restrict__ hout, __half* __restrict__ Anext, float scale) {
    extern __shared__ float sred[];  // [HH][CC]
    int n = blockIdx.x;
    int tid = threadIdx.x;
    int h = tid >> 5, lane = tid & 31;
    const __half* q = qkvs;
    const __half* k = qkvs + hc;
    const __half* v = qkvs + 2 * hc;
    const size_t qbase = (size_t)n * ld + (size_t)h * CC;
    int j0 = rowptr[n], j1 = rowptr[n + 1];
    float mmax = -INFINITY, den = 0.f;

    if constexpr (CC >= 256) {
        const int R = CC / 256;
        float qv[R][8], acc[R][8];
#pragma unroll
        for (int i = 0; i < R; i++) {
            uint4 t = *(const uint4*)(q + qbase + i * 256 + lane * 8);
            h8_to_f8(t, qv[i]);
#pragma unroll
            for (int j = 0; j < 8; j++) acc[i][j] = 0.f;
        }
        for (int j = j0; j < j1; j++) {
            int s = src[perm[j]];
            const size_t sb = (size_t)s * ld + (size_t)h * CC;
            float kf[R][8], vf[R][8];
#pragma unroll
            for (int i = 0; i < R; i++) {
                uint4 tk = *(const uint4*)(k + sb + i * 256 + lane * 8);
                uint4 tv = *(const uint4*)(v + sb + i * 256 + lane * 8);
                h8_to_f8(tk, kf[i]);
                h8_to_f8(tv, vf[i]);
            }
            float dot = 0.f;
#pragma unroll
            for (int i = 0; i < R; i++)
#pragma unroll
                for (int c = 0; c < 8; c++) dot = fmaf(qv[i][c], kf[i][c], dot);
#pragma unroll
            for (int o = 16; o; o >>= 1) dot += __shfl_xor_sync(0xFFFFFFFFu, dot, o);
            float a = dot * scale;
            float mnew = fmaxf(mmax, a);
            float corr = __expf(mmax - mnew);
            float wt = __expf(a - mnew);
            den = den * corr + wt;
#pragma unroll
            for (int i = 0; i < R; i++)
#pragma unroll
                for (int c = 0; c < 8; c++) acc[i][c] = fmaf(wt, vf[i][c], acc[i][c] * corr);
            mmax = mnew;
        }
        float inv = 1.f / fmaxf(den, 1e-16f);
#pragma unroll
        for (int i = 0; i < R; i++) {
            float4 o0 = make_float4(acc[i][0] * inv, acc[i][1] * inv, acc[i][2] * inv, acc[i][3] * inv);
            float4 o1 = make_float4(acc[i][4] * inv, acc[i][5] * inv, acc[i][6] * inv, acc[i][7] * inv);
            *(float4*)(sred + h * CC + i * 256 + lane * 8) = o0;
            *(float4*)(sred + h * CC + i * 256 + lane * 8 + 4) = o1;
        }
    } else {
        // CC == 64
        float2 qv = __half22float2(*(const __half2*)(q + qbase + lane * 2));
        float2 acc = make_float2(0.f, 0.f);
        for (int j = j0; j < j1; j++) {
            int s = src[perm[j]];
            const size_t sb = (size_t)s * ld + (size_t)h * CC;
            float2 kv = __half22float2(*(const __half2*)(k + sb + lane * 2));
            float2 vv = __half22float2(*(const __half2*)(v + sb + lane * 2));
            float dot = fmaf(qv.x, kv.x, qv.y * kv.y);
#pragma unroll
            for (int o = 16; o; o >>= 1) dot += __shfl_xor_sync(0xFFFFFFFFu, dot, o);
            float a = dot * scale;
            float mnew = fmaxf(mmax, a);
            float corr = __expf(mmax - mnew);
            float wt = __expf(a - mnew);
            den = den * corr + wt;
            acc.x = fmaf(wt, vv.x, acc.x * corr);
            acc.y = fmaf(wt, vv.y, acc.y * corr);
            mmax = mnew;
        }
        float inv = 1.f / fmaxf(den, 1e-16f);
        *(float2*)(sred + h * CC + lane * 2) = make_float2(acc.x * inv, acc.y * inv);
    }
    __syncthreads();

    // head-mean + skip + ELU + output
    const __half* skipp = qkvs + 3 * hc;
    for (int c = tid; c < CC; c += 256) {
        float s = 0.f;
#pragma unroll
        for (int h2 = 0; h2 < HH; h2++) s += sred[h2 * CC + c];
        float val = s * (1.f / HH) + __half2float(skipp[(size_t)n * ld + c]);
        val = val > 0.f ? val : expm1f(val);
        if (hout) hout[(size_t)n * CC + c] = val;
        if (Anext) Anext[(size_t)n * CC + c] = __float2half_rn(val);
    }
}

// ---------------- pooling ----------------
__global__ void gate_kernel(const float* __restrict__ h, const float* __restrict__ gw,
                            const float* __restrict__ gb, const int* __restrict__ batch,
                            float* __restrict__ gate, float* __restrict__ gm) {
    int n = (blockIdx.x * blockDim.x + threadIdx.x) >> 5;
    int lane = threadIdx.x & 31;
    if (n >= NN) return;
    float s = 0.f;
    for (int c = lane; c < 64; c += 32) s += h[(size_t)n * 64 + c] * gw[c];
#pragma unroll
    for (int o = 16; o; o >>= 1) s += __shfl_xor_sync(0xFFFFFFFFu, s, o);
    if (lane == 0) {
        s += gb[0];
        gate[n] = s;
        atomicMaxFloat(&gm[batch[n]], s);
    }
}
__global__ void gate_exp_kernel(const int* __restrict__ batch, float* __restrict__ gate,
                                const float* __restrict__ gm, float* __restrict__ gd) {
    int n = blockIdx.x * blockDim.x + threadIdx.x;
    if (n >= NN) return;
    int b = batch[n];
    float e = expf(gate[n] - gm[b]);
    gate[n] = e;
    atomicAdd(&gd[b], e);
}
__global__ void pool_kernel(const float* __restrict__ h, const int* __restrict__ batch,
                            const float* __restrict__ gate, const float* __restrict__ gd,
                            float* __restrict__ pool) {
    int i = blockIdx.x * blockDim.x + threadIdx.x;
    if (i >= NN * 64) return;
    int n = i / 64, c = i % 64;
    int b = batch[n];
    float w = gate[n] / fmaxf(gd[b], 1e-16f);
    atomicAdd(&pool[b * 64 + c], w * h[i]);
}
__global__ void fc_kernel(const float* __restrict__ pool, const float* __restrict__ fw,
                          const float* __restrict__ fb, float* __restrict__ out) {
    int i = blockIdx.x * blockDim.x + threadIdx.x;
    if (i >= NG * 10) return;
    int g = i / 10, o = i % 10;
    float s = fb[o];
#pragma unroll
    for (int c = 0; c < 64; c++) s += pool[g * 64 + c] * fw[c * 10 + o];
    out[i] = s;
}

// ---------------- host side ----------------
static inline void launch_fill(float* p, float v, size_t n) {
    fill_kernel<<<(unsigned)((n + 255) / 256), 256>>>(p, v, n);
}

struct Ptrs {
    __half* qkvs;
    float *hA, *gate, *gm, *gd, *pool, *biasp;
    __half *Ac, *Bc;
    int *deg, *rowptr, *cursor, *perm;
};

static void tconv_layer(int fin, int C, const float* const* W, const int* src,
                        float* hout, __half* Anext, const Ptrs& P) {
    int hc = C * HH;
    int Ntot = 3 * hc + C;
    dim3 tg((fin + 31) / 32, (hc + 31) / 32);
    convBT_kernel<<<tg, dim3(32, 8)>>>(W[0], P.Bc, fin, hc, 0);
    convBT_kernel<<<tg, dim3(32, 8)>>>(W[2], P.Bc, fin, hc, hc);
    convBT_kernel<<<tg, dim3(32, 8)>>>(W[4], P.Bc, fin, hc, 2 * hc);
    dim3 tg2((fin + 31) / 32, (C + 31) / 32);
    convBT_kernel<<<tg2, dim3(32, 8)>>>(W[6], P.Bc, fin, C, 3 * hc);
    pack_bias_kernel<<<(Ntot + 255) / 256, 256>>>(W[1], W[3], W[5], W[7], hc, C, P.biasp);

    dim3 grid((Ntot + BN - 1) / BN, (NN + BM - 1) / BM);
    gemm_mma_kernel<<<grid, 512, GEMM_SMEM>>>(P.Ac, P.Bc, P.biasp, P.qkvs, NN, fin, Ntot);

    float scale = 1.f / sqrtf((float)C);
    int smem = HH * C * sizeof(float);
    if (C == 512)
        attn_combine_kernel<512><<<NN, 256, smem>>>(P.qkvs, Ntot, hc, P.rowptr, P.perm, src, hout, Anext, scale);
    else if (C == 256)
        attn_combine_kernel<256><<<NN, 256, smem>>>(P.qkvs, Ntot, hc, P.rowptr, P.perm, src, hout, Anext, scale);
    else
        attn_combine_kernel<64><<<NN, 256, smem>>>(P.qkvs, Ntot, hc, P.rowptr, P.perm, src, hout, Anext, scale);
}

extern "C" void kernel_launch(void* const* d_in, const int* in_sizes, int n_in,
                              void* d_out, int out_size) {
    const float* x     = (const float*)d_in[0];
    const int*   ei    = (const int*)d_in[1];
    const int*   batch = (const int*)d_in[2];
    const float* W[24];
    for (int i = 0; i < 24; i++) W[i] = (const float*)d_in[3 + i];
    const float* gate_w = (const float*)d_in[27];
    const float* gate_b = (const float*)d_in[28];
    const float* fc_w   = (const float*)d_in[29];
    const float* fc_b   = (const float*)d_in[30];
    float* out = (float*)d_out;

    const int* src = ei;
    const int* dst = ei + NE;

    cudaFuncSetAttribute(gemm_mma_kernel, cudaFuncAttributeMaxDynamicSharedMemorySize, GEMM_SMEM);

    Ptrs P;
    cudaGetSymbolAddress((void**)&P.qkvs, g_qkvs);
    cudaGetSymbolAddress((void**)&P.hA, g_hA);
    cudaGetSymbolAddress((void**)&P.gate, g_gate);
    cudaGetSymbolAddress((void**)&P.gm, g_gm);
    cudaGetSymbolAddress((void**)&P.gd, g_gd);
    cudaGetSymbolAddress((void**)&P.pool, g_pool);
    cudaGetSymbolAddress((void**)&P.biasp, g_biasp);
    cudaGetSymbolAddress((void**)&P.Ac, g_Acomp);
    cudaGetSymbolAddress((void**)&P.Bc, g_Bcomp);
    cudaGetSymbolAddress((void**)&P.deg, g_deg);
    cudaGetSymbolAddress((void**)&P.rowptr, g_rowptr);
    cudaGetSymbolAddress((void**)&P.cursor, g_cursor);
    cudaGetSymbolAddress((void**)&P.perm, g_perm);

    // CSR build
    fill_int_kernel<<<(NN + 255) / 256, 256>>>(P.deg, 0, NN);
    hist_kernel<<<(NE + 255) / 256, 256>>>(dst, P.deg);
    csr_scan_kernel<<<1, 1024>>>(P.deg, P.rowptr, P.cursor);
    scatter_kernel<<<(NE + 255) / 256, 256>>>(dst, P.cursor, P.perm);

    // Layer 1 A' from x
    size_t na = (size_t)NN * 128;
    convA_kernel<<<(unsigned)((na + 255) / 256), 256>>>(x, P.Ac, na);
    tconv_layer(128, 512, &W[0],  src, nullptr, P.Ac, P);
    tconv_layer(512, 256, &W[8],  src, nullptr, P.Ac, P);
    tconv_layer(256, 64,  &W[16], src, P.hA, nullptr, P);

    // Global attention pooling on hA [NN, 64]
    launch_fill(P.gm, -INFINITY, NG);
    launch_fill(P.gd, 0.f, NG);
    launch_fill(P.pool, 0.f, (size_t)NG * 64);
    gate_kernel<<<(NN * 32 + 255) / 256, 256>>>(P.hA, gate_w, gate_b, batch, P.gate, P.gm);
    gate_exp_kernel<<<(NN + 255) / 256, 256>>>(batch, P.gate, P.gm, P.gd);
    pool_kernel<<<(NN * 64 + 255) / 256, 256>>>(P.hA, batch, P.gate, P.gd, P.pool);
    fc_kernel<<<(NG * 10 + 255) / 256, 256>>>(P.pool, fc_w, fc_b, out);
}

// round 9
// speedup vs baseline: 5.9968x; 1.0538x over previous
#include <cuda_runtime.h>
#include <cuda_fp16.h>
#include <math.h>
#include <stdint.h>

#define NN 10000
#define NE 30000
#define NG 50
#define HH 8
#define NTOT1 12800  // 3*4096+512

// ---------------- scratch (device globals) ----------------
__device__ __half g_qkvs[NN * NTOT1];
__device__ float g_hA[NN * 512];
__device__ float g_gate[NN];
__device__ float g_biasp[NTOT1];
__device__ __half g_Acomp[NN * 512];
__device__ __half g_Bcomp[6400 * 512];
__device__ int g_deg[NN];
__device__ int g_rowptr[NN + 1];
__device__ int g_cursor[NN];
__device__ int g_perm[NE];

// ---------------- helpers ----------------
__device__ __forceinline__ uint32_t smem_u32(const void* p) {
    uint32_t a;
    asm("{ .reg .u64 t; cvta.to.shared.u64 t, %1; cvt.u32.u64 %0, t; }" : "=r"(a) : "l"(p));
    return a;
}
__device__ __forceinline__ void cp16(uint32_t saddr, const void* g, bool pred) {
    int sz = pred ? 16 : 0;
    asm volatile("cp.async.cg.shared.global [%0], [%1], 16, %2;" :: "r"(saddr), "l"(g), "r"(sz));
}
__device__ __forceinline__ void cp_commit() { asm volatile("cp.async.commit_group;"); }
__device__ __forceinline__ void cp_wait0() { asm volatile("cp.async.wait_group 0;"); }
__device__ __forceinline__ void cp_wait1() { asm volatile("cp.async.wait_group 1;"); }
__device__ __forceinline__ void ldmx4(uint32_t* r, uint32_t addr) {
    asm volatile("ldmatrix.sync.aligned.m8n8.x4.shared.b16 {%0,%1,%2,%3}, [%4];"
                 : "=r"(r[0]), "=r"(r[1]), "=r"(r[2]), "=r"(r[3]) : "r"(addr));
}
__device__ __forceinline__ void mma_fp16(float* c, const uint32_t* a, uint32_t b0, uint32_t b1) {
    asm volatile(
        "mma.sync.aligned.m16n8k16.row.col.f32.f16.f16.f32 "
        "{%0,%1,%2,%3}, {%4,%5,%6,%7}, {%8,%9}, {%0,%1,%2,%3};"
        : "+f"(c[0]), "+f"(c[1]), "+f"(c[2]), "+f"(c[3])
        : "r"(a[0]), "r"(a[1]), "r"(a[2]), "r"(a[3]), "r"(b0), "r"(b1));
}
__device__ __forceinline__ void h8_to_f8(uint4 t, float* f) {
    const __half2* hp = (const __half2*)&t;
#pragma unroll
    for (int j = 0; j < 4; j++) {
        float2 xy = __half22float2(hp[j]);
        f[2 * j] = xy.x;
        f[2 * j + 1] = xy.y;
    }
}
__device__ __forceinline__ int lbound(const int* a, int n, int key) {
    int lo = 0, hi = n;
    while (lo < hi) {
        int mid = (lo + hi) >> 1;
        if (a[mid] < key) lo = mid + 1;
        else hi = mid;
    }
    return lo;
}

// ---------------- utility kernels ----------------
__global__ void fill_int_kernel(int* p, int v, int n) {
    int i = blockIdx.x * blockDim.x + threadIdx.x;
    if (i < n) p[i] = v;
}

// ---------------- fp32 -> fp16 convert ----------------
__global__ void convA_kernel(const float* __restrict__ A, __half* __restrict__ out, size_t n) {
    size_t i = (size_t)blockIdx.x * blockDim.x + threadIdx.x;
    if (i >= n) return;
    out[i] = __float2half_rn(A[i]);
}

// merged: 4 weight matrices [K,N_z] -> B' rows, z = blockIdx.z
__global__ void convBT4_kernel(const float* __restrict__ qw, const float* __restrict__ kw,
                               const float* __restrict__ vw, const float* __restrict__ sw,
                               __half* __restrict__ out, int K, int hc, int C) {
    int z = blockIdx.z;
    const float* W = (z == 0) ? qw : (z == 1) ? kw : (z == 2) ? vw : sw;
    int N = (z < 3) ? hc : C;
    int rowOff = z * hc;
    __shared__ float t[32][33];
    int kb = blockIdx.x * 32, nb = blockIdx.y * 32;
    if (nb >= N) return;
    int tx = threadIdx.x, ty = threadIdx.y;  // 32 x 8
    for (int r = ty; r < 32; r += 8) {
        int kk = kb + r, nn2 = nb + tx;
        t[r][tx] = (kk < K && nn2 < N) ? W[(size_t)kk * N + nn2] : 0.f;
    }
    __syncthreads();
    for (int r = ty; r < 32; r += 8) {
        int nn2 = nb + r, kk = kb + tx;
        if (nn2 < N && kk < K)
            out[(size_t)(rowOff + nn2) * K + kk] = __float2half_rn(t[tx][r]);
    }
}

__global__ void pack_bias_kernel(const float* __restrict__ qb, const float* __restrict__ kb,
                                 const float* __restrict__ vb, const float* __restrict__ sb,
                                 int hc, int C, float* __restrict__ out) {
    int i = blockIdx.x * blockDim.x + threadIdx.x;
    int Ntot = 3 * hc + C;
    if (i >= Ntot) return;
    float v;
    if (i < hc) v = qb[i];
    else if (i < 2 * hc) v = kb[i - hc];
    else if (i < 3 * hc) v = vb[i - 2 * hc];
    else v = sb[i - 3 * hc];
    out[i] = v;
}

// ---------------- fp16 mma.sync GEMM ----------------
#define BM 128
#define BN 256
#define LDT 40
#define SA_BYTES (BM * LDT * 2)
#define SB_BYTES (BN * LDT * 2)
#define GEMM_SMEM (3 * (SA_BYTES + SB_BYTES))

__global__ void __launch_bounds__(512)
gemm_mma_kernel(const __half* __restrict__ A, const __half* __restrict__ B,
                const float* __restrict__ bias, __half* __restrict__ C,
                int M, int K, int N) {
    extern __shared__ char smraw[];
    uint32_t aBase = smem_u32(smraw);
    uint32_t bBase = aBase + 3 * SA_BYTES;
    int tid = threadIdx.x;
    int lane = tid & 31, wid = tid >> 5;
    int m0 = blockIdx.y * BM, n0 = blockIdx.x * BN;
    int warp_m = wid >> 2, warp_n = wid & 3;
    int m_base = warp_m * 32, n_base = warp_n * 64;

    float acc[2][8][4];
#pragma unroll
    for (int i = 0; i < 2; i++)
#pragma unroll
        for (int j = 0; j < 8; j++)
#pragma unroll
            for (int r = 0; r < 4; r++) acc[i][j][r] = 0.f;

    int nk = K >> 5;

    auto load_stage = [&](int st, int kt) {
        {
            int row = tid >> 2, ch = tid & 3;
            int gr = m0 + row;
            uint32_t sa = aBase + st * SA_BYTES + (row * LDT + ch * 8) * 2;
            const __half* g = A + (size_t)(gr < M ? gr : 0) * K + kt * 32 + ch * 8;
            cp16(sa, g, gr < M);
        }
#pragma unroll
        for (int l = 0; l < 2; l++) {
            int idx = tid + l * 512;
            int row = idx >> 2, ch = idx & 3;
            int gn = n0 + row;
            uint32_t sb = bBase + st * SB_BYTES + (row * LDT + ch * 8) * 2;
            const __half* g = B + (size_t)(gn < N ? gn : 0) * K + kt * 32 + ch * 8;
            cp16(sb, g, gn < N);
        }
        cp_commit();
    };

    load_stage(0, 0);
    if (nk > 1) load_stage(1, 1);
    else cp_commit();

    int a_r = lane & 15;
    int a_c = (lane >> 4) * 8;
    int b_r = (lane & 7) + ((lane >> 4) << 3);
    int b_c = ((lane >> 3) & 1) * 8;

    for (int kt = 0; kt < nk; kt++) {
        int st = kt % 3;
        if (kt + 1 < nk) cp_wait1();
        else cp_wait0();
        __syncthreads();
        if (kt + 2 < nk) load_stage((kt + 2) % 3, kt + 2);
        uint32_t sa = aBase + st * SA_BYTES;
        uint32_t sb = bBase + st * SB_BYTES;
#pragma unroll
        for (int ks = 0; ks < 32; ks += 16) {
            uint32_t af[2][4];
#pragma unroll
            for (int im = 0; im < 2; im++)
                ldmx4(af[im], sa + ((m_base + im * 16 + a_r) * LDT + ks + a_c) * 2);
            uint32_t bf[4][4];
#pragma unroll
            for (int ib = 0; ib < 4; ib++)
                ldmx4(bf[ib], sb + ((n_base + ib * 16 + b_r) * LDT + ks + b_c) * 2);
#pragma unroll
            for (int im = 0; im < 2; im++)
#pragma unroll
                for (int jn = 0; jn < 8; jn++)
                    mma_fp16(acc[im][jn], af[im], bf[jn >> 1][(jn & 1) * 2], bf[jn >> 1][(jn & 1) * 2 + 1]);
        }
        __syncthreads();
    }

#pragma unroll
    for (int im = 0; im < 2; im++) {
        int row0 = m0 + m_base + im * 16 + (lane >> 2);
#pragma unroll
        for (int jn = 0; jn < 8; jn++) {
            int col = n0 + n_base + jn * 8 + (lane & 3) * 2;
            if (col < N) {
                float bx = bias[col], by = bias[col + 1];
                if (row0 < M) {
                    __half2 o = __floats2half2_rn(acc[im][jn][0] + bx, acc[im][jn][1] + by);
                    *(__half2*)&C[(size_t)row0 * N + col] = o;
                }
                if (row0 + 8 < M) {
                    __half2 o = __floats2half2_rn(acc[im][jn][2] + bx, acc[im][jn][3] + by);
                    *(__half2*)&C[(size_t)(row0 + 8) * N + col] = o;
                }
            }
        }
    }
}

// ---------------- CSR build ----------------
__global__ void hist_kernel(const int* __restrict__ dst, int* __restrict__ deg) {
    int e = blockIdx.x * blockDim.x + threadIdx.x;
    if (e < NE) atomicAdd(&deg[dst[e]], 1);
}
__global__ void csr_scan_kernel(const int* __restrict__ deg, int* __restrict__ rowptr,
                                int* __restrict__ cursor) {
    __shared__ int part[1024];
    int t = threadIdx.x;
    int base = t * 10;
    int local[10];
    int s = 0;
#pragma unroll
    for (int i = 0; i < 10; i++) {
        int idx = base + i;
        local[i] = (idx < NN) ? deg[idx] : 0;
        s += local[i];
    }
    part[t] = s;
    __syncthreads();
    for (int off = 1; off < 1024; off <<= 1) {
        int v = (t >= off) ? part[t - off] : 0;
        __syncthreads();
        part[t] += v;
        __syncthreads();
    }
    int run = (t > 0) ? part[t - 1] : 0;
#pragma unroll
    for (int i = 0; i < 10; i++) {
        int idx = base + i;
        if (idx < NN) {
            rowptr[idx] = run;
            cursor[idx] = run;
            run += local[i];
        }
    }
    if (t == 1023) rowptr[NN] = run;
}
__global__ void scatter_kernel(const int* __restrict__ dst, int* __restrict__ cursor,
                               int* __restrict__ perm) {
    int e = blockIdx.x * blockDim.x + threadIdx.x;
    if (e < NE) {
        int pos = atomicAdd(&cursor[dst[e]], 1);
        perm[pos] = e;
    }
}

// ---------------- fused attention + head-mean + skip + ELU (+ optional gate) ----------------
template <int CC>
__global__ void __launch_bounds__(256)
attn_combine_kernel(const __half* __restrict__ qkvs, int ld, int hc,
                    const int* __restrict__ rowptr, const int* __restrict__ perm,
                    const int* __restrict__ src,
                    float* __restrict__ hout, __half* __restrict__ Anext, float scale,
                    const float* __restrict__ gw, const float* __restrict__ gb,
                    float* __restrict__ gatep) {
    extern __shared__ float sred[];  // [HH][CC]
    int n = blockIdx.x;
    int tid = threadIdx.x;
    int h = tid >> 5, lane = tid & 31;
    const __half* q = qkvs;
    const __half* k = qkvs + hc;
    const __half* v = qkvs + 2 * hc;
    const size_t qbase = (size_t)n * ld + (size_t)h * CC;
    int j0 = rowptr[n], j1 = rowptr[n + 1];
    float mmax = -INFINITY, den = 0.f;

    if constexpr (CC >= 256) {
        const int R = CC / 256;
        float qv[R][8], acc[R][8];
#pragma unroll
        for (int i = 0; i < R; i++) {
            uint4 t = *(const uint4*)(q + qbase + i * 256 + lane * 8);
            h8_to_f8(t, qv[i]);
#pragma unroll
            for (int j = 0; j < 8; j++) acc[i][j] = 0.f;
        }
        for (int j = j0; j < j1; j++) {
            int s = src[perm[j]];
            const size_t sb = (size_t)s * ld + (size_t)h * CC;
            float kf[R][8], vf[R][8];
#pragma unroll
            for (int i = 0; i < R; i++) {
                uint4 tk = *(const uint4*)(k + sb + i * 256 + lane * 8);
                uint4 tv = *(const uint4*)(v + sb + i * 256 + lane * 8);
                h8_to_f8(tk, kf[i]);
                h8_to_f8(tv, vf[i]);
            }
            float dot = 0.f;
#pragma unroll
            for (int i = 0; i < R; i++)
#pragma unroll
                for (int c = 0; c < 8; c++) dot = fmaf(qv[i][c], kf[i][c], dot);
#pragma unroll
            for (int o = 16; o; o >>= 1) dot += __shfl_xor_sync(0xFFFFFFFFu, dot, o);
            float a = dot * scale;
            float mnew = fmaxf(mmax, a);
            float corr = __expf(mmax - mnew);
            float wt = __expf(a - mnew);
            den = den * corr + wt;
#pragma unroll
            for (int i = 0; i < R; i++)
#pragma unroll
                for (int c = 0; c < 8; c++) acc[i][c] = fmaf(wt, vf[i][c], acc[i][c] * corr);
            mmax = mnew;
        }
        float inv = 1.f / fmaxf(den, 1e-16f);
#pragma unroll
        for (int i = 0; i < R; i++) {
            float4 o0 = make_float4(acc[i][0] * inv, acc[i][1] * inv, acc[i][2] * inv, acc[i][3] * inv);
            float4 o1 = make_float4(acc[i][4] * inv, acc[i][5] * inv, acc[i][6] * inv, acc[i][7] * inv);
            *(float4*)(sred + h * CC + i * 256 + lane * 8) = o0;
            *(float4*)(sred + h * CC + i * 256 + lane * 8 + 4) = o1;
        }
    } else {
        float2 qv = __half22float2(*(const __half2*)(q + qbase + lane * 2));
        float2 acc = make_float2(0.f, 0.f);
        for (int j = j0; j < j1; j++) {
            int s = src[perm[j]];
            const size_t sb = (size_t)s * ld + (size_t)h * CC;
            float2 kv = __half22float2(*(const __half2*)(k + sb + lane * 2));
            float2 vv = __half22float2(*(const __half2*)(v + sb + lane * 2));
            float dot = fmaf(qv.x, kv.x, qv.y * kv.y);
#pragma unroll
            for (int o = 16; o; o >>= 1) dot += __shfl_xor_sync(0xFFFFFFFFu, dot, o);
            float a = dot * scale;
            float mnew = fmaxf(mmax, a);
            float corr = __expf(mmax - mnew);
            float wt = __expf(a - mnew);
            den = den * corr + wt;
            acc.x = fmaf(wt, vv.x, acc.x * corr);
            acc.y = fmaf(wt, vv.y, acc.y * corr);
            mmax = mnew;
        }
        float inv = 1.f / fmaxf(den, 1e-16f);
        *(float2*)(sred + h * CC + lane * 2) = make_float2(acc.x * inv, acc.y * inv);
    }
    __syncthreads();

    const __half* skipp = qkvs + 3 * hc;
    float gacc = 0.f;
    for (int c = tid; c < CC; c += 256) {
        float s = 0.f;
#pragma unroll
        for (int h2 = 0; h2 < HH; h2++) s += sred[h2 * CC + c];
        float val = s * (1.f / HH) + __half2float(skipp[(size_t)n * ld + c]);
        val = val > 0.f ? val : expm1f(val);
        if (hout) hout[(size_t)n * CC + c] = val;
        if (Anext) Anext[(size_t)n * CC + c] = __float2half_rn(val);
        if (gatep) gacc = fmaf(val, gw[c], gacc);
    }
    if (gatep) {
        __syncthreads();
        sred[tid] = gacc;
        __syncthreads();
        for (int off = 128; off; off >>= 1) {
            if (tid < off) sred[tid] += sred[tid + off];
            __syncthreads();
        }
        if (tid == 0) gatep[n] = sred[0] + gb[0];
    }
}

// ---------------- fused pooling: one block per graph ----------------
__global__ void __launch_bounds__(256)
pool_all_kernel(const float* __restrict__ h, const float* __restrict__ gate,
                const int* __restrict__ batch, const float* __restrict__ fw,
                const float* __restrict__ fb, float* __restrict__ out) {
    __shared__ float red[256];
    __shared__ float spool[4][64];
    __shared__ float pool[64];
    __shared__ float sm, sd;
    int g = blockIdx.x;
    int tid = threadIdx.x;
    int lo = lbound(batch, NN, g);
    int hi = lbound(batch, NN, g + 1);

    // max gate
    float m = -INFINITY;
    for (int n = lo + tid; n < hi; n += 256) m = fmaxf(m, gate[n]);
    red[tid] = m;
    __syncthreads();
    for (int off = 128; off; off >>= 1) {
        if (tid < off) red[tid] = fmaxf(red[tid], red[tid + off]);
        __syncthreads();
    }
    if (tid == 0) sm = red[0];
    __syncthreads();
    float mm = sm;

    // sum exp
    float s = 0.f;
    for (int n = lo + tid; n < hi; n += 256) s += expf(gate[n] - mm);
    red[tid] = s;
    __syncthreads();
    for (int off = 128; off; off >>= 1) {
        if (tid < off) red[tid] += red[tid + off];
        __syncthreads();
    }
    if (tid == 0) sd = fmaxf(red[0], 1e-16f);
    __syncthreads();
    float inv = 1.f / sd;

    // weighted pool: 4 groups x 64 channels
    int grp = tid >> 6, c = tid & 63;
    float acc = 0.f;
    for (int n = lo + grp; n < hi; n += 4) {
        float w = expf(gate[n] - mm) * inv;
        acc = fmaf(w, h[(size_t)n * 64 + c], acc);
    }
    spool[grp][c] = acc;
    __syncthreads();
    if (tid < 64) pool[tid] = spool[0][tid] + spool[1][tid] + spool[2][tid] + spool[3][tid];
    __syncthreads();

    // fc
    if (tid < 10) {
        float o = fb[tid];
#pragma unroll
        for (int cc = 0; cc < 64; cc++) o = fmaf(pool[cc], fw[cc * 10 + tid], o);
        out[g * 10 + tid] = o;
    }
}

// ---------------- host side ----------------
struct Ptrs {
    __half* qkvs;
    float *hA, *gate, *biasp;
    __half *Ac, *Bc;
    int *deg, *rowptr, *cursor, *perm;
};

static void layer_gemm(int fin, int C, const float* const* W, const Ptrs& P) {
    int hc = C * HH;
    int Ntot = 3 * hc + C;
    dim3 tg((fin + 31) / 32, (hc + 31) / 32, 4);
    convBT4_kernel<<<tg, dim3(32, 8)>>>(W[0], W[2], W[4], W[6], P.Bc, fin, hc, C);
    pack_bias_kernel<<<(Ntot + 255) / 256, 256>>>(W[1], W[3], W[5], W[7], hc, C, P.biasp);
    dim3 grid((Ntot + BN - 1) / BN, (NN + BM - 1) / BM);
    gemm_mma_kernel<<<grid, 512, GEMM_SMEM>>>(P.Ac, P.Bc, P.biasp, P.qkvs, NN, fin, Ntot);
}

static void layer_attn(int C, const int* src, float* hout, __half* Anext,
                       const float* gw, const float* gb, float* gatep, const Ptrs& P) {
    int hc = C * HH;
    int Ntot = 3 * hc + C;
    float scale = 1.f / sqrtf((float)C);
    int smem = HH * C * sizeof(float);
    if (C == 512)
        attn_combine_kernel<512><<<NN, 256, smem>>>(P.qkvs, Ntot, hc, P.rowptr, P.perm, src, hout, Anext, scale, gw, gb, gatep);
    else if (C == 256)
        attn_combine_kernel<256><<<NN, 256, smem>>>(P.qkvs, Ntot, hc, P.rowptr, P.perm, src, hout, Anext, scale, gw, gb, gatep);
    else
        attn_combine_kernel<64><<<NN, 256, smem>>>(P.qkvs, Ntot, hc, P.rowptr, P.perm, src, hout, Anext, scale, gw, gb, gatep);
}

extern "C" void kernel_launch(void* const* d_in, const int* in_sizes, int n_in,
                              void* d_out, int out_size) {
    const float* x     = (const float*)d_in[0];
    const int*   ei    = (const int*)d_in[1];
    const int*   batch = (const int*)d_in[2];
    const float* W[24];
    for (int i = 0; i < 24; i++) W[i] = (const float*)d_in[3 + i];
    const float* gate_w = (const float*)d_in[27];
    const float* gate_b = (const float*)d_in[28];
    const float* fc_w   = (const float*)d_in[29];
    const float* fc_b   = (const float*)d_in[30];
    float* out = (float*)d_out;

    const int* src = ei;
    const int* dst = ei + NE;

    cudaFuncSetAttribute(gemm_mma_kernel, cudaFuncAttributeMaxDynamicSharedMemorySize, GEMM_SMEM);

    Ptrs P;
    cudaGetSymbolAddress((void**)&P.qkvs, g_qkvs);
    cudaGetSymbolAddress((void**)&P.hA, g_hA);
    cudaGetSymbolAddress((void**)&P.gate, g_gate);
    cudaGetSymbolAddress((void**)&P.biasp, g_biasp);
    cudaGetSymbolAddress((void**)&P.Ac, g_Acomp);
    cudaGetSymbolAddress((void**)&P.Bc, g_Bcomp);
    cudaGetSymbolAddress((void**)&P.deg, g_deg);
    cudaGetSymbolAddress((void**)&P.rowptr, g_rowptr);
    cudaGetSymbolAddress((void**)&P.cursor, g_cursor);
    cudaGetSymbolAddress((void**)&P.perm, g_perm);

    // Layer-1 GEMM first (profiler lands here)
    size_t na = (size_t)NN * 128;
    convA_kernel<<<(unsigned)((na + 255) / 256), 256>>>(x, P.Ac, na);
    layer_gemm(128, 512, &W[0], P);

    // CSR build (overlaps nothing but only needed before attention)
    fill_int_kernel<<<(NN + 255) / 256, 256>>>(P.deg, 0, NN);
    hist_kernel<<<(NE + 255) / 256, 256>>>(dst, P.deg);
    csr_scan_kernel<<<1, 1024>>>(P.deg, P.rowptr, P.cursor);
    scatter_kernel<<<(NE + 255) / 256, 256>>>(dst, P.cursor, P.perm);

    layer_attn(512, src, nullptr, P.Ac, nullptr, nullptr, nullptr, P);

    layer_gemm(512, 256, &W[8], P);
    layer_attn(256, src, nullptr, P.Ac, nullptr, nullptr, nullptr, P);

    layer_gemm(256, 64, &W[16], P);
    layer_attn(64, src, P.hA, nullptr, gate_w, gate_b, P.gate, P);

    // fused pooling + fc
    pool_all_kernel<<<NG, 256>>>(P.hA, P.gate, batch, fc_w, fc_b, out);
}

// round 10
// speedup vs baseline: 6.4416x; 1.0742x over previous
#include <cuda_runtime.h>
#include <cuda_fp16.h>
#include <math.h>
#include <stdint.h>

#define NN 10000
#define NE 30000
#define NG 50
#define HH 8
#define NTOT1 12800  // 3*4096+512

// ---------------- scratch (device globals) ----------------
__device__ __half g_qkvs[NN * NTOT1];
__device__ float g_hA[NN * 512];
__device__ float g_gate[NN];
__device__ float g_biasp[NTOT1];
__device__ __half g_Acomp[NN * 512];
__device__ __half g_Bcomp[6400 * 512];
__device__ int g_deg[NN];
__device__ int g_rowptr[NN + 1];
__device__ int g_cursor[NN];
__device__ int g_perm[NE];

// ---------------- helpers ----------------
__device__ __forceinline__ uint32_t smem_u32(const void* p) {
    uint32_t a;
    asm("{ .reg .u64 t; cvta.to.shared.u64 t, %1; cvt.u32.u64 %0, t; }" : "=r"(a) : "l"(p));
    return a;
}
__device__ __forceinline__ void cp16(uint32_t saddr, const void* g, bool pred) {
    int sz = pred ? 16 : 0;
    asm volatile("cp.async.cg.shared.global [%0], [%1], 16, %2;" :: "r"(saddr), "l"(g), "r"(sz));
}
__device__ __forceinline__ void cp_commit() { asm volatile("cp.async.commit_group;"); }
__device__ __forceinline__ void cp_wait0() { asm volatile("cp.async.wait_group 0;"); }
__device__ __forceinline__ void cp_wait1() { asm volatile("cp.async.wait_group 1;"); }
__device__ __forceinline__ void ldmx4(uint32_t* r, uint32_t addr) {
    asm volatile("ldmatrix.sync.aligned.m8n8.x4.shared.b16 {%0,%1,%2,%3}, [%4];"
                 : "=r"(r[0]), "=r"(r[1]), "=r"(r[2]), "=r"(r[3]) : "r"(addr));
}
__device__ __forceinline__ void mma_fp16(float* c, const uint32_t* a, uint32_t b0, uint32_t b1) {
    asm volatile(
        "mma.sync.aligned.m16n8k16.row.col.f32.f16.f16.f32 "
        "{%0,%1,%2,%3}, {%4,%5,%6,%7}, {%8,%9}, {%0,%1,%2,%3};"
        : "+f"(c[0]), "+f"(c[1]), "+f"(c[2]), "+f"(c[3])
        : "r"(a[0]), "r"(a[1]), "r"(a[2]), "r"(a[3]), "r"(b0), "r"(b1));
}
__device__ __forceinline__ void h8_to_f8(uint4 t, float* f) {
    const __half2* hp = (const __half2*)&t;
#pragma unroll
    for (int j = 0; j < 4; j++) {
        float2 xy = __half22float2(hp[j]);
        f[2 * j] = xy.x;
        f[2 * j + 1] = xy.y;
    }
}
__device__ __forceinline__ int lbound(const int* a, int n, int key) {
    int lo = 0, hi = n;
    while (lo < hi) {
        int mid = (lo + hi) >> 1;
        if (a[mid] < key) lo = mid + 1;
        else hi = mid;
    }
    return lo;
}

// ---------------- utility kernels ----------------
__global__ void fill_int_kernel(int* p, int v, int n) {
    int i = blockIdx.x * blockDim.x + threadIdx.x;
    if (i < n) p[i] = v;
}

// ---------------- fp32 -> fp16 convert ----------------
__global__ void convA_kernel(const float* __restrict__ A, __half* __restrict__ out, size_t n) {
    size_t i = (size_t)blockIdx.x * blockDim.x + threadIdx.x;
    if (i >= n) return;
    out[i] = __float2half_rn(A[i]);
}

// merged: 4 weight matrices [K,N_z] -> B' rows, z = blockIdx.z
__global__ void convBT4_kernel(const float* __restrict__ qw, const float* __restrict__ kw,
                               const float* __restrict__ vw, const float* __restrict__ sw,
                               __half* __restrict__ out, int K, int hc, int C) {
    int z = blockIdx.z;
    const float* W = (z == 0) ? qw : (z == 1) ? kw : (z == 2) ? vw : sw;
    int N = (z < 3) ? hc : C;
    int rowOff = z * hc;
    __shared__ float t[32][33];
    int kb = blockIdx.x * 32, nb = blockIdx.y * 32;
    if (nb >= N) return;
    int tx = threadIdx.x, ty = threadIdx.y;  // 32 x 8
    for (int r = ty; r < 32; r += 8) {
        int kk = kb + r, nn2 = nb + tx;
        t[r][tx] = (kk < K && nn2 < N) ? W[(size_t)kk * N + nn2] : 0.f;
    }
    __syncthreads();
    for (int r = ty; r < 32; r += 8) {
        int nn2 = nb + r, kk = kb + tx;
        if (nn2 < N && kk < K)
            out[(size_t)(rowOff + nn2) * K + kk] = __float2half_rn(t[tx][r]);
    }
}

__global__ void pack_bias_kernel(const float* __restrict__ qb, const float* __restrict__ kb,
                                 const float* __restrict__ vb, const float* __restrict__ sb,
                                 int hc, int C, float* __restrict__ out) {
    int i = blockIdx.x * blockDim.x + threadIdx.x;
    int Ntot = 3 * hc + C;
    if (i >= Ntot) return;
    float v;
    if (i < hc) v = qb[i];
    else if (i < 2 * hc) v = kb[i - hc];
    else if (i < 3 * hc) v = vb[i - 2 * hc];
    else v = sb[i - 3 * hc];
    out[i] = v;
}

// ---------------- fp16 mma.sync GEMM: 64x256 tile, 256 threads, 2 CTAs/SM ----------------
#define BM 64
#define BN 256
#define LDT 40
#define SA_BYTES (BM * LDT * 2)
#define SB_BYTES (BN * LDT * 2)
#define GEMM_SMEM (3 * (SA_BYTES + SB_BYTES))

__global__ void __launch_bounds__(256, 2)
gemm_mma_kernel(const __half* __restrict__ A, const __half* __restrict__ B,
                const float* __restrict__ bias, __half* __restrict__ C,
                int M, int K, int N) {
    extern __shared__ char smraw[];
    uint32_t aBase = smem_u32(smraw);
    uint32_t bBase = aBase + 3 * SA_BYTES;
    int tid = threadIdx.x;
    int lane = tid & 31, wid = tid >> 5;
    int m0 = blockIdx.y * BM, n0 = blockIdx.x * BN;
    int warp_m = wid >> 2, warp_n = wid & 3;  // 2 x 4
    int m_base = warp_m * 32, n_base = warp_n * 64;

    float acc[2][8][4];
#pragma unroll
    for (int i = 0; i < 2; i++)
#pragma unroll
        for (int j = 0; j < 8; j++)
#pragma unroll
            for (int r = 0; r < 4; r++) acc[i][j][r] = 0.f;

    int nk = K >> 5;

    auto load_stage = [&](int st, int kt) {
        // A: 64 rows x 4 chunks = 256 tasks (1/thread)
        {
            int row = tid >> 2, ch = tid & 3;
            int gr = m0 + row;
            uint32_t sa = aBase + st * SA_BYTES + (row * LDT + ch * 8) * 2;
            const __half* g = A + (size_t)(gr < M ? gr : 0) * K + kt * 32 + ch * 8;
            cp16(sa, g, gr < M);
        }
        // B: 256 rows x 4 chunks = 1024 tasks (4/thread)
#pragma unroll
        for (int l = 0; l < 4; l++) {
            int idx = tid + l * 256;
            int row = idx >> 2, ch = idx & 3;
            int gn = n0 + row;
            uint32_t sb = bBase + st * SB_BYTES + (row * LDT + ch * 8) * 2;
            const __half* g = B + (size_t)(gn < N ? gn : 0) * K + kt * 32 + ch * 8;
            cp16(sb, g, gn < N);
        }
        cp_commit();
    };

    load_stage(0, 0);
    if (nk > 1) load_stage(1, 1);
    else cp_commit();

    int a_r = lane & 15;
    int a_c = (lane >> 4) * 8;
    int b_r = (lane & 7) + ((lane >> 4) << 3);
    int b_c = ((lane >> 3) & 1) * 8;

    for (int kt = 0; kt < nk; kt++) {
        int st = kt % 3;
        if (kt + 1 < nk) cp_wait1();
        else cp_wait0();
        __syncthreads();
        if (kt + 2 < nk) load_stage((kt + 2) % 3, kt + 2);
        uint32_t sa = aBase + st * SA_BYTES;
        uint32_t sb = bBase + st * SB_BYTES;
#pragma unroll
        for (int ks = 0; ks < 32; ks += 16) {
            uint32_t af[2][4];
#pragma unroll
            for (int im = 0; im < 2; im++)
                ldmx4(af[im], sa + ((m_base + im * 16 + a_r) * LDT + ks + a_c) * 2);
            uint32_t bf[4][4];
#pragma unroll
            for (int ib = 0; ib < 4; ib++)
                ldmx4(bf[ib], sb + ((n_base + ib * 16 + b_r) * LDT + ks + b_c) * 2);
#pragma unroll
            for (int im = 0; im < 2; im++)
#pragma unroll
                for (int jn = 0; jn < 8; jn++)
                    mma_fp16(acc[im][jn], af[im], bf[jn >> 1][(jn & 1) * 2], bf[jn >> 1][(jn & 1) * 2 + 1]);
        }
        __syncthreads();
    }

#pragma unroll
    for (int im = 0; im < 2; im++) {
        int row0 = m0 + m_base + im * 16 + (lane >> 2);
#pragma unroll
        for (int jn = 0; jn < 8; jn++) {
            int col = n0 + n_base + jn * 8 + (lane & 3) * 2;
            if (col < N) {
                float bx = bias[col], by = bias[col + 1];
                if (row0 < M) {
                    __half2 o = __floats2half2_rn(acc[im][jn][0] + bx, acc[im][jn][1] + by);
                    *(__half2*)&C[(size_t)row0 * N + col] = o;
                }
                if (row0 + 8 < M) {
                    __half2 o = __floats2half2_rn(acc[im][jn][2] + bx, acc[im][jn][3] + by);
                    *(__half2*)&C[(size_t)(row0 + 8) * N + col] = o;
                }
            }
        }
    }
}

// ---------------- CSR build ----------------
__global__ void hist_kernel(const int* __restrict__ dst, int* __restrict__ deg) {
    int e = blockIdx.x * blockDim.x + threadIdx.x;
    if (e < NE) atomicAdd(&deg[dst[e]], 1);
}
__global__ void csr_scan_kernel(const int* __restrict__ deg, int* __restrict__ rowptr,
                                int* __restrict__ cursor) {
    __shared__ int part[1024];
    int t = threadIdx.x;
    int base = t * 10;
    int local[10];
    int s = 0;
#pragma unroll
    for (int i = 0; i < 10; i++) {
        int idx = base + i;
        local[i] = (idx < NN) ? deg[idx] : 0;
        s += local[i];
    }
    part[t] = s;
    __syncthreads();
    for (int off = 1; off < 1024; off <<= 1) {
        int v = (t >= off) ? part[t - off] : 0;
        __syncthreads();
        part[t] += v;
        __syncthreads();
    }
    int run = (t > 0) ? part[t - 1] : 0;
#pragma unroll
    for (int i = 0; i < 10; i++) {
        int idx = base + i;
        if (idx < NN) {
            rowptr[idx] = run;
            cursor[idx] = run;
            run += local[i];
        }
    }
    if (t == 1023) rowptr[NN] = run;
}
__global__ void scatter_kernel(const int* __restrict__ dst, int* __restrict__ cursor,
                               int* __restrict__ perm) {
    int e = blockIdx.x * blockDim.x + threadIdx.x;
    if (e < NE) {
        int pos = atomicAdd(&cursor[dst[e]], 1);
        perm[pos] = e;
    }
}

// ---------------- fused attention + head-mean + skip + ELU (+ optional gate) ----------------
template <int CC>
__global__ void __launch_bounds__(256)
attn_combine_kernel(const __half* __restrict__ qkvs, int ld, int hc,
                    const int* __restrict__ rowptr, const int* __restrict__ perm,
                    const int* __restrict__ src,
                    float* __restrict__ hout, __half* __restrict__ Anext, float scale,
                    const float* __restrict__ gw, const float* __restrict__ gb,
                    float* __restrict__ gatep) {
    extern __shared__ float sred[];  // [HH][CC]
    int n = blockIdx.x;
    int tid = threadIdx.x;
    int h = tid >> 5, lane = tid & 31;
    const __half* q = qkvs;
    const __half* k = qkvs + hc;
    const __half* v = qkvs + 2 * hc;
    const size_t qbase = (size_t)n * ld + (size_t)h * CC;
    int j0 = rowptr[n], j1 = rowptr[n + 1];
    float mmax = -INFINITY, den = 0.f;

    if constexpr (CC >= 256) {
        const int R = CC / 256;
        float qv[R][8], acc[R][8];
#pragma unroll
        for (int i = 0; i < R; i++) {
            uint4 t = *(const uint4*)(q + qbase + i * 256 + lane * 8);
            h8_to_f8(t, qv[i]);
#pragma unroll
            for (int j = 0; j < 8; j++) acc[i][j] = 0.f;
        }
        for (int j = j0; j < j1; j++) {
            int s = src[perm[j]];
            const size_t sb = (size_t)s * ld + (size_t)h * CC;
            float kf[R][8], vf[R][8];
#pragma unroll
            for (int i = 0; i < R; i++) {
                uint4 tk = *(const uint4*)(k + sb + i * 256 + lane * 8);
                uint4 tv = *(const uint4*)(v + sb + i * 256 + lane * 8);
                h8_to_f8(tk, kf[i]);
                h8_to_f8(tv, vf[i]);
            }
            float dot = 0.f;
#pragma unroll
            for (int i = 0; i < R; i++)
#pragma unroll
                for (int c = 0; c < 8; c++) dot = fmaf(qv[i][c], kf[i][c], dot);
#pragma unroll
            for (int o = 16; o; o >>= 1) dot += __shfl_xor_sync(0xFFFFFFFFu, dot, o);
            float a = dot * scale;
            float mnew = fmaxf(mmax, a);
            float corr = __expf(mmax - mnew);
            float wt = __expf(a - mnew);
            den = den * corr + wt;
#pragma unroll
            for (int i = 0; i < R; i++)
#pragma unroll
                for (int c = 0; c < 8; c++) acc[i][c] = fmaf(wt, vf[i][c], acc[i][c] * corr);
            mmax = mnew;
        }
        float inv = 1.f / fmaxf(den, 1e-16f);
#pragma unroll
        for (int i = 0; i < R; i++) {
            float4 o0 = make_float4(acc[i][0] * inv, acc[i][1] * inv, acc[i][2] * inv, acc[i][3] * inv);
            float4 o1 = make_float4(acc[i][4] * inv, acc[i][5] * inv, acc[i][6] * inv, acc[i][7] * inv);
            *(float4*)(sred + h * CC + i * 256 + lane * 8) = o0;
            *(float4*)(sred + h * CC + i * 256 + lane * 8 + 4) = o1;
        }
    } else {
        float2 qv = __half22float2(*(const __half2*)(q + qbase + lane * 2));
        float2 acc = make_float2(0.f, 0.f);
        for (int j = j0; j < j1; j++) {
            int s = src[perm[j]];
            const size_t sb = (size_t)s * ld + (size_t)h * CC;
            float2 kv = __half22float2(*(const __half2*)(k + sb + lane * 2));
            float2 vv = __half22float2(*(const __half2*)(v + sb + lane * 2));
            float dot = fmaf(qv.x, kv.x, qv.y * kv.y);
#pragma unroll
            for (int o = 16; o; o >>= 1) dot += __shfl_xor_sync(0xFFFFFFFFu, dot, o);
            float a = dot * scale;
            float mnew = fmaxf(mmax, a);
            float corr = __expf(mmax - mnew);
            float wt = __expf(a - mnew);
            den = den * corr + wt;
            acc.x = fmaf(wt, vv.x, acc.x * corr);
            acc.y = fmaf(wt, vv.y, acc.y * corr);
            mmax = mnew;
        }
        float inv = 1.f / fmaxf(den, 1e-16f);
        *(float2*)(sred + h * CC + lane * 2) = make_float2(acc.x * inv, acc.y * inv);
    }
    __syncthreads();

    const __half* skipp = qkvs + 3 * hc;
    float gacc = 0.f;
    for (int c = tid; c < CC; c += 256) {
        float s = 0.f;
#pragma unroll
        for (int h2 = 0; h2 < HH; h2++) s += sred[h2 * CC + c];
        float val = s * (1.f / HH) + __half2float(skipp[(size_t)n * ld + c]);
        val = val > 0.f ? val : expm1f(val);
        if (hout) hout[(size_t)n * CC + c] = val;
        if (Anext) Anext[(size_t)n * CC + c] = __float2half_rn(val);
        if (gatep) gacc = fmaf(val, gw[c], gacc);
    }
    if (gatep) {
        __syncthreads();
        sred[tid] = gacc;
        __syncthreads();
        for (int off = 128; off; off >>= 1) {
            if (tid < off) sred[tid] += sred[tid + off];
            __syncthreads();
        }
        if (tid == 0) gatep[n] = sred[0] + gb[0];
    }
}

// ---------------- fused pooling: one block per graph ----------------
__global__ void __launch_bounds__(256)
pool_all_kernel(const float* __restrict__ h, const float* __restrict__ gate,
                const int* __restrict__ batch, const float* __restrict__ fw,
                const float* __restrict__ fb, float* __restrict__ out) {
    __shared__ float red[256];
    __shared__ float spool[4][64];
    __shared__ float pool[64];
    __shared__ float sm, sd;
    int g = blockIdx.x;
    int tid = threadIdx.x;
    int lo = lbound(batch, NN, g);
    int hi = lbound(batch, NN, g + 1);

    float m = -INFINITY;
    for (int n = lo + tid; n < hi; n += 256) m = fmaxf(m, gate[n]);
    red[tid] = m;
    __syncthreads();
    for (int off = 128; off; off >>= 1) {
        if (tid < off) red[tid] = fmaxf(red[tid], red[tid + off]);
        __syncthreads();
    }
    if (tid == 0) sm = red[0];
    __syncthreads();
    float mm = sm;

    float s = 0.f;
    for (int n = lo + tid; n < hi; n += 256) s += expf(gate[n] - mm);
    red[tid] = s;
    __syncthreads();
    for (int off = 128; off; off >>= 1) {
        if (tid < off) red[tid] += red[tid + off];
        __syncthreads();
    }
    if (tid == 0) sd = fmaxf(red[0], 1e-16f);
    __syncthreads();
    float inv = 1.f / sd;

    int grp = tid >> 6, c = tid & 63;
    float acc = 0.f;
    for (int n = lo + grp; n < hi; n += 4) {
        float w = expf(gate[n] - mm) * inv;
        acc = fmaf(w, h[(size_t)n * 64 + c], acc);
    }
    spool[grp][c] = acc;
    __syncthreads();
    if (tid < 64) pool[tid] = spool[0][tid] + spool[1][tid] + spool[2][tid] + spool[3][tid];
    __syncthreads();

    if (tid < 10) {
        float o = fb[tid];
#pragma unroll
        for (int cc = 0; cc < 64; cc++) o = fmaf(pool[cc], fw[cc * 10 + tid], o);
        out[g * 10 + tid] = o;
    }
}

// ---------------- host side ----------------
struct Ptrs {
    __half* qkvs;
    float *hA, *gate, *biasp;
    __half *Ac, *Bc;
    int *deg, *rowptr, *cursor, *perm;
};

static void layer_gemm(int fin, int C, const float* const* W, const Ptrs& P) {
    int hc = C * HH;
    int Ntot = 3 * hc + C;
    dim3 tg((fin + 31) / 32, (hc + 31) / 32, 4);
    convBT4_kernel<<<tg, dim3(32, 8)>>>(W[0], W[2], W[4], W[6], P.Bc, fin, hc, C);
    pack_bias_kernel<<<(Ntot + 255) / 256, 256>>>(W[1], W[3], W[5], W[7], hc, C, P.biasp);
    dim3 grid((Ntot + BN - 1) / BN, (NN + BM - 1) / BM);
    gemm_mma_kernel<<<grid, 256, GEMM_SMEM>>>(P.Ac, P.Bc, P.biasp, P.qkvs, NN, fin, Ntot);
}

static void layer_attn(int C, const int* src, float* hout, __half* Anext,
                       const float* gw, const float* gb, float* gatep, const Ptrs& P) {
    int hc = C * HH;
    int Ntot = 3 * hc + C;
    float scale = 1.f / sqrtf((float)C);
    int smem = HH * C * sizeof(float);
    if (C == 512)
        attn_combine_kernel<512><<<NN, 256, smem>>>(P.qkvs, Ntot, hc, P.rowptr, P.perm, src, hout, Anext, scale, gw, gb, gatep);
    else if (C == 256)
        attn_combine_kernel<256><<<NN, 256, smem>>>(P.qkvs, Ntot, hc, P.rowptr, P.perm, src, hout, Anext, scale, gw, gb, gatep);
    else
        attn_combine_kernel<64><<<NN, 256, smem>>>(P.qkvs, Ntot, hc, P.rowptr, P.perm, src, hout, Anext, scale, gw, gb, gatep);
}

extern "C" void kernel_launch(void* const* d_in, const int* in_sizes, int n_in,
                              void* d_out, int out_size) {
    const float* x     = (const float*)d_in[0];
    const int*   ei    = (const int*)d_in[1];
    const int*   batch = (const int*)d_in[2];
    const float* W[24];
    for (int i = 0; i < 24; i++) W[i] = (const float*)d_in[3 + i];
    const float* gate_w = (const float*)d_in[27];
    const float* gate_b = (const float*)d_in[28];
    const float* fc_w   = (const float*)d_in[29];
    const float* fc_b   = (const float*)d_in[30];
    float* out = (float*)d_out;

    const int* src = ei;
    const int* dst = ei + NE;

    cudaFuncSetAttribute(gemm_mma_kernel, cudaFuncAttributeMaxDynamicSharedMemorySize, GEMM_SMEM);

    Ptrs P;
    cudaGetSymbolAddress((void**)&P.qkvs, g_qkvs);
    cudaGetSymbolAddress((void**)&P.hA, g_hA);
    cudaGetSymbolAddress((void**)&P.gate, g_gate);
    cudaGetSymbolAddress((void**)&P.biasp, g_biasp);
    cudaGetSymbolAddress((void**)&P.Ac, g_Acomp);
    cudaGetSymbolAddress((void**)&P.Bc, g_Bcomp);
    cudaGetSymbolAddress((void**)&P.deg, g_deg);
    cudaGetSymbolAddress((void**)&P.rowptr, g_rowptr);
    cudaGetSymbolAddress((void**)&P.cursor, g_cursor);
    cudaGetSymbolAddress((void**)&P.perm, g_perm);

    size_t na = (size_t)NN * 128;
    convA_kernel<<<(unsigned)((na + 255) / 256), 256>>>(x, P.Ac, na);
    layer_gemm(128, 512, &W[0], P);

    fill_int_kernel<<<(NN + 255) / 256, 256>>>(P.deg, 0, NN);
    hist_kernel<<<(NE + 255) / 256, 256>>>(dst, P.deg);
    csr_scan_kernel<<<1, 1024>>>(P.deg, P.rowptr, P.cursor);
    scatter_kernel<<<(NE + 255) / 256, 256>>>(dst, P.cursor, P.perm);

    layer_attn(512, src, nullptr, P.Ac, nullptr, nullptr, nullptr, P);

    layer_gemm(512, 256, &W[8], P);
    layer_attn(256, src, nullptr, P.Ac, nullptr, nullptr, nullptr, P);

    layer_gemm(256, 64, &W[16], P);
    layer_attn(64, src, P.hA, nullptr, gate_w, gate_b, P.gate, P);

    pool_all_kernel<<<NG, 256>>>(P.hA, P.gate, batch, fc_w, fc_b, out);
}

// round 11
// speedup vs baseline: 6.8961x; 1.0705x over previous
#include <cuda_runtime.h>
#include <cuda_fp16.h>
#include <math.h>
#include <stdint.h>

#define NN 10000
#define NE 30000
#define NG 50
#define HH 8
#define NTOT1 12800  // 3*4096+512

// ---------------- scratch (device globals) ----------------
__device__ __half g_qkvs[NN * NTOT1];
__device__ float g_hA[NN * 512];
__device__ float g_gate[NN];
__device__ float g_biasp[NTOT1];
__device__ __half g_Acomp[NN * 512];
__device__ __half g_Bcomp[6400 * 512];
__device__ int g_deg[NN];
__device__ int g_rowptr[NN + 1];
__device__ int g_cursor[NN];
__device__ int g_perm[NE];

// ---------------- helpers ----------------
__device__ __forceinline__ uint32_t smem_u32(const void* p) {
    uint32_t a;
    asm("{ .reg .u64 t; cvta.to.shared.u64 t, %1; cvt.u32.u64 %0, t; }" : "=r"(a) : "l"(p));
    return a;
}
__device__ __forceinline__ void cp16(uint32_t saddr, const void* g, bool pred) {
    int sz = pred ? 16 : 0;
    asm volatile("cp.async.cg.shared.global [%0], [%1], 16, %2;" :: "r"(saddr), "l"(g), "r"(sz));
}
__device__ __forceinline__ void cp_commit() { asm volatile("cp.async.commit_group;"); }
__device__ __forceinline__ void cp_wait0() { asm volatile("cp.async.wait_group 0;"); }
__device__ __forceinline__ void ldmx4(uint32_t* r, uint32_t addr) {
    asm volatile("ldmatrix.sync.aligned.m8n8.x4.shared.b16 {%0,%1,%2,%3}, [%4];"
                 : "=r"(r[0]), "=r"(r[1]), "=r"(r[2]), "=r"(r[3]) : "r"(addr));
}
__device__ __forceinline__ void mma_fp16(float* c, const uint32_t* a, uint32_t b0, uint32_t b1) {
    asm volatile(
        "mma.sync.aligned.m16n8k16.row.col.f32.f16.f16.f32 "
        "{%0,%1,%2,%3}, {%4,%5,%6,%7}, {%8,%9}, {%0,%1,%2,%3};"
        : "+f"(c[0]), "+f"(c[1]), "+f"(c[2]), "+f"(c[3])
        : "r"(a[0]), "r"(a[1]), "r"(a[2]), "r"(a[3]), "r"(b0), "r"(b1));
}
__device__ __forceinline__ void h8_to_f8(uint4 t, float* f) {
    const __half2* hp = (const __half2*)&t;
#pragma unroll
    for (int j = 0; j < 4; j++) {
        float2 xy = __half22float2(hp[j]);
        f[2 * j] = xy.x;
        f[2 * j + 1] = xy.y;
    }
}
__device__ __forceinline__ int lbound(const int* a, int n, int key) {
    int lo = 0, hi = n;
    while (lo < hi) {
        int mid = (lo + hi) >> 1;
        if (a[mid] < key) lo = mid + 1;
        else hi = mid;
    }
    return lo;
}

// ---------------- utility kernels ----------------
__global__ void fill_int_kernel(int* p, int v, int n) {
    int i = blockIdx.x * blockDim.x + threadIdx.x;
    if (i < n) p[i] = v;
}

// ---------------- fp32 -> fp16 convert ----------------
__global__ void convA_kernel(const float* __restrict__ A, __half* __restrict__ out, size_t n) {
    size_t i = (size_t)blockIdx.x * blockDim.x + threadIdx.x;
    if (i >= n) return;
    out[i] = __float2half_rn(A[i]);
}

// merged: 4 weight matrices [K,N_z] -> B' rows, z = blockIdx.z
__global__ void convBT4_kernel(const float* __restrict__ qw, const float* __restrict__ kw,
                               const float* __restrict__ vw, const float* __restrict__ sw,
                               __half* __restrict__ out, int K, int hc, int C) {
    int z = blockIdx.z;
    const float* W = (z == 0) ? qw : (z == 1) ? kw : (z == 2) ? vw : sw;
    int N = (z < 3) ? hc : C;
    int rowOff = z * hc;
    __shared__ float t[32][33];
    int kb = blockIdx.x * 32, nb = blockIdx.y * 32;
    if (nb >= N) return;
    int tx = threadIdx.x, ty = threadIdx.y;  // 32 x 8
    for (int r = ty; r < 32; r += 8) {
        int kk = kb + r, nn2 = nb + tx;
        t[r][tx] = (kk < K && nn2 < N) ? W[(size_t)kk * N + nn2] : 0.f;
    }
    __syncthreads();
    for (int r = ty; r < 32; r += 8) {
        int nn2 = nb + r, kk = kb + tx;
        if (nn2 < N && kk < K)
            out[(size_t)(rowOff + nn2) * K + kk] = __float2half_rn(t[tx][r]);
    }
}

__global__ void pack_bias_kernel(const float* __restrict__ qb, const float* __restrict__ kb,
                                 const float* __restrict__ vb, const float* __restrict__ sb,
                                 int hc, int C, float* __restrict__ out) {
    int i = blockIdx.x * blockDim.x + threadIdx.x;
    int Ntot = 3 * hc + C;
    if (i >= Ntot) return;
    float v;
    if (i < hc) v = qb[i];
    else if (i < 2 * hc) v = kb[i - hc];
    else if (i < 3 * hc) v = vb[i - 2 * hc];
    else v = sb[i - 3 * hc];
    out[i] = v;
}

// ---------------- fp16 mma.sync GEMM: 64x256 tile, BKK=64, single-sync double buffer ----------------
#define BM 64
#define BN 256
#define BKK 64
#define LDT 72
#define SA_BYTES (BM * LDT * 2)
#define SB_BYTES (BN * LDT * 2)
#define GEMM_SMEM (2 * (SA_BYTES + SB_BYTES))

__global__ void __launch_bounds__(256, 2)
gemm_mma_kernel(const __half* __restrict__ A, const __half* __restrict__ B,
                const float* __restrict__ bias, __half* __restrict__ C,
                int M, int K, int N) {
    extern __shared__ char smraw[];
    uint32_t aBase = smem_u32(smraw);
    uint32_t bBase = aBase + 2 * SA_BYTES;
    int tid = threadIdx.x;
    int lane = tid & 31, wid = tid >> 5;
    int m0 = blockIdx.y * BM, n0 = blockIdx.x * BN;
    int warp_m = wid >> 2, warp_n = wid & 3;  // 2 x 4
    int m_base = warp_m * 32, n_base = warp_n * 64;

    float acc[2][8][4];
#pragma unroll
    for (int i = 0; i < 2; i++)
#pragma unroll
        for (int j = 0; j < 8; j++)
#pragma unroll
            for (int r = 0; r < 4; r++) acc[i][j][r] = 0.f;

    int nk = K >> 6;  // K multiple of 64 (128/256/512)

    auto load_stage = [&](int st, int kt) {
        // A: 64 rows x 8 chunks = 512 tasks (2/thread)
#pragma unroll
        for (int l = 0; l < 2; l++) {
            int idx = tid + l * 256;
            int row = idx >> 3, ch = idx & 7;
            int gr = m0 + row;
            uint32_t sa = aBase + st * SA_BYTES + (row * LDT + ch * 8) * 2;
            const __half* g = A + (size_t)(gr < M ? gr : 0) * K + kt * BKK + ch * 8;
            cp16(sa, g, gr < M);
        }
        // B: 256 rows x 8 chunks = 2048 tasks (8/thread)
#pragma unroll
        for (int l = 0; l < 8; l++) {
            int idx = tid + l * 256;
            int row = idx >> 3, ch = idx & 7;
            int gn = n0 + row;
            uint32_t sb = bBase + st * SB_BYTES + (row * LDT + ch * 8) * 2;
            const __half* g = B + (size_t)(gn < N ? gn : 0) * K + kt * BKK + ch * 8;
            cp16(sb, g, gn < N);
        }
        cp_commit();
    };

    load_stage(0, 0);

    int a_r = lane & 15;
    int a_c = (lane >> 4) * 8;
    int b_r = (lane & 7) + ((lane >> 4) << 3);
    int b_c = ((lane >> 3) & 1) * 8;

    for (int kt = 0; kt < nk; kt++) {
        int st = kt & 1;
        cp_wait0();
        __syncthreads();
        if (kt + 1 < nk) load_stage(st ^ 1, kt + 1);
        uint32_t sa = aBase + st * SA_BYTES;
        uint32_t sb = bBase + st * SB_BYTES;
#pragma unroll
        for (int ks = 0; ks < BKK; ks += 16) {
            uint32_t af[2][4];
#pragma unroll
            for (int im = 0; im < 2; im++)
                ldmx4(af[im], sa + ((m_base + im * 16 + a_r) * LDT + ks + a_c) * 2);
            uint32_t bf[4][4];
#pragma unroll
            for (int ib = 0; ib < 4; ib++)
                ldmx4(bf[ib], sb + ((n_base + ib * 16 + b_r) * LDT + ks + b_c) * 2);
#pragma unroll
            for (int im = 0; im < 2; im++)
#pragma unroll
                for (int jn = 0; jn < 8; jn++)
                    mma_fp16(acc[im][jn], af[im], bf[jn >> 1][(jn & 1) * 2], bf[jn >> 1][(jn & 1) * 2 + 1]);
        }
    }

#pragma unroll
    for (int im = 0; im < 2; im++) {
        int row0 = m0 + m_base + im * 16 + (lane >> 2);
#pragma unroll
        for (int jn = 0; jn < 8; jn++) {
            int col = n0 + n_base + jn * 8 + (lane & 3) * 2;
            if (col < N) {
                float bx = bias[col], by = bias[col + 1];
                if (row0 < M) {
                    __half2 o = __floats2half2_rn(acc[im][jn][0] + bx, acc[im][jn][1] + by);
                    *(__half2*)&C[(size_t)row0 * N + col] = o;
                }
                if (row0 + 8 < M) {
                    __half2 o = __floats2half2_rn(acc[im][jn][2] + bx, acc[im][jn][3] + by);
                    *(__half2*)&C[(size_t)(row0 + 8) * N + col] = o;
                }
            }
        }
    }
}

// ---------------- CSR build ----------------
__global__ void hist_kernel(const int* __restrict__ dst, int* __restrict__ deg) {
    int e = blockIdx.x * blockDim.x + threadIdx.x;
    if (e < NE) atomicAdd(&deg[dst[e]], 1);
}
__global__ void csr_scan_kernel(const int* __restrict__ deg, int* __restrict__ rowptr,
                                int* __restrict__ cursor) {
    __shared__ int part[1024];
    int t = threadIdx.x;
    int base = t * 10;
    int local[10];
    int s = 0;
#pragma unroll
    for (int i = 0; i < 10; i++) {
        int idx = base + i;
        local[i] = (idx < NN) ? deg[idx] : 0;
        s += local[i];
    }
    part[t] = s;
    __syncthreads();
    for (int off = 1; off < 1024; off <<= 1) {
        int v = (t >= off) ? part[t - off] : 0;
        __syncthreads();
        part[t] += v;
        __syncthreads();
    }
    int run = (t > 0) ? part[t - 1] : 0;
#pragma unroll
    for (int i = 0; i < 10; i++) {
        int idx = base + i;
        if (idx < NN) {
            rowptr[idx] = run;
            cursor[idx] = run;
            run += local[i];
        }
    }
    if (t == 1023) rowptr[NN] = run;
}
__global__ void scatter_kernel(const int* __restrict__ dst, int* __restrict__ cursor,
                               int* __restrict__ perm) {
    int e = blockIdx.x * blockDim.x + threadIdx.x;
    if (e < NE) {
        int pos = atomicAdd(&cursor[dst[e]], 1);
        perm[pos] = e;
    }
}

// ---------------- fused attention + head-mean + skip + ELU (+ optional gate) ----------------
template <int CC>
__global__ void __launch_bounds__(256)
attn_combine_kernel(const __half* __restrict__ qkvs, int ld, int hc,
                    const int* __restrict__ rowptr, const int* __restrict__ perm,
                    const int* __restrict__ src,
                    float* __restrict__ hout, __half* __restrict__ Anext, float scale,
                    const float* __restrict__ gw, const float* __restrict__ gb,
                    float* __restrict__ gatep) {
    extern __shared__ float sred[];  // [HH][CC]
    int n = blockIdx.x;
    int tid = threadIdx.x;
    int h = tid >> 5, lane = tid & 31;
    const __half* q = qkvs;
    const __half* k = qkvs + hc;
    const __half* v = qkvs + 2 * hc;
    const size_t qbase = (size_t)n * ld + (size_t)h * CC;
    int j0 = rowptr[n], j1 = rowptr[n + 1];
    float mmax = -INFINITY, den = 0.f;

    if constexpr (CC >= 256) {
        const int R = CC / 256;
        float qv[R][8], acc[R][8];
#pragma unroll
        for (int i = 0; i < R; i++) {
            uint4 t = *(const uint4*)(q + qbase + i * 256 + lane * 8);
            h8_to_f8(t, qv[i]);
#pragma unroll
            for (int j = 0; j < 8; j++) acc[i][j] = 0.f;
        }
        for (int j = j0; j < j1; j++) {
            int s = src[perm[j]];
            const size_t sb = (size_t)s * ld + (size_t)h * CC;
            float kf[R][8], vf[R][8];
#pragma unroll
            for (int i = 0; i < R; i++) {
                uint4 tk = *(const uint4*)(k + sb + i * 256 + lane * 8);
                uint4 tv = *(const uint4*)(v + sb + i * 256 + lane * 8);
                h8_to_f8(tk, kf[i]);
                h8_to_f8(tv, vf[i]);
            }
            float dot = 0.f;
#pragma unroll
            for (int i = 0; i < R; i++)
#pragma unroll
                for (int c = 0; c < 8; c++) dot = fmaf(qv[i][c], kf[i][c], dot);
#pragma unroll
            for (int o = 16; o; o >>= 1) dot += __shfl_xor_sync(0xFFFFFFFFu, dot, o);
            float a = dot * scale;
            float mnew = fmaxf(mmax, a);
            float corr = __expf(mmax - mnew);
            float wt = __expf(a - mnew);
            den = den * corr + wt;
#pragma unroll
            for (int i = 0; i < R; i++)
#pragma unroll
                for (int c = 0; c < 8; c++) acc[i][c] = fmaf(wt, vf[i][c], acc[i][c] * corr);
            mmax = mnew;
        }
        float inv = 1.f / fmaxf(den, 1e-16f);
#pragma unroll
        for (int i = 0; i < R; i++) {
            float4 o0 = make_float4(acc[i][0] * inv, acc[i][1] * inv, acc[i][2] * inv, acc[i][3] * inv);
            float4 o1 = make_float4(acc[i][4] * inv, acc[i][5] * inv, acc[i][6] * inv, acc[i][7] * inv);
            *(float4*)(sred + h * CC + i * 256 + lane * 8) = o0;
            *(float4*)(sred + h * CC + i * 256 + lane * 8 + 4) = o1;
        }
    } else {
        float2 qv = __half22float2(*(const __half2*)(q + qbase + lane * 2));
        float2 acc = make_float2(0.f, 0.f);
        for (int j = j0; j < j1; j++) {
            int s = src[perm[j]];
            const size_t sb = (size_t)s * ld + (size_t)h * CC;
            float2 kv = __half22float2(*(const __half2*)(k + sb + lane * 2));
            float2 vv = __half22float2(*(const __half2*)(v + sb + lane * 2));
            float dot = fmaf(qv.x, kv.x, qv.y * kv.y);
#pragma unroll
            for (int o = 16; o; o >>= 1) dot += __shfl_xor_sync(0xFFFFFFFFu, dot, o);
            float a = dot * scale;
            float mnew = fmaxf(mmax, a);
            float corr = __expf(mmax - mnew);
            float wt = __expf(a - mnew);
            den = den * corr + wt;
            acc.x = fmaf(wt, vv.x, acc.x * corr);
            acc.y = fmaf(wt, vv.y, acc.y * corr);
            mmax = mnew;
        }
        float inv = 1.f / fmaxf(den, 1e-16f);
        *(float2*)(sred + h * CC + lane * 2) = make_float2(acc.x * inv, acc.y * inv);
    }
    __syncthreads();

    const __half* skipp = qkvs + 3 * hc;
    float gacc = 0.f;
    for (int c = tid; c < CC; c += 256) {
        float s = 0.f;
#pragma unroll
        for (int h2 = 0; h2 < HH; h2++) s += sred[h2 * CC + c];
        float val = s * (1.f / HH) + __half2float(skipp[(size_t)n * ld + c]);
        val = val > 0.f ? val : expm1f(val);
        if (hout) hout[(size_t)n * CC + c] = val;
        if (Anext) Anext[(size_t)n * CC + c] = __float2half_rn(val);
        if (gatep) gacc = fmaf(val, gw[c], gacc);
    }
    if (gatep) {
        __syncthreads();
        sred[tid] = gacc;
        __syncthreads();
        for (int off = 128; off; off >>= 1) {
            if (tid < off) sred[tid] += sred[tid + off];
            __syncthreads();
        }
        if (tid == 0) gatep[n] = sred[0] + gb[0];
    }
}

// ---------------- fused pooling: one block per graph ----------------
__global__ void __launch_bounds__(256)
pool_all_kernel(const float* __restrict__ h, const float* __restrict__ gate,
                const int* __restrict__ batch, const float* __restrict__ fw,
                const float* __restrict__ fb, float* __restrict__ out) {
    __shared__ float red[256];
    __shared__ float spool[4][64];
    __shared__ float pool[64];
    __shared__ float sm, sd;
    int g = blockIdx.x;
    int tid = threadIdx.x;
    int lo = lbound(batch, NN, g);
    int hi = lbound(batch, NN, g + 1);

    float m = -INFINITY;
    for (int n = lo + tid; n < hi; n += 256) m = fmaxf(m, gate[n]);
    red[tid] = m;
    __syncthreads();
    for (int off = 128; off; off >>= 1) {
        if (tid < off) red[tid] = fmaxf(red[tid], red[tid + off]);
        __syncthreads();
    }
    if (tid == 0) sm = red[0];
    __syncthreads();
    float mm = sm;

    float s = 0.f;
    for (int n = lo + tid; n < hi; n += 256) s += expf(gate[n] - mm);
    red[tid] = s;
    __syncthreads();
    for (int off = 128; off; off >>= 1) {
        if (tid < off) red[tid] += red[tid + off];
        __syncthreads();
    }
    if (tid == 0) sd = fmaxf(red[0], 1e-16f);
    __syncthreads();
    float inv = 1.f / sd;

    int grp = tid >> 6, c = tid & 63;
    float acc = 0.f;
    for (int n = lo + grp; n < hi; n += 4) {
        float w = expf(gate[n] - mm) * inv;
        acc = fmaf(w, h[(size_t)n * 64 + c], acc);
    }
    spool[grp][c] = acc;
    __syncthreads();
    if (tid < 64) pool[tid] = spool[0][tid] + spool[1][tid] + spool[2][tid] + spool[3][tid];
    __syncthreads();

    if (tid < 10) {
        float o = fb[tid];
#pragma unroll
        for (int cc = 0; cc < 64; cc++) o = fmaf(pool[cc], fw[cc * 10 + tid], o);
        out[g * 10 + tid] = o;
    }
}

// ---------------- host side ----------------
struct Ptrs {
    __half* qkvs;
    float *hA, *gate, *biasp;
    __half *Ac, *Bc;
    int *deg, *rowptr, *cursor, *perm;
};

static void layer_gemm(int fin, int C, const float* const* W, const Ptrs& P) {
    int hc = C * HH;
    int Ntot = 3 * hc + C;
    dim3 tg((fin + 31) / 32, (hc + 31) / 32, 4);
    convBT4_kernel<<<tg, dim3(32, 8)>>>(W[0], W[2], W[4], W[6], P.Bc, fin, hc, C);
    pack_bias_kernel<<<(Ntot + 255) / 256, 256>>>(W[1], W[3], W[5], W[7], hc, C, P.biasp);
    dim3 grid((Ntot + BN - 1) / BN, (NN + BM - 1) / BM);
    gemm_mma_kernel<<<grid, 256, GEMM_SMEM>>>(P.Ac, P.Bc, P.biasp, P.qkvs, NN, fin, Ntot);
}

static void layer_attn(int C, const int* src, float* hout, __half* Anext,
                       const float* gw, const float* gb, float* gatep, const Ptrs& P) {
    int hc = C * HH;
    int Ntot = 3 * hc + C;
    float scale = 1.f / sqrtf((float)C);
    int smem = HH * C * sizeof(float);
    if (C == 512)
        attn_combine_kernel<512><<<NN, 256, smem>>>(P.qkvs, Ntot, hc, P.rowptr, P.perm, src, hout, Anext, scale, gw, gb, gatep);
    else if (C == 256)
        attn_combine_kernel<256><<<NN, 256, smem>>>(P.qkvs, Ntot, hc, P.rowptr, P.perm, src, hout, Anext, scale, gw, gb, gatep);
    else
        attn_combine_kernel<64><<<NN, 256, smem>>>(P.qkvs, Ntot, hc, P.rowptr, P.perm, src, hout, Anext, scale, gw, gb, gatep);
}

extern "C" void kernel_launch(void* const* d_in, const int* in_sizes, int n_in,
                              void* d_out, int out_size) {
    const float* x     = (const float*)d_in[0];
    const int*   ei    = (const int*)d_in[1];
    const int*   batch = (const int*)d_in[2];
    const float* W[24];
    for (int i = 0; i < 24; i++) W[i] = (const float*)d_in[3 + i];
    const float* gate_w = (const float*)d_in[27];
    const float* gate_b = (const float*)d_in[28];
    const float* fc_w   = (const float*)d_in[29];
    const float* fc_b   = (const float*)d_in[30];
    float* out = (float*)d_out;

    const int* src = ei;
    const int* dst = ei + NE;

    cudaFuncSetAttribute(gemm_mma_kernel, cudaFuncAttributeMaxDynamicSharedMemorySize, GEMM_SMEM);

    Ptrs P;
    cudaGetSymbolAddress((void**)&P.qkvs, g_qkvs);
    cudaGetSymbolAddress((void**)&P.hA, g_hA);
    cudaGetSymbolAddress((void**)&P.gate, g_gate);
    cudaGetSymbolAddress((void**)&P.biasp, g_biasp);
    cudaGetSymbolAddress((void**)&P.Ac, g_Acomp);
    cudaGetSymbolAddress((void**)&P.Bc, g_Bcomp);
    cudaGetSymbolAddress((void**)&P.deg, g_deg);
    cudaGetSymbolAddress((void**)&P.rowptr, g_rowptr);
    cudaGetSymbolAddress((void**)&P.cursor, g_cursor);
    cudaGetSymbolAddress((void**)&P.perm, g_perm);

    size_t na = (size_t)NN * 128;
    convA_kernel<<<(unsigned)((na + 255) / 256), 256>>>(x, P.Ac, na);
    layer_gemm(128, 512, &W[0], P);

    fill_int_kernel<<<(NN + 255) / 256, 256>>>(P.deg, 0, NN);
    hist_kernel<<<(NE + 255) / 256, 256>>>(dst, P.deg);
    csr_scan_kernel<<<1, 1024>>>(P.deg, P.rowptr, P.cursor);
    scatter_kernel<<<(NE + 255) / 256, 256>>>(dst, P.cursor, P.perm);

    layer_attn(512, src, nullptr, P.Ac, nullptr, nullptr, nullptr, P);

    layer_gemm(512, 256, &W[8], P);
    layer_attn(256, src, nullptr, P.Ac, nullptr, nullptr, nullptr, P);

    layer_gemm(256, 64, &W[16], P);
    layer_attn(64, src, P.hA, nullptr, gate_w, gate_b, P.gate, P);

    pool_all_kernel<<<NG, 256>>>(P.hA, P.gate, batch, fc_w, fc_b, out);
}

// round 12
// speedup vs baseline: 7.2103x; 1.0456x over previous
#include <cuda_runtime.h>
#include <cuda_fp16.h>
#include <math.h>
#include <stdint.h>

#define NN 10000
#define NE 30000
#define NG 50
#define HH 8
#define NTOT1 12800  // 3*4096+512

// ---------------- scratch (device globals) ----------------
__device__ __half g_qkvs[NN * NTOT1];
__device__ float g_hA[NN * 512];
__device__ float g_gate[NN];
__device__ float g_biasp[NTOT1];
__device__ __half g_Acomp[NN * 512];
__device__ __half g_Bcomp[6400 * 512];
__device__ int g_deg[NN];
__device__ int g_rowptr[NN + 1];
__device__ int g_cursor[NN];
__device__ int g_perm[NE];

// ---------------- helpers ----------------
__device__ __forceinline__ uint32_t smem_u32(const void* p) {
    uint32_t a;
    asm("{ .reg .u64 t; cvta.to.shared.u64 t, %1; cvt.u32.u64 %0, t; }" : "=r"(a) : "l"(p));
    return a;
}
__device__ __forceinline__ void cp16(uint32_t saddr, const void* g, bool pred) {
    int sz = pred ? 16 : 0;
    asm volatile("cp.async.cg.shared.global [%0], [%1], 16, %2;" :: "r"(saddr), "l"(g), "r"(sz));
}
__device__ __forceinline__ void cp_commit() { asm volatile("cp.async.commit_group;"); }
__device__ __forceinline__ void cp_wait0() { asm volatile("cp.async.wait_group 0;"); }
__device__ __forceinline__ void ldmx4(uint32_t* r, uint32_t addr) {
    asm volatile("ldmatrix.sync.aligned.m8n8.x4.shared.b16 {%0,%1,%2,%3}, [%4];"
                 : "=r"(r[0]), "=r"(r[1]), "=r"(r[2]), "=r"(r[3]) : "r"(addr));
}
__device__ __forceinline__ void mma_fp16(float* c, const uint32_t* a, uint32_t b0, uint32_t b1) {
    asm volatile(
        "mma.sync.aligned.m16n8k16.row.col.f32.f16.f16.f32 "
        "{%0,%1,%2,%3}, {%4,%5,%6,%7}, {%8,%9}, {%0,%1,%2,%3};"
        : "+f"(c[0]), "+f"(c[1]), "+f"(c[2]), "+f"(c[3])
        : "r"(a[0]), "r"(a[1]), "r"(a[2]), "r"(a[3]), "r"(b0), "r"(b1));
}
__device__ __forceinline__ void h8_to_f8(uint4 t, float* f) {
    const __half2* hp = (const __half2*)&t;
#pragma unroll
    for (int j = 0; j < 4; j++) {
        float2 xy = __half22float2(hp[j]);
        f[2 * j] = xy.x;
        f[2 * j + 1] = xy.y;
    }
}
__device__ __forceinline__ int lbound(const int* a, int n, int key) {
    int lo = 0, hi = n;
    while (lo < hi) {
        int mid = (lo + hi) >> 1;
        if (a[mid] < key) lo = mid + 1;
        else hi = mid;
    }
    return lo;
}

// ---------------- utility kernels ----------------
__global__ void fill_int_kernel(int* p, int v, int n) {
    int i = blockIdx.x * blockDim.x + threadIdx.x;
    if (i < n) p[i] = v;
}

// ---------------- fp32 -> fp16 convert ----------------
__global__ void convA_kernel(const float* __restrict__ A, __half* __restrict__ out, size_t n) {
    size_t i = (size_t)blockIdx.x * blockDim.x + threadIdx.x;
    if (i >= n) return;
    out[i] = __float2half_rn(A[i]);
}

// merged: 4 weight matrices [K,N_z] -> B' rows, z = blockIdx.z
__global__ void convBT4_kernel(const float* __restrict__ qw, const float* __restrict__ kw,
                               const float* __restrict__ vw, const float* __restrict__ sw,
                               __half* __restrict__ out, int K, int hc, int C) {
    int z = blockIdx.z;
    const float* W = (z == 0) ? qw : (z == 1) ? kw : (z == 2) ? vw : sw;
    int N = (z < 3) ? hc : C;
    int rowOff = z * hc;
    __shared__ float t[32][33];
    int kb = blockIdx.x * 32, nb = blockIdx.y * 32;
    if (nb >= N) return;
    int tx = threadIdx.x, ty = threadIdx.y;  // 32 x 8
    for (int r = ty; r < 32; r += 8) {
        int kk = kb + r, nn2 = nb + tx;
        t[r][tx] = (kk < K && nn2 < N) ? W[(size_t)kk * N + nn2] : 0.f;
    }
    __syncthreads();
    for (int r = ty; r < 32; r += 8) {
        int nn2 = nb + r, kk = kb + tx;
        if (nn2 < N && kk < K)
            out[(size_t)(rowOff + nn2) * K + kk] = __float2half_rn(t[tx][r]);
    }
}

__global__ void pack_bias_kernel(const float* __restrict__ qb, const float* __restrict__ kb,
                                 const float* __restrict__ vb, const float* __restrict__ sb,
                                 int hc, int C, float* __restrict__ out) {
    int i = blockIdx.x * blockDim.x + threadIdx.x;
    int Ntot = 3 * hc + C;
    if (i >= Ntot) return;
    float v;
    if (i < hc) v = qb[i];
    else if (i < 2 * hc) v = kb[i - hc];
    else if (i < 3 * hc) v = vb[i - 2 * hc];
    else v = sb[i - 3 * hc];
    out[i] = v;
}

// ---------------- fp16 mma.sync GEMM: 128x128 tile, BKK=64, single-sync double buffer ----------------
#define BM 128
#define BN 128
#define BKK 64
#define LDT 72
#define SA_BYTES (BM * LDT * 2)
#define SB_BYTES (BN * LDT * 2)
#define GEMM_SMEM (2 * (SA_BYTES + SB_BYTES))

__global__ void __launch_bounds__(256, 2)
gemm_mma_kernel(const __half* __restrict__ A, const __half* __restrict__ B,
                const float* __restrict__ bias, __half* __restrict__ C,
                int M, int K, int N) {
    extern __shared__ char smraw[];
    uint32_t aBase = smem_u32(smraw);
    uint32_t bBase = aBase + 2 * SA_BYTES;
    int tid = threadIdx.x;
    int lane = tid & 31, wid = tid >> 5;
    int m0 = blockIdx.y * BM, n0 = blockIdx.x * BN;
    int warp_m = wid & 3, warp_n = wid >> 2;  // 4 x 2
    int m_base = warp_m * 32, n_base = warp_n * 64;

    float acc[2][8][4];
#pragma unroll
    for (int i = 0; i < 2; i++)
#pragma unroll
        for (int j = 0; j < 8; j++)
#pragma unroll
            for (int r = 0; r < 4; r++) acc[i][j][r] = 0.f;

    int nk = K >> 6;  // K multiple of 64

    auto load_stage = [&](int st, int kt) {
        // A: 128 rows x 8 chunks = 1024 tasks (4/thread)
#pragma unroll
        for (int l = 0; l < 4; l++) {
            int idx = tid + l * 256;
            int row = idx >> 3, ch = idx & 7;
            int gr = m0 + row;
            uint32_t sa = aBase + st * SA_BYTES + (row * LDT + ch * 8) * 2;
            const __half* g = A + (size_t)(gr < M ? gr : 0) * K + kt * BKK + ch * 8;
            cp16(sa, g, gr < M);
        }
        // B: 128 rows x 8 chunks = 1024 tasks (4/thread)
#pragma unroll
        for (int l = 0; l < 4; l++) {
            int idx = tid + l * 256;
            int row = idx >> 3, ch = idx & 7;
            int gn = n0 + row;
            uint32_t sb = bBase + st * SB_BYTES + (row * LDT + ch * 8) * 2;
            const __half* g = B + (size_t)(gn < N ? gn : 0) * K + kt * BKK + ch * 8;
            cp16(sb, g, gn < N);
        }
        cp_commit();
    };

    load_stage(0, 0);

    int a_r = lane & 15;
    int a_c = (lane >> 4) * 8;
    int b_r = (lane & 7) + ((lane >> 4) << 3);
    int b_c = ((lane >> 3) & 1) * 8;

    for (int kt = 0; kt < nk; kt++) {
        int st = kt & 1;
        cp_wait0();
        __syncthreads();
        if (kt + 1 < nk) load_stage(st ^ 1, kt + 1);
        uint32_t sa = aBase + st * SA_BYTES;
        uint32_t sb = bBase + st * SB_BYTES;
#pragma unroll
        for (int ks = 0; ks < BKK; ks += 16) {
            uint32_t af[2][4];
#pragma unroll
            for (int im = 0; im < 2; im++)
                ldmx4(af[im], sa + ((m_base + im * 16 + a_r) * LDT + ks + a_c) * 2);
            uint32_t bf[4][4];
#pragma unroll
            for (int ib = 0; ib < 4; ib++)
                ldmx4(bf[ib], sb + ((n_base + ib * 16 + b_r) * LDT + ks + b_c) * 2);
#pragma unroll
            for (int im = 0; im < 2; im++)
#pragma unroll
                for (int jn = 0; jn < 8; jn++)
                    mma_fp16(acc[im][jn], af[im], bf[jn >> 1][(jn & 1) * 2], bf[jn >> 1][(jn & 1) * 2 + 1]);
        }
    }

#pragma unroll
    for (int im = 0; im < 2; im++) {
        int row0 = m0 + m_base + im * 16 + (lane >> 2);
#pragma unroll
        for (int jn = 0; jn < 8; jn++) {
            int col = n0 + n_base + jn * 8 + (lane & 3) * 2;
            if (col < N) {
                float bx = bias[col], by = bias[col + 1];
                if (row0 < M) {
                    __half2 o = __floats2half2_rn(acc[im][jn][0] + bx, acc[im][jn][1] + by);
                    *(__half2*)&C[(size_t)row0 * N + col] = o;
                }
                if (row0 + 8 < M) {
                    __half2 o = __floats2half2_rn(acc[im][jn][2] + bx, acc[im][jn][3] + by);
                    *(__half2*)&C[(size_t)(row0 + 8) * N + col] = o;
                }
            }
        }
    }
}

// ---------------- CSR build ----------------
__global__ void hist_kernel(const int* __restrict__ dst, int* __restrict__ deg) {
    int e = blockIdx.x * blockDim.x + threadIdx.x;
    if (e < NE) atomicAdd(&deg[dst[e]], 1);
}
__global__ void csr_scan_kernel(const int* __restrict__ deg, int* __restrict__ rowptr,
                                int* __restrict__ cursor) {
    __shared__ int part[1024];
    int t = threadIdx.x;
    int base = t * 10;
    int local[10];
    int s = 0;
#pragma unroll
    for (int i = 0; i < 10; i++) {
        int idx = base + i;
        local[i] = (idx < NN) ? deg[idx] : 0;
        s += local[i];
    }
    part[t] = s;
    __syncthreads();
    for (int off = 1; off < 1024; off <<= 1) {
        int v = (t >= off) ? part[t - off] : 0;
        __syncthreads();
        part[t] += v;
        __syncthreads();
    }
    int run = (t > 0) ? part[t - 1] : 0;
#pragma unroll
    for (int i = 0; i < 10; i++) {
        int idx = base + i;
        if (idx < NN) {
            rowptr[idx] = run;
            cursor[idx] = run;
            run += local[i];
        }
    }
    if (t == 1023) rowptr[NN] = run;
}
__global__ void scatter_kernel(const int* __restrict__ dst, int* __restrict__ cursor,
                               int* __restrict__ perm) {
    int e = blockIdx.x * blockDim.x + threadIdx.x;
    if (e < NE) {
        int pos = atomicAdd(&cursor[dst[e]], 1);
        perm[pos] = e;
    }
}

// ---------------- fused attention + head-mean + skip + ELU (+ optional gate) ----------------
template <int CC>
__global__ void __launch_bounds__(256)
attn_combine_kernel(const __half* __restrict__ qkvs, int ld, int hc,
                    const int* __restrict__ rowptr, const int* __restrict__ perm,
                    const int* __restrict__ src,
                    float* __restrict__ hout, __half* __restrict__ Anext, float scale,
                    const float* __restrict__ gw, const float* __restrict__ gb,
                    float* __restrict__ gatep) {
    extern __shared__ float sred[];  // [HH][CC]
    int n = blockIdx.x;
    int tid = threadIdx.x;
    int h = tid >> 5, lane = tid & 31;
    const __half* q = qkvs;
    const __half* k = qkvs + hc;
    const __half* v = qkvs + 2 * hc;
    const size_t qbase = (size_t)n * ld + (size_t)h * CC;
    int j0 = rowptr[n], j1 = rowptr[n + 1];
    float mmax = -INFINITY, den = 0.f;

    if constexpr (CC >= 256) {
        const int R = CC / 256;
        float qv[R][8], acc[R][8];
#pragma unroll
        for (int i = 0; i < R; i++) {
            uint4 t = *(const uint4*)(q + qbase + i * 256 + lane * 8);
            h8_to_f8(t, qv[i]);
#pragma unroll
            for (int j = 0; j < 8; j++) acc[i][j] = 0.f;
        }
        for (int j = j0; j < j1; j++) {
            int s = src[perm[j]];
            const size_t sb = (size_t)s * ld + (size_t)h * CC;
            float kf[R][8], vf[R][8];
#pragma unroll
            for (int i = 0; i < R; i++) {
                uint4 tk = *(const uint4*)(k + sb + i * 256 + lane * 8);
                uint4 tv = *(const uint4*)(v + sb + i * 256 + lane * 8);
                h8_to_f8(tk, kf[i]);
                h8_to_f8(tv, vf[i]);
            }
            float dot = 0.f;
#pragma unroll
            for (int i = 0; i < R; i++)
#pragma unroll
                for (int c = 0; c < 8; c++) dot = fmaf(qv[i][c], kf[i][c], dot);
#pragma unroll
            for (int o = 16; o; o >>= 1) dot += __shfl_xor_sync(0xFFFFFFFFu, dot, o);
            float a = dot * scale;
            float mnew = fmaxf(mmax, a);
            float corr = __expf(mmax - mnew);
            float wt = __expf(a - mnew);
            den = den * corr + wt;
#pragma unroll
            for (int i = 0; i < R; i++)
#pragma unroll
                for (int c = 0; c < 8; c++) acc[i][c] = fmaf(wt, vf[i][c], acc[i][c] * corr);
            mmax = mnew;
        }
        float inv = 1.f / fmaxf(den, 1e-16f);
#pragma unroll
        for (int i = 0; i < R; i++) {
            float4 o0 = make_float4(acc[i][0] * inv, acc[i][1] * inv, acc[i][2] * inv, acc[i][3] * inv);
            float4 o1 = make_float4(acc[i][4] * inv, acc[i][5] * inv, acc[i][6] * inv, acc[i][7] * inv);
            *(float4*)(sred + h * CC + i * 256 + lane * 8) = o0;
            *(float4*)(sred + h * CC + i * 256 + lane * 8 + 4) = o1;
        }
    } else {
        float2 qv = __half22float2(*(const __half2*)(q + qbase + lane * 2));
        float2 acc = make_float2(0.f, 0.f);
        for (int j = j0; j < j1; j++) {
            int s = src[perm[j]];
            const size_t sb = (size_t)s * ld + (size_t)h * CC;
            float2 kv = __half22float2(*(const __half2*)(k + sb + lane * 2));
            float2 vv = __half22float2(*(const __half2*)(v + sb + lane * 2));
            float dot = fmaf(qv.x, kv.x, qv.y * kv.y);
#pragma unroll
            for (int o = 16; o; o >>= 1) dot += __shfl_xor_sync(0xFFFFFFFFu, dot, o);
            float a = dot * scale;
            float mnew = fmaxf(mmax, a);
            float corr = __expf(mmax - mnew);
            float wt = __expf(a - mnew);
            den = den * corr + wt;
            acc.x = fmaf(wt, vv.x, acc.x * corr);
            acc.y = fmaf(wt, vv.y, acc.y * corr);
            mmax = mnew;
        }
        float inv = 1.f / fmaxf(den, 1e-16f);
        *(float2*)(sred + h * CC + lane * 2) = make_float2(acc.x * inv, acc.y * inv);
    }
    __syncthreads();

    const __half* skipp = qkvs + 3 * hc;
    float gacc = 0.f;
    for (int c = tid; c < CC; c += 256) {
        float s = 0.f;
#pragma unroll
        for (int h2 = 0; h2 < HH; h2++) s += sred[h2 * CC + c];
        float val = s * (1.f / HH) + __half2float(skipp[(size_t)n * ld + c]);
        val = val > 0.f ? val : expm1f(val);
        if (hout) hout[(size_t)n * CC + c] = val;
        if (Anext) Anext[(size_t)n * CC + c] = __float2half_rn(val);
        if (gatep) gacc = fmaf(val, gw[c], gacc);
    }
    if (gatep) {
        __syncthreads();
        sred[tid] = gacc;
        __syncthreads();
        for (int off = 128; off; off >>= 1) {
            if (tid < off) sred[tid] += sred[tid + off];
            __syncthreads();
        }
        if (tid == 0) gatep[n] = sred[0] + gb[0];
    }
}

// ---------------- fused pooling: one block per graph ----------------
__global__ void __launch_bounds__(256)
pool_all_kernel(const float* __restrict__ h, const float* __restrict__ gate,
                const int* __restrict__ batch, const float* __restrict__ fw,
                const float* __restrict__ fb, float* __restrict__ out) {
    __shared__ float red[256];
    __shared__ float spool[4][64];
    __shared__ float pool[64];
    __shared__ float sm, sd;
    int g = blockIdx.x;
    int tid = threadIdx.x;
    int lo = lbound(batch, NN, g);
    int hi = lbound(batch, NN, g + 1);

    float m = -INFINITY;
    for (int n = lo + tid; n < hi; n += 256) m = fmaxf(m, gate[n]);
    red[tid] = m;
    __syncthreads();
    for (int off = 128; off; off >>= 1) {
        if (tid < off) red[tid] = fmaxf(red[tid], red[tid + off]);
        __syncthreads();
    }
    if (tid == 0) sm = red[0];
    __syncthreads();
    float mm = sm;

    float s = 0.f;
    for (int n = lo + tid; n < hi; n += 256) s += expf(gate[n] - mm);
    red[tid] = s;
    __syncthreads();
    for (int off = 128; off; off >>= 1) {
        if (tid < off) red[tid] += red[tid + off];
        __syncthreads();
    }
    if (tid == 0) sd = fmaxf(red[0], 1e-16f);
    __syncthreads();
    float inv = 1.f / sd;

    int grp = tid >> 6, c = tid & 63;
    float acc = 0.f;
    for (int n = lo + grp; n < hi; n += 4) {
        float w = expf(gate[n] - mm) * inv;
        acc = fmaf(w, h[(size_t)n * 64 + c], acc);
    }
    spool[grp][c] = acc;
    __syncthreads();
    if (tid < 64) pool[tid] = spool[0][tid] + spool[1][tid] + spool[2][tid] + spool[3][tid];
    __syncthreads();

    if (tid < 10) {
        float o = fb[tid];
#pragma unroll
        for (int cc = 0; cc < 64; cc++) o = fmaf(pool[cc], fw[cc * 10 + tid], o);
        out[g * 10 + tid] = o;
    }
}

// ---------------- host side ----------------
struct Ptrs {
    __half* qkvs;
    float *hA, *gate, *biasp;
    __half *Ac, *Bc;
    int *deg, *rowptr, *cursor, *perm;
};

static void layer_gemm(int fin, int C, const float* const* W, const Ptrs& P) {
    int hc = C * HH;
    int Ntot = 3 * hc + C;
    dim3 tg((fin + 31) / 32, (hc + 31) / 32, 4);
    convBT4_kernel<<<tg, dim3(32, 8)>>>(W[0], W[2], W[4], W[6], P.Bc, fin, hc, C);
    pack_bias_kernel<<<(Ntot + 255) / 256, 256>>>(W[1], W[3], W[5], W[7], hc, C, P.biasp);
    dim3 grid((Ntot + BN - 1) / BN, (NN + BM - 1) / BM);
    gemm_mma_kernel<<<grid, 256, GEMM_SMEM>>>(P.Ac, P.Bc, P.biasp, P.qkvs, NN, fin, Ntot);
}

static void layer_attn(int C, const int* src, float* hout, __half* Anext,
                       const float* gw, const float* gb, float* gatep, const Ptrs& P) {
    int hc = C * HH;
    int Ntot = 3 * hc + C;
    float scale = 1.f / sqrtf((float)C);
    int smem = HH * C * sizeof(float);
    if (C == 512)
        attn_combine_kernel<512><<<NN, 256, smem>>>(P.qkvs, Ntot, hc, P.rowptr, P.perm, src, hout, Anext, scale, gw, gb, gatep);
    else if (C == 256)
        attn_combine_kernel<256><<<NN, 256, smem>>>(P.qkvs, Ntot, hc, P.rowptr, P.perm, src, hout, Anext, scale, gw, gb, gatep);
    else
        attn_combine_kernel<64><<<NN, 256, smem>>>(P.qkvs, Ntot, hc, P.rowptr, P.perm, src, hout, Anext, scale, gw, gb, gatep);
}

extern "C" void kernel_launch(void* const* d_in, const int* in_sizes, int n_in,
                              void* d_out, int out_size) {
    const float* x     = (const float*)d_in[0];
    const int*   ei    = (const int*)d_in[1];
    const int*   batch = (const int*)d_in[2];
    const float* W[24];
    for (int i = 0; i < 24; i++) W[i] = (const float*)d_in[3 + i];
    const float* gate_w = (const float*)d_in[27];
    const float* gate_b = (const float*)d_in[28];
    const float* fc_w   = (const float*)d_in[29];
    const float* fc_b   = (const float*)d_in[30];
    float* out = (float*)d_out;

    const int* src = ei;
    const int* dst = ei + NE;

    cudaFuncSetAttribute(gemm_mma_kernel, cudaFuncAttributeMaxDynamicSharedMemorySize, GEMM_SMEM);

    Ptrs P;
    cudaGetSymbolAddress((void**)&P.qkvs, g_qkvs);
    cudaGetSymbolAddress((void**)&P.hA, g_hA);
    cudaGetSymbolAddress((void**)&P.gate, g_gate);
    cudaGetSymbolAddress((void**)&P.biasp, g_biasp);
    cudaGetSymbolAddress((void**)&P.Ac, g_Acomp);
    cudaGetSymbolAddress((void**)&P.Bc, g_Bcomp);
    cudaGetSymbolAddress((void**)&P.deg, g_deg);
    cudaGetSymbolAddress((void**)&P.rowptr, g_rowptr);
    cudaGetSymbolAddress((void**)&P.cursor, g_cursor);
    cudaGetSymbolAddress((void**)&P.perm, g_perm);

    size_t na = (size_t)NN * 128;
    convA_kernel<<<(unsigned)((na + 255) / 256), 256>>>(x, P.Ac, na);
    layer_gemm(128, 512, &W[0], P);

    fill_int_kernel<<<(NN + 255) / 256, 256>>>(P.deg, 0, NN);
    hist_kernel<<<(NE + 255) / 256, 256>>>(dst, P.deg);
    csr_scan_kernel<<<1, 1024>>>(P.deg, P.rowptr, P.cursor);
    scatter_kernel<<<(NE + 255) / 256, 256>>>(dst, P.cursor, P.perm);

    layer_attn(512, src, nullptr, P.Ac, nullptr, nullptr, nullptr, P);

    layer_gemm(512, 256, &W[8], P);
    layer_attn(256, src, nullptr, P.Ac, nullptr, nullptr, nullptr, P);

    layer_gemm(256, 64, &W[16], P);
    layer_attn(64, src, P.hA, nullptr, gate_w, gate_b, P.gate, P);

    pool_all_kernel<<<NG, 256>>>(P.hA, P.gate, batch, fc_w, fc_b, out);
}